// round 10
// baseline (speedup 1.0000x reference)
#include <cuda_runtime.h>
#include <cuda_bf16.h>
#include <stdint.h>

#define B_   4
#define L_   2048
#define D_   1024
#define H_   16
#define DK_  64
#define HD_  1024
#define MROWS_ 8192
#define LN_EPS_ 1e-5f
#define NROWS_ATTN (B_ * H_ * L_)

// ---------------------------------------------------------------------------
// Scratch (device globals). Packed split-bf16: [M][K/32][32 hi | 32 lo] 128B.
// ---------------------------------------------------------------------------
__device__ __align__(256) uint8_t g_qpk [(long long)MROWS_ * D_ * 4];
__device__ __align__(256) uint8_t g_kpk [(long long)MROWS_ * D_ * 4];
__device__ __align__(256) uint8_t g_vpk [(long long)MROWS_ * D_ * 4];
__device__ __align__(256) uint8_t g_wqpk[(long long)HD_ * D_ * 4];
__device__ __align__(256) uint8_t g_wkpk[(long long)HD_ * D_ * 4];
__device__ __align__(256) uint8_t g_wvpk[(long long)HD_ * D_ * 4];
__device__ __align__(256) uint8_t g_wopk[(long long)D_ * HD_ * 4];
__device__ __align__(256) uint8_t g_qhpk[(long long)MROWS_ * HD_ * 4];
__device__ __align__(256) uint8_t g_khpk[(long long)MROWS_ * HD_ * 4];
__device__ __align__(256) uint8_t g_vTpk[(long long)B_ * H_ * DK_ * L_ * 4];
__device__ __align__(256) uint8_t g_oapk[(long long)MROWS_ * HD_ * 4];
__device__ float g_vh[MROWS_ * HD_];
__device__ float g_op[MROWS_ * HD_];
__device__ float g_rs[NROWS_ATTN];

// ---------------------------------------------------------------------------
// helpers
// ---------------------------------------------------------------------------
__device__ __forceinline__ uint32_t smem_u32(const void* p) {
    uint32_t a;
    asm("{ .reg .u64 t; cvta.to.shared.u64 t, %1; cvt.u32.u64 %0, t; }" : "=r"(a) : "l"(p));
    return a;
}
__device__ __forceinline__ uint32_t sw128(uint32_t off) {
    return off ^ ((off >> 3) & 0x70);
}
__device__ __forceinline__ void cpa16(uint32_t dst, const void* src) {
    asm volatile("cp.async.cg.shared.global [%0], [%1], 16;" :: "r"(dst), "l"(src));
}
#define CP_COMMIT() asm volatile("cp.async.commit_group;" ::: "memory")
#define CP_WAIT0()  asm volatile("cp.async.wait_group 0;" ::: "memory")
#define CP_WAIT1()  asm volatile("cp.async.wait_group 1;" ::: "memory")
#define LDSM_X4(r0, r1, r2, r3, addr)                                      \
    asm volatile("ldmatrix.sync.aligned.m8n8.x4.shared.b16 "               \
                 "{%0,%1,%2,%3}, [%4];"                                    \
                 : "=r"(r0), "=r"(r1), "=r"(r2), "=r"(r3) : "r"(addr))

__device__ __forceinline__ void mma16816(float* d, const uint32_t* a, const uint32_t* b) {
    asm volatile(
        "mma.sync.aligned.m16n8k16.row.col.f32.bf16.bf16.f32 "
        "{%0,%1,%2,%3}, {%4,%5,%6,%7}, {%8,%9}, {%0,%1,%2,%3};"
        : "+f"(d[0]), "+f"(d[1]), "+f"(d[2]), "+f"(d[3])
        : "r"(a[0]), "r"(a[1]), "r"(a[2]), "r"(a[3]), "r"(b[0]), "r"(b[1]));
}

__device__ __forceinline__ void pack_store2(uint8_t* p, float v0, float v1) {
    __nv_bfloat162 h = __floats2bfloat162_rn(v0, v1);
    float2 f = __bfloat1622float2(h);
    __nv_bfloat162 l = __floats2bfloat162_rn(v0 - f.x, v1 - f.y);
    *(uint32_t*)p = *(uint32_t*)&h;
    *(uint32_t*)(p + 64) = *(uint32_t*)&l;
}
__device__ __forceinline__ void pack_store4(uint8_t* p, float4 v) {
    __nv_bfloat162 h0 = __floats2bfloat162_rn(v.x, v.y);
    __nv_bfloat162 h1 = __floats2bfloat162_rn(v.z, v.w);
    float2 f0 = __bfloat1622float2(h0), f1 = __bfloat1622float2(h1);
    __nv_bfloat162 l0 = __floats2bfloat162_rn(v.x - f0.x, v.y - f0.y);
    __nv_bfloat162 l1 = __floats2bfloat162_rn(v.z - f1.x, v.w - f1.y);
    uint2 hu, lu;
    hu.x = *(uint32_t*)&h0; hu.y = *(uint32_t*)&h1;
    lu.x = *(uint32_t*)&l0; lu.y = *(uint32_t*)&l1;
    *(uint2*)p = hu;
    *(uint2*)(p + 64) = lu;
}
__device__ __forceinline__ void combine8(const uint4 h, const uint4 l, float inv, float* out) {
    const uint32_t hu[4] = { h.x, h.y, h.z, h.w };
    const uint32_t lu[4] = { l.x, l.y, l.z, l.w };
#pragma unroll
    for (int j = 0; j < 4; j++) {
        __nv_bfloat162 hb = *(const __nv_bfloat162*)&hu[j];
        __nv_bfloat162 lb = *(const __nv_bfloat162*)&lu[j];
        float2 hf = __bfloat1622float2(hb), lf = __bfloat1622float2(lb);
        out[2 * j]     = (hf.x + lf.x) * inv;
        out[2 * j + 1] = (hf.y + lf.y) * inv;
    }
}

// ---------------------------------------------------------------------------
// pack fp32 [M,K] -> packed split bf16 ; batched over 3 tensors via blockIdx.z
// ---------------------------------------------------------------------------
__global__ void __launch_bounds__(256)
pack_split3(const float* __restrict__ s0, const float* __restrict__ s1,
            const float* __restrict__ s2,
            uint8_t* __restrict__ d0, uint8_t* __restrict__ d1,
            uint8_t* __restrict__ d2, int K)
{
    const float* src = (blockIdx.z == 0) ? s0 : (blockIdx.z == 1) ? s1 : s2;
    uint8_t* dst = (blockIdx.z == 0) ? d0 : (blockIdx.z == 1) ? d1 : d2;
    const long long idx = (long long)blockIdx.x * 256 + threadIdx.x;
    const int perRow = K >> 2;
    const long long m = idx / perRow;
    const int j = (int)(idx - m * perRow);
    float4 v = *(const float4*)(src + m * K + j * 4);
    const int e0 = j * 4;
    uint8_t* p = dst + (m * (K >> 5) + (e0 >> 5)) * 128 + (e0 & 31) * 2;
    pack_store4(p, v);
}
__global__ void __launch_bounds__(256)
pack_split1(const float* __restrict__ src, uint8_t* __restrict__ dst, int K)
{
    const long long idx = (long long)blockIdx.x * 256 + threadIdx.x;
    const int perRow = K >> 2;
    const long long m = idx / perRow;
    const int j = (int)(idx - m * perRow);
    float4 v = *(const float4*)(src + m * K + j * 4);
    const int e0 = j * 4;
    uint8_t* p = dst + (m * (K >> 5) + (e0 >> 5)) * 128 + (e0 & 31) * 2;
    pack_store4(p, v);
}

// ---------------------------------------------------------------------------
// Packed split-bf16 GEMM. CTA tile 128 x TN, 32-K chunks, 8 warps as 4x2
// (warp tile 32 x TN/2), 2 CTAs/SM. 3-stage cp.async pipeline, ONE barrier
// per chunk. Fragment order: Ah,Bh,Al loads -> hh+lh mma -> Bl load -> hl mma.
// MODE 0: C fp32 + bias.  MODE 1: C packed + bias.
// MODE 2: exp(alpha*acc) -> packed + rowsum atomics.
// MODE 3: A staged tiles -> normalized fp32 P write; epilogue *1/rowsum -> packed.
// ---------------------------------------------------------------------------
template<int TN, int MODE>
__global__ void __launch_bounds__(256, 2)
pk_gemm(const uint8_t* Apk, const uint8_t* __restrict__ Bpk,
        const float* __restrict__ bias,
        float* Cf, uint8_t* Cpk, float* rs,
        int nchunks, long long ldA, long long ldB, int ldc, long long ldCpk,
        int zdiv,
        long long sAo, long long sAi, long long sBo, long long sBi,
        long long sCfO, long long sCfI, long long sCpO, long long sCpI,
        long long rsO, long long rsI, float alpha)
{
    constexpr int NT = TN / 16;            // n8-tiles per warp
    constexpr int NB = TN / 32;            // B cp.async per thread per chunk
    constexpr int STAGE = 16384 + TN * 128;

    extern __shared__ uint8_t dyn_raw[];
    __shared__ float s_bias[TN];
    __shared__ float s_aux[128];

    const int tid = threadIdx.x, wid = tid >> 5, lane = tid & 31;
    const int z = blockIdx.z, zo = z / zdiv, zi = z - zo * zdiv;
    Apk += zo * sAo + zi * sAi;
    Bpk += zo * sBo + zi * sBi;
    if (MODE == 0 || MODE == 3) Cf += zo * sCfO + zi * sCfI;
    if (MODE != 0) Cpk += zo * sCpO + zi * sCpI;
    const long long rs_off = zo * rsO + zi * rsI;

    const long long m0 = (long long)blockIdx.y * 128;
    const long long n0 = (long long)blockIdx.x * TN;

    uint32_t raw = smem_u32(dyn_raw);
    uint32_t base = (raw + 1023u) & ~1023u;
    uint8_t* dsm = dyn_raw + (base - raw);
    uint8_t* smA[3] = { dsm, dsm + STAGE, dsm + 2 * STAGE };
    const uint32_t aSu[3] = { base, base + STAGE, base + 2 * STAGE };
    const uint32_t bSu[3] = { base + 16384, base + STAGE + 16384, base + 2 * STAGE + 16384 };

    if (MODE == 0 || MODE == 1) {
        for (int i = tid; i < TN; i += 256) s_bias[i] = bias ? bias[n0 + i] : 0.0f;
    }
    if (MODE == 2) { if (tid < 128) s_aux[tid] = 0.0f; }
    if (MODE == 3) { if (tid < 128) s_aux[tid] = 1.0f / rs[rs_off + m0 + tid]; }

    float acc[2][NT][4];
#pragma unroll
    for (int i = 0; i < 2; i++)
#pragma unroll
        for (int j = 0; j < NT; j++)
#pragma unroll
            for (int e = 0; e < 4; e++) acc[i][j][e] = 0.0f;

    const uint32_t a_row = (uint32_t)((lane & 7) + (lane & 8));
    const uint32_t a_kof = (uint32_t)(((lane >> 4) & 1) * 16);
    const uint32_t b_row = (uint32_t)((lane & 7) + ((lane >> 4) & 1) * 8);
    const uint32_t b_kof = (uint32_t)(((lane >> 3) & 1) * 16);
    const int wm = (wid & 3) * 32;
    const int wn = (wid >> 2) * (TN / 2);

    auto prefetch = [&](int s, int c) {
        const uint8_t* Ab = Apk + (long long)c * 128;
#pragma unroll
        for (int i = 0; i < 4; i++) {
            const int idx = i * 256 + tid, row = idx >> 3, g = idx & 7;
            cpa16(aSu[s] + sw128((uint32_t)(row * 128 + g * 16)),
                  Ab + (m0 + row) * ldA + g * 16);
        }
        const uint8_t* Bb = Bpk + (long long)c * 128;
#pragma unroll
        for (int i = 0; i < NB; i++) {
            const int idx = i * 256 + tid, row = idx >> 3, g = idx & 7;
            cpa16(bSu[s] + sw128((uint32_t)(row * 128 + g * 16)),
                  Bb + (n0 + row) * ldB + g * 16);
        }
        CP_COMMIT();
    };

    // preamble: 2 chunks in flight
    prefetch(0, 0);
    if (nchunks > 1) prefetch(1, 1);

    int cur = 0;
    for (int c = 0; c < nchunks; c++) {
        // wait until chunk c's group is complete
        if (c + 1 < nchunks) { CP_WAIT1(); } else { CP_WAIT0(); }
        __syncthreads();   // one barrier per chunk: also fences stage reuse

        // prefetch chunk c+2 into the stage last used by chunk c-1
        if (c + 2 < nchunks) {
            int s = cur - 1; if (s < 0) s += 3;
            prefetch(s, c + 2);
        }

        if (MODE == 3) {
            // reconstruct normalized fp32 P for this 32-K chunk (in place)
            const int r = tid >> 1, hh = tid & 1;
            const uint8_t* sa = smA[cur];
            const float inv = s_aux[r];
            uint4 h0 = *(const uint4*)(sa + sw128((uint32_t)(r * 128 + hh * 32)));
            uint4 h1 = *(const uint4*)(sa + sw128((uint32_t)(r * 128 + hh * 32 + 16)));
            uint4 l0 = *(const uint4*)(sa + sw128((uint32_t)(r * 128 + 64 + hh * 32)));
            uint4 l1 = *(const uint4*)(sa + sw128((uint32_t)(r * 128 + 64 + hh * 32 + 16)));
            float o[16];
            combine8(h0, l0, inv, o);
            combine8(h1, l1, inv, o + 8);
            float* dst = Cf + (m0 + r) * (long long)ldc + c * 32 + hh * 16;
            *(float4*)(dst +  0) = make_float4(o[0],  o[1],  o[2],  o[3]);
            *(float4*)(dst +  4) = make_float4(o[4],  o[5],  o[6],  o[7]);
            *(float4*)(dst +  8) = make_float4(o[8],  o[9],  o[10], o[11]);
            *(float4*)(dst + 12) = make_float4(o[12], o[13], o[14], o[15]);
        }

        const uint32_t aS = aSu[cur], bS = bSu[cur];
#pragma unroll
        for (int ks = 0; ks < 2; ks++) {
            uint32_t ah[2][4], al[2][4], bf[NT][2];
            // A hi + A lo + B hi all issued up front
#pragma unroll
            for (int mt = 0; mt < 2; mt++) {
                uint32_t off = (uint32_t)(wm + mt * 16 + a_row) * 128 + ks * 32 + a_kof;
                LDSM_X4(ah[mt][0], ah[mt][1], ah[mt][2], ah[mt][3], aS + sw128(off));
            }
#pragma unroll
            for (int mt = 0; mt < 2; mt++) {
                uint32_t off = (uint32_t)(wm + mt * 16 + a_row) * 128 + 64 + ks * 32 + a_kof;
                LDSM_X4(al[mt][0], al[mt][1], al[mt][2], al[mt][3], aS + sw128(off));
            }
#pragma unroll
            for (int p = 0; p < NT / 2; p++) {
                uint32_t r0, r1, r2, r3;
                uint32_t off = (uint32_t)(wn + p * 16 + b_row) * 128 + ks * 32 + b_kof;
                LDSM_X4(r0, r1, r2, r3, bS + sw128(off));
                bf[2 * p][0] = r0; bf[2 * p][1] = r1;
                bf[2 * p + 1][0] = r2; bf[2 * p + 1][1] = r3;
            }
            // 32 back-to-back mmas: hh then lh
#pragma unroll
            for (int mt = 0; mt < 2; mt++)
#pragma unroll
                for (int nt = 0; nt < NT; nt++)
                    mma16816(acc[mt][nt], ah[mt], bf[nt]);
#pragma unroll
            for (int mt = 0; mt < 2; mt++)
#pragma unroll
                for (int nt = 0; nt < NT; nt++)
                    mma16816(acc[mt][nt], al[mt], bf[nt]);
            // B lo (reuse bf), then hl
#pragma unroll
            for (int p = 0; p < NT / 2; p++) {
                uint32_t r0, r1, r2, r3;
                uint32_t off = (uint32_t)(wn + p * 16 + b_row) * 128 + 64 + ks * 32 + b_kof;
                LDSM_X4(r0, r1, r2, r3, bS + sw128(off));
                bf[2 * p][0] = r0; bf[2 * p][1] = r1;
                bf[2 * p + 1][0] = r2; bf[2 * p + 1][1] = r3;
            }
#pragma unroll
            for (int mt = 0; mt < 2; mt++)
#pragma unroll
                for (int nt = 0; nt < NT; nt++)
                    mma16816(acc[mt][nt], ah[mt], bf[nt]);
        }
        cur++; if (cur == 3) cur = 0;
    }

    // ---- epilogue ----
    const int g = lane >> 2, t = lane & 3;
    if (MODE == 2) {
#pragma unroll
        for (int mt = 0; mt < 2; mt++) {
            float sum0 = 0.0f, sum1 = 0.0f;
#pragma unroll
            for (int nt = 0; nt < NT; nt++) {
                const int colw = wn + nt * 8 + 2 * t;
                const long long row0 = m0 + wm + mt * 16 + g;
                float e0 = __expf(acc[mt][nt][0] * alpha);
                float e1 = __expf(acc[mt][nt][1] * alpha);
                float e2 = __expf(acc[mt][nt][2] * alpha);
                float e3 = __expf(acc[mt][nt][3] * alpha);
                const long long colg = n0 + colw;
                const long long ch = colg >> 5;
                const int wi = (int)(colg & 31);
                pack_store2(Cpk + row0 * ldCpk + ch * 128 + wi * 2, e0, e1);
                pack_store2(Cpk + (row0 + 8) * ldCpk + ch * 128 + wi * 2, e2, e3);
                sum0 += e0 + e1; sum1 += e2 + e3;
            }
            sum0 += __shfl_xor_sync(0xffffffffu, sum0, 1);
            sum0 += __shfl_xor_sync(0xffffffffu, sum0, 2);
            sum1 += __shfl_xor_sync(0xffffffffu, sum1, 1);
            sum1 += __shfl_xor_sync(0xffffffffu, sum1, 2);
            if (t == 0) {
                atomicAdd(&s_aux[wm + mt * 16 + g], sum0);
                atomicAdd(&s_aux[wm + mt * 16 + g + 8], sum1);
            }
        }
        __syncthreads();
        if (tid < 128)
            atomicAdd(&rs[rs_off + m0 + tid], s_aux[tid]);
    } else if (MODE == 1 || MODE == 3) {
#pragma unroll
        for (int mt = 0; mt < 2; mt++) {
            const float i0 = (MODE == 3) ? s_aux[wm + mt * 16 + g] : 1.0f;
            const float i1 = (MODE == 3) ? s_aux[wm + mt * 16 + g + 8] : 1.0f;
#pragma unroll
            for (int nt = 0; nt < NT; nt++) {
                const int colw = wn + nt * 8 + 2 * t;
                const long long row0 = m0 + wm + mt * 16 + g;
                const float b0 = (MODE == 1) ? s_bias[colw] : 0.0f;
                const float b1 = (MODE == 1) ? s_bias[colw + 1] : 0.0f;
                float v0 = acc[mt][nt][0] * i0 + b0;
                float v1 = acc[mt][nt][1] * i0 + b1;
                float v2 = acc[mt][nt][2] * i1 + b0;
                float v3 = acc[mt][nt][3] * i1 + b1;
                const long long colg = n0 + colw;
                const long long ch = colg >> 5;
                const int wi = (int)(colg & 31);
                pack_store2(Cpk + row0 * ldCpk + ch * 128 + wi * 2, v0, v1);
                pack_store2(Cpk + (row0 + 8) * ldCpk + ch * 128 + wi * 2, v2, v3);
            }
        }
    } else {
#pragma unroll
        for (int mt = 0; mt < 2; mt++) {
#pragma unroll
            for (int nt = 0; nt < NT; nt++) {
                const int colw = wn + nt * 8 + 2 * t;
                const float b0 = s_bias[colw], b1 = s_bias[colw + 1];
                const long long row0 = m0 + wm + mt * 16 + g;
                *(float2*)(Cf + row0 * (long long)ldc + n0 + colw) =
                    make_float2(acc[mt][nt][0] + b0, acc[mt][nt][1] + b1);
                *(float2*)(Cf + (row0 + 8) * (long long)ldc + n0 + colw) =
                    make_float2(acc[mt][nt][2] + b0, acc[mt][nt][3] + b1);
            }
        }
    }
}

// ---------------------------------------------------------------------------
// V transpose: vh fp32 [B,L,H,DK] -> vT packed [(b*H+h)][dk][L/32][128B]
// ---------------------------------------------------------------------------
__global__ void __launch_bounds__(256)
transpose_v_pk(const float* __restrict__ vh, uint8_t* __restrict__ vT)
{
    __shared__ float tsm[32][33];
    const int bh = blockIdx.z;
    const int b = bh >> 4, h = bh & 15;
    const int l0 = blockIdx.x * 32;
    const int d0 = blockIdx.y * 32;
    const int tid = threadIdx.x;
    const int tx = tid & 31;
    const int ty = tid >> 5;

    const float* src = vh + ((long long)b * L_ + l0) * HD_ + h * DK_ + d0;
#pragma unroll
    for (int i = 0; i < 32; i += 8)
        tsm[ty + i][tx] = src[(long long)(ty + i) * HD_ + tx];
    __syncthreads();

    const int lp = tid & 15;
#pragma unroll
    for (int it = 0; it < 2; it++) {
        const int d = (tid >> 4) + 16 * it;
        uint8_t* p = vT + ((long long)bh * 64 + d0 + d) * (L_ / 32 * 128)
                        + (l0 >> 5) * 128 + lp * 4;
        pack_store2(p, tsm[2 * lp][d], tsm[2 * lp + 1][d]);
    }
}

__global__ void zero_rs(float* __restrict__ rs)
{
    rs[blockIdx.x * 256 + threadIdx.x] = 0.0f;
}

// ---------------------------------------------------------------------------
// LayerNorm + residual
// ---------------------------------------------------------------------------
__global__ void __launch_bounds__(256)
ln_residual(const float* __restrict__ x, const float* __restrict__ res,
            const float* __restrict__ gam, const float* __restrict__ bet,
            float* __restrict__ out)
{
    const long long row = blockIdx.x;
    const float4* x4 = (const float4*)(x   + row * D_);
    const float4* r4 = (const float4*)(res + row * D_);
    const int tid = threadIdx.x;

    float4 v = x4[tid];
    float s  = (v.x + v.y) + (v.z + v.w);
    float sq = (v.x * v.x + v.y * v.y) + (v.z * v.z + v.w * v.w);
#pragma unroll
    for (int o = 16; o > 0; o >>= 1) {
        s  += __shfl_xor_sync(0xffffffffu, s,  o);
        sq += __shfl_xor_sync(0xffffffffu, sq, o);
    }
    __shared__ float ss[8], sqs[8];
    if ((tid & 31) == 0) { ss[tid >> 5] = s; sqs[tid >> 5] = sq; }
    __syncthreads();
    s  = (ss[0]  + ss[1])  + (ss[2]  + ss[3])  + (ss[4]  + ss[5])  + (ss[6]  + ss[7]);
    sq = (sqs[0] + sqs[1]) + (sqs[2] + sqs[3]) + (sqs[4] + sqs[5]) + (sqs[6] + sqs[7]);

    const float mean = s * (1.0f / D_);
    float var = sq * (1.0f / D_) - mean * mean;
    var = fmaxf(var, 0.0f);
    const float rstd = rsqrtf(var + LN_EPS_);

    float4 g  = ((const float4*)gam)[tid];
    float4 bt = ((const float4*)bet)[tid];
    float4 r  = r4[tid];
    float4 o;
    o.x = (v.x - mean) * rstd * g.x + bt.x + r.x;
    o.y = (v.y - mean) * rstd * g.y + bt.y + r.y;
    o.z = (v.z - mean) * rstd * g.z + bt.z + r.z;
    o.w = (v.w - mean) * rstd * g.w + bt.w + r.w;
    ((float4*)(out + row * D_))[tid] = o;
}

// ---------------------------------------------------------------------------
// Launch
// ---------------------------------------------------------------------------
extern "C" void kernel_launch(void* const* d_in, const int* in_sizes, int n_in,
                              void* d_out, int out_size)
{
    (void)in_sizes; (void)n_in; (void)out_size;
    const float* q  = (const float*)d_in[0];
    const float* k  = (const float*)d_in[1];
    const float* v  = (const float*)d_in[2];
    const float* wq = (const float*)d_in[3];
    const float* bq = (const float*)d_in[4];
    const float* wk = (const float*)d_in[5];
    const float* bk = (const float*)d_in[6];
    const float* wv = (const float*)d_in[7];
    const float* bv = (const float*)d_in[8];
    const float* wo = (const float*)d_in[9];
    const float* bo = (const float*)d_in[10];
    const float* lg = (const float*)d_in[11];
    const float* lb = (const float*)d_in[12];

    float* out  = (float*)d_out;
    float* attn = out + (long long)B_ * L_ * D_;
    uint8_t* attn_b = (uint8_t*)attn;

    uint8_t *qpk, *kpk, *vpk, *wqpk, *wkpk, *wvpk, *wopk, *qhpk, *khpk, *vTpk, *oapk;
    float *vh, *op, *rs;
    cudaGetSymbolAddress((void**)&qpk,  g_qpk);
    cudaGetSymbolAddress((void**)&kpk,  g_kpk);
    cudaGetSymbolAddress((void**)&vpk,  g_vpk);
    cudaGetSymbolAddress((void**)&wqpk, g_wqpk);
    cudaGetSymbolAddress((void**)&wkpk, g_wkpk);
    cudaGetSymbolAddress((void**)&wvpk, g_wvpk);
    cudaGetSymbolAddress((void**)&wopk, g_wopk);
    cudaGetSymbolAddress((void**)&qhpk, g_qhpk);
    cudaGetSymbolAddress((void**)&khpk, g_khpk);
    cudaGetSymbolAddress((void**)&vTpk, g_vTpk);
    cudaGetSymbolAddress((void**)&oapk, g_oapk);
    cudaGetSymbolAddress((void**)&vh,   g_vh);
    cudaGetSymbolAddress((void**)&op,   g_op);
    cudaGetSymbolAddress((void**)&rs,   g_rs);

    const int SMEM128 = 3 * (16384 + 128 * 128) + 1024;   // 99328
    const int SMEM64  = 3 * (16384 + 64 * 128) + 1024;    // 74752
    cudaFuncSetAttribute((const void*)pk_gemm<128, 0>, cudaFuncAttributeMaxDynamicSharedMemorySize, SMEM128);
    cudaFuncSetAttribute((const void*)pk_gemm<128, 1>, cudaFuncAttributeMaxDynamicSharedMemorySize, SMEM128);
    cudaFuncSetAttribute((const void*)pk_gemm<128, 2>, cudaFuncAttributeMaxDynamicSharedMemorySize, SMEM128);
    cudaFuncSetAttribute((const void*)pk_gemm<64, 3>,  cudaFuncAttributeMaxDynamicSharedMemorySize, SMEM64);

    dim3 blk(256);

    zero_rs<<<NROWS_ATTN / 256, blk>>>(rs);

    // pack inputs + weights (batched)
    pack_split3<<<dim3(MROWS_ * D_ / 4 / 256, 1, 3), blk>>>(q, k, v, qpk, kpk, vpk, D_);
    pack_split3<<<dim3(HD_ * D_ / 4 / 256, 1, 3), blk>>>(wq, wk, wv, wqpk, wkpk, wvpk, D_);
    pack_split1<<<D_ * HD_ / 4 / 256, blk>>>(wo, wopk, HD_);

    const long long ld32 = 32 * 128;   // 4096B row (K=1024)
    const long long ld64 = 64 * 128;   // 8192B row (K=2048)

    // QKV projections (K=1024 -> 32 chunks), 128x128 tiles
    dim3 gproj(HD_ / 128, MROWS_ / 128, 1);
    pk_gemm<128, 1><<<gproj, blk, SMEM128>>>(qpk, wqpk, bq, nullptr, qhpk, nullptr,
        32, ld32, ld32, 0, ld32, 1,
        0, 0, 0, 0, 0, 0, 0, 0, 0, 0, 1.0f);
    pk_gemm<128, 1><<<gproj, blk, SMEM128>>>(kpk, wkpk, bk, nullptr, khpk, nullptr,
        32, ld32, ld32, 0, ld32, 1,
        0, 0, 0, 0, 0, 0, 0, 0, 0, 0, 1.0f);
    pk_gemm<128, 0><<<gproj, blk, SMEM128>>>(vpk, wvpk, bv, vh, nullptr, nullptr,
        32, ld32, ld32, HD_, 0, 1,
        0, 0, 0, 0, 0, 0, 0, 0, 0, 0, 1.0f);

    transpose_v_pk<<<dim3(L_ / 32, DK_ / 32, B_ * H_), blk>>>(vh, vTpk);

    // Scores (K=64 -> 2 chunks), 128x128 tiles
    dim3 gsc(L_ / 128, L_ / 128, B_ * H_);
    pk_gemm<128, 2><<<gsc, blk, SMEM128>>>(qhpk, khpk, nullptr, nullptr, attn_b, rs,
        2, ld32, ld32, 0, ld64, H_,
        (long long)L_ * ld32, 256,
        (long long)L_ * ld32, 256,
        0, 0,
        (long long)L_ * L_ * 4, (long long)B_ * L_ * L_ * 4,
        (long long)L_, (long long)B_ * L_,
        0.125f);

    // PV (K=2048 -> 64 chunks), 128x64 tiles: in-place normalized P + oa packed
    dim3 gpv(1, L_ / 128, B_ * H_);
    pk_gemm<64, 3><<<gpv, blk, SMEM64>>>(attn_b, vTpk, nullptr, attn, oapk, rs,
        64, ld64, ld64, L_, ld32, H_,
        (long long)L_ * L_ * 4, (long long)B_ * L_ * L_ * 4,
        (long long)DK_ * ld64 * H_, (long long)DK_ * ld64,
        (long long)L_ * L_, (long long)B_ * L_ * L_,
        (long long)L_ * ld32, 256,
        (long long)L_, (long long)B_ * L_,
        1.0f);

    // Output projection (K=1024 -> 32 chunks), 128x128 tiles
    dim3 gop(D_ / 128, MROWS_ / 128, 1);
    pk_gemm<128, 0><<<gop, blk, SMEM128>>>(oapk, wopk, bo, op, nullptr, nullptr,
        32, ld32, ld32, D_, 0, 1,
        0, 0, 0, 0, 0, 0, 0, 0, 0, 0, 1.0f);

    // LayerNorm + residual
    ln_residual<<<MROWS_, blk>>>(op, q, lg, lb, out);
}

// round 11
// speedup vs baseline: 1.0948x; 1.0948x over previous
#include <cuda_runtime.h>
#include <cuda_fp16.h>
#include <stdint.h>

#define B_   4
#define L_   2048
#define D_   1024
#define H_   16
#define DK_  64
#define HD_  1024
#define MROWS_ 8192
#define LN_EPS_ 1e-5f
#define NROWS_ATTN (B_ * H_ * L_)

// ---------------------------------------------------------------------------
// Scratch (device globals). Packed split-fp16: [M][K/32][32 hi | 32 lo] 128B.
// ---------------------------------------------------------------------------
__device__ __align__(256) uint8_t g_qpk [(long long)MROWS_ * D_ * 4];
__device__ __align__(256) uint8_t g_kpk [(long long)MROWS_ * D_ * 4];
__device__ __align__(256) uint8_t g_vpk [(long long)MROWS_ * D_ * 4];
__device__ __align__(256) uint8_t g_wqpk[(long long)HD_ * D_ * 4];
__device__ __align__(256) uint8_t g_wkpk[(long long)HD_ * D_ * 4];
__device__ __align__(256) uint8_t g_wvpk[(long long)HD_ * D_ * 4];
__device__ __align__(256) uint8_t g_wopk[(long long)D_ * HD_ * 4];
__device__ __align__(256) uint8_t g_qhpk[(long long)MROWS_ * HD_ * 4];
__device__ __align__(256) uint8_t g_khpk[(long long)MROWS_ * HD_ * 4];
__device__ __align__(256) uint8_t g_vTpk[(long long)B_ * H_ * DK_ * L_ * 4];
__device__ __align__(256) uint8_t g_oapk[(long long)MROWS_ * HD_ * 4];
__device__ float g_vh[MROWS_ * HD_];
__device__ float g_op[MROWS_ * HD_];
__device__ float g_rs[NROWS_ATTN];

// ---------------------------------------------------------------------------
// helpers
// ---------------------------------------------------------------------------
__device__ __forceinline__ uint32_t smem_u32(const void* p) {
    uint32_t a;
    asm("{ .reg .u64 t; cvta.to.shared.u64 t, %1; cvt.u32.u64 %0, t; }" : "=r"(a) : "l"(p));
    return a;
}
__device__ __forceinline__ uint32_t sw128(uint32_t off) {
    return off ^ ((off >> 3) & 0x70);
}
__device__ __forceinline__ void cpa16(uint32_t dst, const void* src) {
    asm volatile("cp.async.cg.shared.global [%0], [%1], 16;" :: "r"(dst), "l"(src));
}
#define CP_COMMIT() asm volatile("cp.async.commit_group;" ::: "memory")
#define CP_WAIT0()  asm volatile("cp.async.wait_group 0;" ::: "memory")
#define CP_WAIT1()  asm volatile("cp.async.wait_group 1;" ::: "memory")
#define LDSM_X4(r0, r1, r2, r3, addr)                                      \
    asm volatile("ldmatrix.sync.aligned.m8n8.x4.shared.b16 "               \
                 "{%0,%1,%2,%3}, [%4];"                                    \
                 : "=r"(r0), "=r"(r1), "=r"(r2), "=r"(r3) : "r"(addr))

__device__ __forceinline__ void mma16816(float* d, const uint32_t* a, const uint32_t* b) {
    asm volatile(
        "mma.sync.aligned.m16n8k16.row.col.f32.f16.f16.f32 "
        "{%0,%1,%2,%3}, {%4,%5,%6,%7}, {%8,%9}, {%0,%1,%2,%3};"
        : "+f"(d[0]), "+f"(d[1]), "+f"(d[2]), "+f"(d[3])
        : "r"(a[0]), "r"(a[1]), "r"(a[2]), "r"(a[3]), "r"(b[0]), "r"(b[1]));
}

__device__ __forceinline__ void pack_store2(uint8_t* p, float v0, float v1) {
    __half2 h = __float22half2_rn(make_float2(v0, v1));
    float2 f = __half22float2(h);
    __half2 l = __float22half2_rn(make_float2(v0 - f.x, v1 - f.y));
    *(uint32_t*)p = *(uint32_t*)&h;
    *(uint32_t*)(p + 64) = *(uint32_t*)&l;
}
__device__ __forceinline__ void pack_store4(uint8_t* p, float4 v) {
    __half2 h0 = __float22half2_rn(make_float2(v.x, v.y));
    __half2 h1 = __float22half2_rn(make_float2(v.z, v.w));
    float2 f0 = __half22float2(h0), f1 = __half22float2(h1);
    __half2 l0 = __float22half2_rn(make_float2(v.x - f0.x, v.y - f0.y));
    __half2 l1 = __float22half2_rn(make_float2(v.z - f1.x, v.w - f1.y));
    uint2 hu, lu;
    hu.x = *(uint32_t*)&h0; hu.y = *(uint32_t*)&h1;
    lu.x = *(uint32_t*)&l0; lu.y = *(uint32_t*)&l1;
    *(uint2*)p = hu;
    *(uint2*)(p + 64) = lu;
}
__device__ __forceinline__ void combine8(const uint4 h, const uint4 l, float inv, float* out) {
    const uint32_t hu[4] = { h.x, h.y, h.z, h.w };
    const uint32_t lu[4] = { l.x, l.y, l.z, l.w };
#pragma unroll
    for (int j = 0; j < 4; j++) {
        __half2 hb = *(const __half2*)&hu[j];
        __half2 lb = *(const __half2*)&lu[j];
        float2 hf = __half22float2(hb), lf = __half22float2(lb);
        out[2 * j]     = (hf.x + lf.x) * inv;
        out[2 * j + 1] = (hf.y + lf.y) * inv;
    }
}

// ---------------------------------------------------------------------------
// pack fp32 [M,K] -> packed split fp16 ; batched over 3 tensors via blockIdx.z
// ---------------------------------------------------------------------------
__global__ void __launch_bounds__(256)
pack_split3(const float* __restrict__ s0, const float* __restrict__ s1,
            const float* __restrict__ s2,
            uint8_t* __restrict__ d0, uint8_t* __restrict__ d1,
            uint8_t* __restrict__ d2, int K)
{
    const float* src = (blockIdx.z == 0) ? s0 : (blockIdx.z == 1) ? s1 : s2;
    uint8_t* dst = (blockIdx.z == 0) ? d0 : (blockIdx.z == 1) ? d1 : d2;
    const long long idx = (long long)blockIdx.x * 256 + threadIdx.x;
    const int perRow = K >> 2;
    const long long m = idx / perRow;
    const int j = (int)(idx - m * perRow);
    float4 v = *(const float4*)(src + m * K + j * 4);
    const int e0 = j * 4;
    uint8_t* p = dst + (m * (K >> 5) + (e0 >> 5)) * 128 + (e0 & 31) * 2;
    pack_store4(p, v);
}
__global__ void __launch_bounds__(256)
pack_split1(const float* __restrict__ src, uint8_t* __restrict__ dst, int K)
{
    const long long idx = (long long)blockIdx.x * 256 + threadIdx.x;
    const int perRow = K >> 2;
    const long long m = idx / perRow;
    const int j = (int)(idx - m * perRow);
    float4 v = *(const float4*)(src + m * K + j * 4);
    const int e0 = j * 4;
    uint8_t* p = dst + (m * (K >> 5) + (e0 >> 5)) * 128 + (e0 & 31) * 2;
    pack_store4(p, v);
}

// ---------------------------------------------------------------------------
// Packed split-fp16 GEMM. CTA tile 128 x TN, 32-K chunks, 8 warps as 4x2
// (warp tile 32 x TN/2), 2 CTAs/SM. PASSES=3: hh+lh+hl. PASSES=2: hh+lh
// (B-lo never read; error ~2^-11 on the B side).
// MODE 0: C fp32 + bias.  MODE 1: C packed + bias.
// MODE 2: exp(alpha*acc)*2^-4 -> packed + rowsum atomics (scale cancels).
// MODE 3: A staged tiles -> normalized fp32 P write; epilogue *1/rowsum -> packed.
// ---------------------------------------------------------------------------
template<int TN, int MODE, int PASSES>
__global__ void __launch_bounds__(256, 2)
pk_gemm(const uint8_t* Apk, const uint8_t* __restrict__ Bpk,
        const float* __restrict__ bias,
        float* Cf, uint8_t* Cpk, float* rs,
        int nchunks, long long ldA, long long ldB, int ldc, long long ldCpk,
        int zdiv,
        long long sAo, long long sAi, long long sBo, long long sBi,
        long long sCfO, long long sCfI, long long sCpO, long long sCpI,
        long long rsO, long long rsI, float alpha)
{
    constexpr int NT = TN / 16;            // n8-tiles per warp
    constexpr int NB = TN / 32;            // B cp.async per thread per chunk
    constexpr int STAGE = 16384 + TN * 128;

    extern __shared__ uint8_t dyn_raw[];
    __shared__ float s_bias[TN];
    __shared__ float s_aux[128];

    const int tid = threadIdx.x, wid = tid >> 5, lane = tid & 31;
    const int z = blockIdx.z, zo = z / zdiv, zi = z - zo * zdiv;
    Apk += zo * sAo + zi * sAi;
    Bpk += zo * sBo + zi * sBi;
    if (MODE == 0 || MODE == 3) Cf += zo * sCfO + zi * sCfI;
    if (MODE != 0) Cpk += zo * sCpO + zi * sCpI;
    const long long rs_off = zo * rsO + zi * rsI;

    const long long m0 = (long long)blockIdx.y * 128;
    const long long n0 = (long long)blockIdx.x * TN;

    uint32_t raw = smem_u32(dyn_raw);
    uint32_t base = (raw + 1023u) & ~1023u;
    uint8_t* dsm = dyn_raw + (base - raw);
    uint8_t* smA[2] = { dsm, dsm + STAGE };
    const uint32_t aSu[2] = { base, base + STAGE };
    const uint32_t bSu[2] = { base + 16384, base + STAGE + 16384 };

    if (MODE == 0 || MODE == 1) {
        for (int i = tid; i < TN; i += 256) s_bias[i] = bias ? bias[n0 + i] : 0.0f;
    }
    if (MODE == 2) { if (tid < 128) s_aux[tid] = 0.0f; }
    if (MODE == 3) { if (tid < 128) s_aux[tid] = 1.0f / rs[rs_off + m0 + tid]; }

    float acc[2][NT][4];
#pragma unroll
    for (int i = 0; i < 2; i++)
#pragma unroll
        for (int j = 0; j < NT; j++)
#pragma unroll
            for (int e = 0; e < 4; e++) acc[i][j][e] = 0.0f;

    const uint32_t a_row = (uint32_t)((lane & 7) + (lane & 8));
    const uint32_t a_kof = (uint32_t)(((lane >> 4) & 1) * 16);
    const uint32_t b_row = (uint32_t)((lane & 7) + ((lane >> 4) & 1) * 8);
    const uint32_t b_kof = (uint32_t)(((lane >> 3) & 1) * 16);
    const int wm = (wid & 3) * 32;
    const int wn = (wid >> 2) * (TN / 2);

    auto prefetch = [&](int s, int c) {
        const uint8_t* Ab = Apk + (long long)c * 128;
#pragma unroll
        for (int i = 0; i < 4; i++) {
            const int idx = i * 256 + tid, row = idx >> 3, g = idx & 7;
            cpa16(aSu[s] + sw128((uint32_t)(row * 128 + g * 16)),
                  Ab + (m0 + row) * ldA + g * 16);
        }
        const uint8_t* Bb = Bpk + (long long)c * 128;
#pragma unroll
        for (int i = 0; i < NB; i++) {
            const int idx = i * 256 + tid, row = idx >> 3, g = idx & 7;
            cpa16(bSu[s] + sw128((uint32_t)(row * 128 + g * 16)),
                  Bb + (n0 + row) * ldB + g * 16);
        }
        CP_COMMIT();
    };

    prefetch(0, 0);
    int cur = 0;
    for (int c = 0; c < nchunks; c++) {
        if (c + 1 < nchunks) {
            prefetch(cur ^ 1, c + 1);
            CP_WAIT1();
        } else {
            CP_WAIT0();
        }
        __syncthreads();

        if (MODE == 3) {
            // reconstruct normalized fp32 P for this 32-K chunk (in place)
            const int r = tid >> 1, hh = tid & 1;
            const uint8_t* sa = smA[cur];
            const float inv = s_aux[r];
            uint4 h0 = *(const uint4*)(sa + sw128((uint32_t)(r * 128 + hh * 32)));
            uint4 h1 = *(const uint4*)(sa + sw128((uint32_t)(r * 128 + hh * 32 + 16)));
            uint4 l0 = *(const uint4*)(sa + sw128((uint32_t)(r * 128 + 64 + hh * 32)));
            uint4 l1 = *(const uint4*)(sa + sw128((uint32_t)(r * 128 + 64 + hh * 32 + 16)));
            float o[16];
            combine8(h0, l0, inv, o);
            combine8(h1, l1, inv, o + 8);
            float* dst = Cf + (m0 + r) * (long long)ldc + c * 32 + hh * 16;
            *(float4*)(dst +  0) = make_float4(o[0],  o[1],  o[2],  o[3]);
            *(float4*)(dst +  4) = make_float4(o[4],  o[5],  o[6],  o[7]);
            *(float4*)(dst +  8) = make_float4(o[8],  o[9],  o[10], o[11]);
            *(float4*)(dst + 12) = make_float4(o[12], o[13], o[14], o[15]);
        }

        const uint32_t aS = aSu[cur], bS = bSu[cur];
#pragma unroll
        for (int ks = 0; ks < 2; ks++) {
            uint32_t ah[2][4], al[2][4], bf[NT][2];
            // A hi
#pragma unroll
            for (int mt = 0; mt < 2; mt++) {
                uint32_t off = (uint32_t)(wm + mt * 16 + a_row) * 128 + ks * 32 + a_kof;
                LDSM_X4(ah[mt][0], ah[mt][1], ah[mt][2], ah[mt][3], aS + sw128(off));
            }
            // B hi
#pragma unroll
            for (int p = 0; p < NT / 2; p++) {
                uint32_t r0, r1, r2, r3;
                uint32_t off = (uint32_t)(wn + p * 16 + b_row) * 128 + ks * 32 + b_kof;
                LDSM_X4(r0, r1, r2, r3, bS + sw128(off));
                bf[2 * p][0] = r0; bf[2 * p][1] = r1;
                bf[2 * p + 1][0] = r2; bf[2 * p + 1][1] = r3;
            }
            // pass 1: hi x hi
#pragma unroll
            for (int mt = 0; mt < 2; mt++)
#pragma unroll
                for (int nt = 0; nt < NT; nt++)
                    mma16816(acc[mt][nt], ah[mt], bf[nt]);
            // A lo
#pragma unroll
            for (int mt = 0; mt < 2; mt++) {
                uint32_t off = (uint32_t)(wm + mt * 16 + a_row) * 128 + 64 + ks * 32 + a_kof;
                LDSM_X4(al[mt][0], al[mt][1], al[mt][2], al[mt][3], aS + sw128(off));
            }
            // pass 2: lo x hi
#pragma unroll
            for (int mt = 0; mt < 2; mt++)
#pragma unroll
                for (int nt = 0; nt < NT; nt++)
                    mma16816(acc[mt][nt], al[mt], bf[nt]);
            if (PASSES == 3) {
                // B lo (reuse bf)
#pragma unroll
                for (int p = 0; p < NT / 2; p++) {
                    uint32_t r0, r1, r2, r3;
                    uint32_t off = (uint32_t)(wn + p * 16 + b_row) * 128 + 64 + ks * 32 + b_kof;
                    LDSM_X4(r0, r1, r2, r3, bS + sw128(off));
                    bf[2 * p][0] = r0; bf[2 * p][1] = r1;
                    bf[2 * p + 1][0] = r2; bf[2 * p + 1][1] = r3;
                }
                // pass 3: hi x lo
#pragma unroll
                for (int mt = 0; mt < 2; mt++)
#pragma unroll
                    for (int nt = 0; nt < NT; nt++)
                        mma16816(acc[mt][nt], ah[mt], bf[nt]);
            }
        }
        __syncthreads();
        cur ^= 1;
    }

    // ---- epilogue ----
    const int g = lane >> 2, t = lane & 3;
    if (MODE == 2) {
        const float esc = 0.0625f;   // 2^-4: keeps exp inside fp16 range; cancels in norm
#pragma unroll
        for (int mt = 0; mt < 2; mt++) {
            float sum0 = 0.0f, sum1 = 0.0f;
#pragma unroll
            for (int nt = 0; nt < NT; nt++) {
                const int colw = wn + nt * 8 + 2 * t;
                const long long row0 = m0 + wm + mt * 16 + g;
                float e0 = __expf(acc[mt][nt][0] * alpha) * esc;
                float e1 = __expf(acc[mt][nt][1] * alpha) * esc;
                float e2 = __expf(acc[mt][nt][2] * alpha) * esc;
                float e3 = __expf(acc[mt][nt][3] * alpha) * esc;
                const long long colg = n0 + colw;
                const long long ch = colg >> 5;
                const int wi = (int)(colg & 31);
                pack_store2(Cpk + row0 * ldCpk + ch * 128 + wi * 2, e0, e1);
                pack_store2(Cpk + (row0 + 8) * ldCpk + ch * 128 + wi * 2, e2, e3);
                sum0 += e0 + e1; sum1 += e2 + e3;
            }
            sum0 += __shfl_xor_sync(0xffffffffu, sum0, 1);
            sum0 += __shfl_xor_sync(0xffffffffu, sum0, 2);
            sum1 += __shfl_xor_sync(0xffffffffu, sum1, 1);
            sum1 += __shfl_xor_sync(0xffffffffu, sum1, 2);
            if (t == 0) {
                atomicAdd(&s_aux[wm + mt * 16 + g], sum0);
                atomicAdd(&s_aux[wm + mt * 16 + g + 8], sum1);
            }
        }
        __syncthreads();
        if (tid < 128)
            atomicAdd(&rs[rs_off + m0 + tid], s_aux[tid]);
    } else if (MODE == 1 || MODE == 3) {
#pragma unroll
        for (int mt = 0; mt < 2; mt++) {
            const float i0 = (MODE == 3) ? s_aux[wm + mt * 16 + g] : 1.0f;
            const float i1 = (MODE == 3) ? s_aux[wm + mt * 16 + g + 8] : 1.0f;
#pragma unroll
            for (int nt = 0; nt < NT; nt++) {
                const int colw = wn + nt * 8 + 2 * t;
                const long long row0 = m0 + wm + mt * 16 + g;
                const float b0 = (MODE == 1) ? s_bias[colw] : 0.0f;
                const float b1 = (MODE == 1) ? s_bias[colw + 1] : 0.0f;
                float v0 = acc[mt][nt][0] * i0 + b0;
                float v1 = acc[mt][nt][1] * i0 + b1;
                float v2 = acc[mt][nt][2] * i1 + b0;
                float v3 = acc[mt][nt][3] * i1 + b1;
                const long long colg = n0 + colw;
                const long long ch = colg >> 5;
                const int wi = (int)(colg & 31);
                pack_store2(Cpk + row0 * ldCpk + ch * 128 + wi * 2, v0, v1);
                pack_store2(Cpk + (row0 + 8) * ldCpk + ch * 128 + wi * 2, v2, v3);
            }
        }
    } else {
#pragma unroll
        for (int mt = 0; mt < 2; mt++) {
#pragma unroll
            for (int nt = 0; nt < NT; nt++) {
                const int colw = wn + nt * 8 + 2 * t;
                const float b0 = s_bias[colw], b1 = s_bias[colw + 1];
                const long long row0 = m0 + wm + mt * 16 + g;
                *(float2*)(Cf + row0 * (long long)ldc + n0 + colw) =
                    make_float2(acc[mt][nt][0] + b0, acc[mt][nt][1] + b1);
                *(float2*)(Cf + (row0 + 8) * (long long)ldc + n0 + colw) =
                    make_float2(acc[mt][nt][2] + b0, acc[mt][nt][3] + b1);
            }
        }
    }
}

// ---------------------------------------------------------------------------
// V transpose: vh fp32 [B,L,H,DK] -> vT packed [(b*H+h)][dk][L/32][128B]
// ---------------------------------------------------------------------------
__global__ void __launch_bounds__(256)
transpose_v_pk(const float* __restrict__ vh, uint8_t* __restrict__ vT)
{
    __shared__ float tsm[32][33];
    const int bh = blockIdx.z;
    const int b = bh >> 4, h = bh & 15;
    const int l0 = blockIdx.x * 32;
    const int d0 = blockIdx.y * 32;
    const int tid = threadIdx.x;
    const int tx = tid & 31;
    const int ty = tid >> 5;

    const float* src = vh + ((long long)b * L_ + l0) * HD_ + h * DK_ + d0;
#pragma unroll
    for (int i = 0; i < 32; i += 8)
        tsm[ty + i][tx] = src[(long long)(ty + i) * HD_ + tx];
    __syncthreads();

    const int lp = tid & 15;
#pragma unroll
    for (int it = 0; it < 2; it++) {
        const int d = (tid >> 4) + 16 * it;
        uint8_t* p = vT + ((long long)bh * 64 + d0 + d) * (L_ / 32 * 128)
                        + (l0 >> 5) * 128 + lp * 4;
        pack_store2(p, tsm[2 * lp][d], tsm[2 * lp + 1][d]);
    }
}

__global__ void zero_rs(float* __restrict__ rs)
{
    rs[blockIdx.x * 256 + threadIdx.x] = 0.0f;
}

// ---------------------------------------------------------------------------
// LayerNorm + residual
// ---------------------------------------------------------------------------
__global__ void __launch_bounds__(256)
ln_residual(const float* __restrict__ x, const float* __restrict__ res,
            const float* __restrict__ gam, const float* __restrict__ bet,
            float* __restrict__ out)
{
    const long long row = blockIdx.x;
    const float4* x4 = (const float4*)(x   + row * D_);
    const float4* r4 = (const float4*)(res + row * D_);
    const int tid = threadIdx.x;

    float4 v = x4[tid];
    float s  = (v.x + v.y) + (v.z + v.w);
    float sq = (v.x * v.x + v.y * v.y) + (v.z * v.z + v.w * v.w);
#pragma unroll
    for (int o = 16; o > 0; o >>= 1) {
        s  += __shfl_xor_sync(0xffffffffu, s,  o);
        sq += __shfl_xor_sync(0xffffffffu, sq, o);
    }
    __shared__ float ss[8], sqs[8];
    if ((tid & 31) == 0) { ss[tid >> 5] = s; sqs[tid >> 5] = sq; }
    __syncthreads();
    s  = (ss[0]  + ss[1])  + (ss[2]  + ss[3])  + (ss[4]  + ss[5])  + (ss[6]  + ss[7]);
    sq = (sqs[0] + sqs[1]) + (sqs[2] + sqs[3]) + (sqs[4] + sqs[5]) + (sqs[6] + sqs[7]);

    const float mean = s * (1.0f / D_);
    float var = sq * (1.0f / D_) - mean * mean;
    var = fmaxf(var, 0.0f);
    const float rstd = rsqrtf(var + LN_EPS_);

    float4 g  = ((const float4*)gam)[tid];
    float4 bt = ((const float4*)bet)[tid];
    float4 r  = r4[tid];
    float4 o;
    o.x = (v.x - mean) * rstd * g.x + bt.x + r.x;
    o.y = (v.y - mean) * rstd * g.y + bt.y + r.y;
    o.z = (v.z - mean) * rstd * g.z + bt.z + r.z;
    o.w = (v.w - mean) * rstd * g.w + bt.w + r.w;
    ((float4*)(out + row * D_))[tid] = o;
}

// ---------------------------------------------------------------------------
// Launch
// ---------------------------------------------------------------------------
extern "C" void kernel_launch(void* const* d_in, const int* in_sizes, int n_in,
                              void* d_out, int out_size)
{
    (void)in_sizes; (void)n_in; (void)out_size;
    const float* q  = (const float*)d_in[0];
    const float* k  = (const float*)d_in[1];
    const float* v  = (const float*)d_in[2];
    const float* wq = (const float*)d_in[3];
    const float* bq = (const float*)d_in[4];
    const float* wk = (const float*)d_in[5];
    const float* bk = (const float*)d_in[6];
    const float* wv = (const float*)d_in[7];
    const float* bv = (const float*)d_in[8];
    const float* wo = (const float*)d_in[9];
    const float* bo = (const float*)d_in[10];
    const float* lg = (const float*)d_in[11];
    const float* lb = (const float*)d_in[12];

    float* out  = (float*)d_out;
    float* attn = out + (long long)B_ * L_ * D_;
    uint8_t* attn_b = (uint8_t*)attn;

    uint8_t *qpk, *kpk, *vpk, *wqpk, *wkpk, *wvpk, *wopk, *qhpk, *khpk, *vTpk, *oapk;
    float *vh, *op, *rs;
    cudaGetSymbolAddress((void**)&qpk,  g_qpk);
    cudaGetSymbolAddress((void**)&kpk,  g_kpk);
    cudaGetSymbolAddress((void**)&vpk,  g_vpk);
    cudaGetSymbolAddress((void**)&wqpk, g_wqpk);
    cudaGetSymbolAddress((void**)&wkpk, g_wkpk);
    cudaGetSymbolAddress((void**)&wvpk, g_wvpk);
    cudaGetSymbolAddress((void**)&wopk, g_wopk);
    cudaGetSymbolAddress((void**)&qhpk, g_qhpk);
    cudaGetSymbolAddress((void**)&khpk, g_khpk);
    cudaGetSymbolAddress((void**)&vTpk, g_vTpk);
    cudaGetSymbolAddress((void**)&oapk, g_oapk);
    cudaGetSymbolAddress((void**)&vh,   g_vh);
    cudaGetSymbolAddress((void**)&op,   g_op);
    cudaGetSymbolAddress((void**)&rs,   g_rs);

    const int SMEM128 = 2 * (16384 + 128 * 128) + 1024;   // 66560
    const int SMEM64  = 2 * (16384 + 64 * 128) + 1024;    // 50176
    cudaFuncSetAttribute((const void*)pk_gemm<128, 0, 2>, cudaFuncAttributeMaxDynamicSharedMemorySize, SMEM128);
    cudaFuncSetAttribute((const void*)pk_gemm<128, 1, 3>, cudaFuncAttributeMaxDynamicSharedMemorySize, SMEM128);
    cudaFuncSetAttribute((const void*)pk_gemm<128, 2, 3>, cudaFuncAttributeMaxDynamicSharedMemorySize, SMEM128);
    cudaFuncSetAttribute((const void*)pk_gemm<64, 3, 2>,  cudaFuncAttributeMaxDynamicSharedMemorySize, SMEM64);

    dim3 blk(256);

    zero_rs<<<NROWS_ATTN / 256, blk>>>(rs);

    // pack inputs + weights (batched)
    pack_split3<<<dim3(MROWS_ * D_ / 4 / 256, 1, 3), blk>>>(q, k, v, qpk, kpk, vpk, D_);
    pack_split3<<<dim3(HD_ * D_ / 4 / 256, 1, 3), blk>>>(wq, wk, wv, wqpk, wkpk, wvpk, D_);
    pack_split1<<<D_ * HD_ / 4 / 256, blk>>>(wo, wopk, HD_);

    const long long ld32 = 32 * 128;   // 4096B row (K=1024)
    const long long ld64 = 64 * 128;   // 8192B row (K=2048)

    // Q/K projections: 3-pass (feeds exp-amplified scores). V projection: 2-pass.
    dim3 gproj(HD_ / 128, MROWS_ / 128, 1);
    pk_gemm<128, 1, 3><<<gproj, blk, SMEM128>>>(qpk, wqpk, bq, nullptr, qhpk, nullptr,
        32, ld32, ld32, 0, ld32, 1,
        0, 0, 0, 0, 0, 0, 0, 0, 0, 0, 1.0f);
    pk_gemm<128, 1, 3><<<gproj, blk, SMEM128>>>(kpk, wkpk, bk, nullptr, khpk, nullptr,
        32, ld32, ld32, 0, ld32, 1,
        0, 0, 0, 0, 0, 0, 0, 0, 0, 0, 1.0f);
    pk_gemm<128, 0, 2><<<gproj, blk, SMEM128>>>(vpk, wvpk, bv, vh, nullptr, nullptr,
        32, ld32, ld32, HD_, 0, 1,
        0, 0, 0, 0, 0, 0, 0, 0, 0, 0, 1.0f);

    transpose_v_pk<<<dim3(L_ / 32, DK_ / 32, B_ * H_), blk>>>(vh, vTpk);

    // Scores (K=64 -> 2 chunks), 3-pass, 128x128 tiles
    dim3 gsc(L_ / 128, L_ / 128, B_ * H_);
    pk_gemm<128, 2, 3><<<gsc, blk, SMEM128>>>(qhpk, khpk, nullptr, nullptr, attn_b, rs,
        2, ld32, ld32, 0, ld64, H_,
        (long long)L_ * ld32, 256,
        (long long)L_ * ld32, 256,
        0, 0,
        (long long)L_ * L_ * 4, (long long)B_ * L_ * L_ * 4,
        (long long)L_, (long long)B_ * L_,
        0.125f);

    // PV (K=2048 -> 64 chunks), 2-pass (V-lo dropped): in-place normalized P + oa packed
    dim3 gpv(1, L_ / 128, B_ * H_);
    pk_gemm<64, 3, 2><<<gpv, blk, SMEM64>>>(attn_b, vTpk, nullptr, attn, oapk, rs,
        64, ld64, ld64, L_, ld32, H_,
        (long long)L_ * L_ * 4, (long long)B_ * L_ * L_ * 4,
        (long long)DK_ * ld64 * H_, (long long)DK_ * ld64,
        (long long)L_ * L_, (long long)B_ * L_ * L_,
        (long long)L_ * ld32, 256,
        (long long)L_, (long long)B_ * L_,
        1.0f);

    // Output projection (K=1024 -> 32 chunks), 2-pass, 128x128 tiles
    dim3 gop(D_ / 128, MROWS_ / 128, 1);
    pk_gemm<128, 0, 2><<<gop, blk, SMEM128>>>(oapk, wopk, bo, op, nullptr, nullptr,
        32, ld32, ld32, D_, 0, 1,
        0, 0, 0, 0, 0, 0, 0, 0, 0, 0, 1.0f);

    // LayerNorm + residual
    ln_residual<<<MROWS_, blk>>>(op, q, lg, lb, out);
}

// round 12
// speedup vs baseline: 1.2186x; 1.1132x over previous
#include <cuda_runtime.h>
#include <cuda_fp16.h>
#include <stdint.h>

#define B_   4
#define L_   2048
#define D_   1024
#define H_   16
#define DK_  64
#define HD_  1024
#define MROWS_ 8192
#define LN_EPS_ 1e-5f
#define NROWS_ATTN (B_ * H_ * L_)

// ---------------------------------------------------------------------------
// Scratch (device globals). Packed split-fp16: [M][K/32][32 hi | 32 lo] 128B.
// ---------------------------------------------------------------------------
__device__ __align__(256) uint8_t g_qpk [(long long)MROWS_ * D_ * 4];
__device__ __align__(256) uint8_t g_kpk [(long long)MROWS_ * D_ * 4];
__device__ __align__(256) uint8_t g_vpk [(long long)MROWS_ * D_ * 4];
__device__ __align__(256) uint8_t g_wqpk[(long long)HD_ * D_ * 4];
__device__ __align__(256) uint8_t g_wkpk[(long long)HD_ * D_ * 4];
__device__ __align__(256) uint8_t g_wvpk[(long long)HD_ * D_ * 4];
__device__ __align__(256) uint8_t g_wopk[(long long)D_ * HD_ * 4];
__device__ __align__(256) uint8_t g_qhpk[(long long)MROWS_ * HD_ * 4];
__device__ __align__(256) uint8_t g_khpk[(long long)MROWS_ * HD_ * 4];
__device__ __align__(256) uint8_t g_vTpk[(long long)B_ * H_ * DK_ * L_ * 4];
__device__ __align__(256) uint8_t g_oapk[(long long)MROWS_ * HD_ * 4];
__device__ float g_vh[MROWS_ * HD_];
__device__ float g_op[MROWS_ * HD_];
__device__ float g_rs[NROWS_ATTN];

// ---------------------------------------------------------------------------
// helpers
// ---------------------------------------------------------------------------
__device__ __forceinline__ uint32_t smem_u32(const void* p) {
    uint32_t a;
    asm("{ .reg .u64 t; cvta.to.shared.u64 t, %1; cvt.u32.u64 %0, t; }" : "=r"(a) : "l"(p));
    return a;
}
__device__ __forceinline__ uint32_t sw128(uint32_t off) {
    return off ^ ((off >> 3) & 0x70);
}
__device__ __forceinline__ void cpa16(uint32_t dst, const void* src) {
    asm volatile("cp.async.cg.shared.global [%0], [%1], 16;" :: "r"(dst), "l"(src));
}
#define CP_COMMIT() asm volatile("cp.async.commit_group;" ::: "memory")
#define CP_WAIT0()  asm volatile("cp.async.wait_group 0;" ::: "memory")
#define CP_WAIT1()  asm volatile("cp.async.wait_group 1;" ::: "memory")
#define LDSM_X4(r0, r1, r2, r3, addr)                                      \
    asm volatile("ldmatrix.sync.aligned.m8n8.x4.shared.b16 "               \
                 "{%0,%1,%2,%3}, [%4];"                                    \
                 : "=r"(r0), "=r"(r1), "=r"(r2), "=r"(r3) : "r"(addr))

__device__ __forceinline__ void mma16816(float* d, const uint32_t* a, const uint32_t* b) {
    asm volatile(
        "mma.sync.aligned.m16n8k16.row.col.f32.f16.f16.f32 "
        "{%0,%1,%2,%3}, {%4,%5,%6,%7}, {%8,%9}, {%0,%1,%2,%3};"
        : "+f"(d[0]), "+f"(d[1]), "+f"(d[2]), "+f"(d[3])
        : "r"(a[0]), "r"(a[1]), "r"(a[2]), "r"(a[3]), "r"(b[0]), "r"(b[1]));
}

__device__ __forceinline__ void pack_store2(uint8_t* p, float v0, float v1) {
    __half2 h = __float22half2_rn(make_float2(v0, v1));
    float2 f = __half22float2(h);
    __half2 l = __float22half2_rn(make_float2(v0 - f.x, v1 - f.y));
    *(uint32_t*)p = *(uint32_t*)&h;
    *(uint32_t*)(p + 64) = *(uint32_t*)&l;
}
__device__ __forceinline__ void pack_store4(uint8_t* p, float4 v) {
    __half2 h0 = __float22half2_rn(make_float2(v.x, v.y));
    __half2 h1 = __float22half2_rn(make_float2(v.z, v.w));
    float2 f0 = __half22float2(h0), f1 = __half22float2(h1);
    __half2 l0 = __float22half2_rn(make_float2(v.x - f0.x, v.y - f0.y));
    __half2 l1 = __float22half2_rn(make_float2(v.z - f1.x, v.w - f1.y));
    uint2 hu, lu;
    hu.x = *(uint32_t*)&h0; hu.y = *(uint32_t*)&h1;
    lu.x = *(uint32_t*)&l0; lu.y = *(uint32_t*)&l1;
    *(uint2*)p = hu;
    *(uint2*)(p + 64) = lu;
}
__device__ __forceinline__ void combine8(const uint4 h, const uint4 l, float inv, float* out) {
    const uint32_t hu[4] = { h.x, h.y, h.z, h.w };
    const uint32_t lu[4] = { l.x, l.y, l.z, l.w };
#pragma unroll
    for (int j = 0; j < 4; j++) {
        __half2 hb = *(const __half2*)&hu[j];
        __half2 lb = *(const __half2*)&lu[j];
        float2 hf = __half22float2(hb), lf = __half22float2(lb);
        out[2 * j]     = (hf.x + lf.x) * inv;
        out[2 * j + 1] = (hf.y + lf.y) * inv;
    }
}

// ---------------------------------------------------------------------------
// pack fp32 [M,K] -> packed split fp16 ; batched over 3 tensors via blockIdx.z
// ---------------------------------------------------------------------------
__global__ void __launch_bounds__(256)
pack_split3(const float* __restrict__ s0, const float* __restrict__ s1,
            const float* __restrict__ s2,
            uint8_t* __restrict__ d0, uint8_t* __restrict__ d1,
            uint8_t* __restrict__ d2, int K)
{
    const float* src = (blockIdx.z == 0) ? s0 : (blockIdx.z == 1) ? s1 : s2;
    uint8_t* dst = (blockIdx.z == 0) ? d0 : (blockIdx.z == 1) ? d1 : d2;
    const long long idx = (long long)blockIdx.x * 256 + threadIdx.x;
    const int perRow = K >> 2;
    const long long m = idx / perRow;
    const int j = (int)(idx - m * perRow);
    float4 v = *(const float4*)(src + m * K + j * 4);
    const int e0 = j * 4;
    uint8_t* p = dst + (m * (K >> 5) + (e0 >> 5)) * 128 + (e0 & 31) * 2;
    pack_store4(p, v);
}
__global__ void __launch_bounds__(256)
pack_split1(const float* __restrict__ src, uint8_t* __restrict__ dst, int K)
{
    const long long idx = (long long)blockIdx.x * 256 + threadIdx.x;
    const int perRow = K >> 2;
    const long long m = idx / perRow;
    const int j = (int)(idx - m * perRow);
    float4 v = *(const float4*)(src + m * K + j * 4);
    const int e0 = j * 4;
    uint8_t* p = dst + (m * (K >> 5) + (e0 >> 5)) * 128 + (e0 & 31) * 2;
    pack_store4(p, v);
}

// ---------------------------------------------------------------------------
// Packed split-fp16 GEMM. CTA tile 128 x TN, 32-K chunks, 8 warps as 4x2
// (warp tile 32 x TN/2), 2 CTAs/SM. All GEMMs 2-pass (hh + lh): B-lo is
// neither loaded from gmem nor read (error absorbed by alpha=1/8 for scores).
// MODE 0: C fp32 + bias.  MODE 1: C packed + bias.
// MODE 2: exp(alpha*acc)*2^-4 -> packed + rowsum atomics (scale cancels).
// MODE 3: A staged tiles -> normalized fp32 P write; epilogue *1/rowsum -> packed.
// ---------------------------------------------------------------------------
template<int TN, int MODE>
__global__ void __launch_bounds__(256, 2)
pk_gemm(const uint8_t* Apk, const uint8_t* __restrict__ Bpk,
        const float* __restrict__ bias,
        float* Cf, uint8_t* Cpk, float* rs,
        int nchunks, long long ldA, long long ldB, int ldc, long long ldCpk,
        int zdiv,
        long long sAo, long long sAi, long long sBo, long long sBi,
        long long sCfO, long long sCfI, long long sCpO, long long sCpI,
        long long rsO, long long rsI, float alpha)
{
    constexpr int NT = TN / 16;            // n8-tiles per warp
    constexpr int NBL = TN / 64;           // B hi-only cp.async iters (TN*4 granules / 256)
    constexpr int STAGE = 16384 + TN * 128;

    extern __shared__ uint8_t dyn_raw[];
    __shared__ float s_bias[TN];
    __shared__ float s_aux[128];

    const int tid = threadIdx.x, wid = tid >> 5, lane = tid & 31;
    const int z = blockIdx.z, zo = z / zdiv, zi = z - zo * zdiv;
    Apk += zo * sAo + zi * sAi;
    Bpk += zo * sBo + zi * sBi;
    if (MODE == 0 || MODE == 3) Cf += zo * sCfO + zi * sCfI;
    if (MODE != 0) Cpk += zo * sCpO + zi * sCpI;
    const long long rs_off = zo * rsO + zi * rsI;

    const long long m0 = (long long)blockIdx.y * 128;
    const long long n0 = (long long)blockIdx.x * TN;

    uint32_t raw = smem_u32(dyn_raw);
    uint32_t base = (raw + 1023u) & ~1023u;
    uint8_t* dsm = dyn_raw + (base - raw);
    uint8_t* smA[2] = { dsm, dsm + STAGE };
    const uint32_t aSu[2] = { base, base + STAGE };
    const uint32_t bSu[2] = { base + 16384, base + STAGE + 16384 };

    if (MODE == 0 || MODE == 1) {
        for (int i = tid; i < TN; i += 256) s_bias[i] = bias ? bias[n0 + i] : 0.0f;
    }
    if (MODE == 2) { if (tid < 128) s_aux[tid] = 0.0f; }
    if (MODE == 3) { if (tid < 128) s_aux[tid] = 1.0f / rs[rs_off + m0 + tid]; }

    float acc[2][NT][4];
#pragma unroll
    for (int i = 0; i < 2; i++)
#pragma unroll
        for (int j = 0; j < NT; j++)
#pragma unroll
            for (int e = 0; e < 4; e++) acc[i][j][e] = 0.0f;

    const uint32_t a_row = (uint32_t)((lane & 7) + (lane & 8));
    const uint32_t a_kof = (uint32_t)(((lane >> 4) & 1) * 16);
    const uint32_t b_row = (uint32_t)((lane & 7) + ((lane >> 4) & 1) * 8);
    const uint32_t b_kof = (uint32_t)(((lane >> 3) & 1) * 16);
    const int wm = (wid & 3) * 32;
    const int wn = (wid >> 2) * (TN / 2);

    auto prefetch = [&](int s, int c) {
        const uint8_t* Ab = Apk + (long long)c * 128;
#pragma unroll
        for (int i = 0; i < 4; i++) {       // A: full chunk (hi + lo)
            const int idx = i * 256 + tid, row = idx >> 3, g = idx & 7;
            cpa16(aSu[s] + sw128((uint32_t)(row * 128 + g * 16)),
                  Ab + (m0 + row) * ldA + g * 16);
        }
        const uint8_t* Bb = Bpk + (long long)c * 128;
#pragma unroll
        for (int i = 0; i < NBL; i++) {     // B: hi half only (g = 0..3)
            const int idx = i * 256 + tid, row = idx >> 2, g = idx & 3;
            cpa16(bSu[s] + sw128((uint32_t)(row * 128 + g * 16)),
                  Bb + (n0 + row) * ldB + g * 16);
        }
        CP_COMMIT();
    };

    prefetch(0, 0);
    int cur = 0;
    for (int c = 0; c < nchunks; c++) {
        if (c + 1 < nchunks) {
            prefetch(cur ^ 1, c + 1);
            CP_WAIT1();
        } else {
            CP_WAIT0();
        }
        __syncthreads();

        if (MODE == 3) {
            // reconstruct normalized fp32 P for this 32-K chunk (in place)
            const int r = tid >> 1, hh = tid & 1;
            const uint8_t* sa = smA[cur];
            const float inv = s_aux[r];
            uint4 h0 = *(const uint4*)(sa + sw128((uint32_t)(r * 128 + hh * 32)));
            uint4 h1 = *(const uint4*)(sa + sw128((uint32_t)(r * 128 + hh * 32 + 16)));
            uint4 l0 = *(const uint4*)(sa + sw128((uint32_t)(r * 128 + 64 + hh * 32)));
            uint4 l1 = *(const uint4*)(sa + sw128((uint32_t)(r * 128 + 64 + hh * 32 + 16)));
            float o[16];
            combine8(h0, l0, inv, o);
            combine8(h1, l1, inv, o + 8);
            float* dst = Cf + (m0 + r) * (long long)ldc + c * 32 + hh * 16;
            *(float4*)(dst +  0) = make_float4(o[0],  o[1],  o[2],  o[3]);
            *(float4*)(dst +  4) = make_float4(o[4],  o[5],  o[6],  o[7]);
            *(float4*)(dst +  8) = make_float4(o[8],  o[9],  o[10], o[11]);
            *(float4*)(dst + 12) = make_float4(o[12], o[13], o[14], o[15]);
        }

        const uint32_t aS = aSu[cur], bS = bSu[cur];
#pragma unroll
        for (int ks = 0; ks < 2; ks++) {
            uint32_t ah[2][4], al[2][4], bf[NT][2];
            // A hi
#pragma unroll
            for (int mt = 0; mt < 2; mt++) {
                uint32_t off = (uint32_t)(wm + mt * 16 + a_row) * 128 + ks * 32 + a_kof;
                LDSM_X4(ah[mt][0], ah[mt][1], ah[mt][2], ah[mt][3], aS + sw128(off));
            }
            // B hi
#pragma unroll
            for (int p = 0; p < NT / 2; p++) {
                uint32_t r0, r1, r2, r3;
                uint32_t off = (uint32_t)(wn + p * 16 + b_row) * 128 + ks * 32 + b_kof;
                LDSM_X4(r0, r1, r2, r3, bS + sw128(off));
                bf[2 * p][0] = r0; bf[2 * p][1] = r1;
                bf[2 * p + 1][0] = r2; bf[2 * p + 1][1] = r3;
            }
            // pass 1: hi x hi
#pragma unroll
            for (int mt = 0; mt < 2; mt++)
#pragma unroll
                for (int nt = 0; nt < NT; nt++)
                    mma16816(acc[mt][nt], ah[mt], bf[nt]);
            // A lo
#pragma unroll
            for (int mt = 0; mt < 2; mt++) {
                uint32_t off = (uint32_t)(wm + mt * 16 + a_row) * 128 + 64 + ks * 32 + a_kof;
                LDSM_X4(al[mt][0], al[mt][1], al[mt][2], al[mt][3], aS + sw128(off));
            }
            // pass 2: lo x hi
#pragma unroll
            for (int mt = 0; mt < 2; mt++)
#pragma unroll
                for (int nt = 0; nt < NT; nt++)
                    mma16816(acc[mt][nt], al[mt], bf[nt]);
        }
        __syncthreads();
        cur ^= 1;
    }

    // ---- epilogue ----
    const int g = lane >> 2, t = lane & 3;
    if (MODE == 2) {
        const float esc = 0.0625f;   // 2^-4: keeps exp inside fp16 range; cancels in norm
#pragma unroll
        for (int mt = 0; mt < 2; mt++) {
            float sum0 = 0.0f, sum1 = 0.0f;
#pragma unroll
            for (int nt = 0; nt < NT; nt++) {
                const int colw = wn + nt * 8 + 2 * t;
                const long long row0 = m0 + wm + mt * 16 + g;
                float e0 = __expf(acc[mt][nt][0] * alpha) * esc;
                float e1 = __expf(acc[mt][nt][1] * alpha) * esc;
                float e2 = __expf(acc[mt][nt][2] * alpha) * esc;
                float e3 = __expf(acc[mt][nt][3] * alpha) * esc;
                const long long colg = n0 + colw;
                const long long ch = colg >> 5;
                const int wi = (int)(colg & 31);
                pack_store2(Cpk + row0 * ldCpk + ch * 128 + wi * 2, e0, e1);
                pack_store2(Cpk + (row0 + 8) * ldCpk + ch * 128 + wi * 2, e2, e3);
                sum0 += e0 + e1; sum1 += e2 + e3;
            }
            sum0 += __shfl_xor_sync(0xffffffffu, sum0, 1);
            sum0 += __shfl_xor_sync(0xffffffffu, sum0, 2);
            sum1 += __shfl_xor_sync(0xffffffffu, sum1, 1);
            sum1 += __shfl_xor_sync(0xffffffffu, sum1, 2);
            if (t == 0) {
                atomicAdd(&s_aux[wm + mt * 16 + g], sum0);
                atomicAdd(&s_aux[wm + mt * 16 + g + 8], sum1);
            }
        }
        __syncthreads();
        if (tid < 128)
            atomicAdd(&rs[rs_off + m0 + tid], s_aux[tid]);
    } else if (MODE == 1 || MODE == 3) {
#pragma unroll
        for (int mt = 0; mt < 2; mt++) {
            const float i0 = (MODE == 3) ? s_aux[wm + mt * 16 + g] : 1.0f;
            const float i1 = (MODE == 3) ? s_aux[wm + mt * 16 + g + 8] : 1.0f;
#pragma unroll
            for (int nt = 0; nt < NT; nt++) {
                const int colw = wn + nt * 8 + 2 * t;
                const long long row0 = m0 + wm + mt * 16 + g;
                const float b0 = (MODE == 1) ? s_bias[colw] : 0.0f;
                const float b1 = (MODE == 1) ? s_bias[colw + 1] : 0.0f;
                float v0 = acc[mt][nt][0] * i0 + b0;
                float v1 = acc[mt][nt][1] * i0 + b1;
                float v2 = acc[mt][nt][2] * i1 + b0;
                float v3 = acc[mt][nt][3] * i1 + b1;
                const long long colg = n0 + colw;
                const long long ch = colg >> 5;
                const int wi = (int)(colg & 31);
                pack_store2(Cpk + row0 * ldCpk + ch * 128 + wi * 2, v0, v1);
                pack_store2(Cpk + (row0 + 8) * ldCpk + ch * 128 + wi * 2, v2, v3);
            }
        }
    } else {
#pragma unroll
        for (int mt = 0; mt < 2; mt++) {
#pragma unroll
            for (int nt = 0; nt < NT; nt++) {
                const int colw = wn + nt * 8 + 2 * t;
                const float b0 = s_bias[colw], b1 = s_bias[colw + 1];
                const long long row0 = m0 + wm + mt * 16 + g;
                *(float2*)(Cf + row0 * (long long)ldc + n0 + colw) =
                    make_float2(acc[mt][nt][0] + b0, acc[mt][nt][1] + b1);
                *(float2*)(Cf + (row0 + 8) * (long long)ldc + n0 + colw) =
                    make_float2(acc[mt][nt][2] + b0, acc[mt][nt][3] + b1);
            }
        }
    }
}

// ---------------------------------------------------------------------------
// V transpose: vh fp32 [B,L,H,DK] -> vT packed [(b*H+h)][dk][L/32][128B]
// ---------------------------------------------------------------------------
__global__ void __launch_bounds__(256)
transpose_v_pk(const float* __restrict__ vh, uint8_t* __restrict__ vT)
{
    __shared__ float tsm[32][33];
    const int bh = blockIdx.z;
    const int b = bh >> 4, h = bh & 15;
    const int l0 = blockIdx.x * 32;
    const int d0 = blockIdx.y * 32;
    const int tid = threadIdx.x;
    const int tx = tid & 31;
    const int ty = tid >> 5;

    const float* src = vh + ((long long)b * L_ + l0) * HD_ + h * DK_ + d0;
#pragma unroll
    for (int i = 0; i < 32; i += 8)
        tsm[ty + i][tx] = src[(long long)(ty + i) * HD_ + tx];
    __syncthreads();

    const int lp = tid & 15;
#pragma unroll
    for (int it = 0; it < 2; it++) {
        const int d = (tid >> 4) + 16 * it;
        uint8_t* p = vT + ((long long)bh * 64 + d0 + d) * (L_ / 32 * 128)
                        + (l0 >> 5) * 128 + lp * 4;
        pack_store2(p, tsm[2 * lp][d], tsm[2 * lp + 1][d]);
    }
}

__global__ void zero_rs(float* __restrict__ rs)
{
    rs[blockIdx.x * 256 + threadIdx.x] = 0.0f;
}

// ---------------------------------------------------------------------------
// LayerNorm + residual
// ---------------------------------------------------------------------------
__global__ void __launch_bounds__(256)
ln_residual(const float* __restrict__ x, const float* __restrict__ res,
            const float* __restrict__ gam, const float* __restrict__ bet,
            float* __restrict__ out)
{
    const long long row = blockIdx.x;
    const float4* x4 = (const float4*)(x   + row * D_);
    const float4* r4 = (const float4*)(res + row * D_);
    const int tid = threadIdx.x;

    float4 v = x4[tid];
    float s  = (v.x + v.y) + (v.z + v.w);
    float sq = (v.x * v.x + v.y * v.y) + (v.z * v.z + v.w * v.w);
#pragma unroll
    for (int o = 16; o > 0; o >>= 1) {
        s  += __shfl_xor_sync(0xffffffffu, s,  o);
        sq += __shfl_xor_sync(0xffffffffu, sq, o);
    }
    __shared__ float ss[8], sqs[8];
    if ((tid & 31) == 0) { ss[tid >> 5] = s; sqs[tid >> 5] = sq; }
    __syncthreads();
    s  = (ss[0]  + ss[1])  + (ss[2]  + ss[3])  + (ss[4]  + ss[5])  + (ss[6]  + ss[7]);
    sq = (sqs[0] + sqs[1]) + (sqs[2] + sqs[3]) + (sqs[4] + sqs[5]) + (sqs[6] + sqs[7]);

    const float mean = s * (1.0f / D_);
    float var = sq * (1.0f / D_) - mean * mean;
    var = fmaxf(var, 0.0f);
    const float rstd = rsqrtf(var + LN_EPS_);

    float4 g  = ((const float4*)gam)[tid];
    float4 bt = ((const float4*)bet)[tid];
    float4 r  = r4[tid];
    float4 o;
    o.x = (v.x - mean) * rstd * g.x + bt.x + r.x;
    o.y = (v.y - mean) * rstd * g.y + bt.y + r.y;
    o.z = (v.z - mean) * rstd * g.z + bt.z + r.z;
    o.w = (v.w - mean) * rstd * g.w + bt.w + r.w;
    ((float4*)(out + row * D_))[tid] = o;
}

// ---------------------------------------------------------------------------
// Launch
// ---------------------------------------------------------------------------
extern "C" void kernel_launch(void* const* d_in, const int* in_sizes, int n_in,
                              void* d_out, int out_size)
{
    (void)in_sizes; (void)n_in; (void)out_size;
    const float* q  = (const float*)d_in[0];
    const float* k  = (const float*)d_in[1];
    const float* v  = (const float*)d_in[2];
    const float* wq = (const float*)d_in[3];
    const float* bq = (const float*)d_in[4];
    const float* wk = (const float*)d_in[5];
    const float* bk = (const float*)d_in[6];
    const float* wv = (const float*)d_in[7];
    const float* bv = (const float*)d_in[8];
    const float* wo = (const float*)d_in[9];
    const float* bo = (const float*)d_in[10];
    const float* lg = (const float*)d_in[11];
    const float* lb = (const float*)d_in[12];

    float* out  = (float*)d_out;
    float* attn = out + (long long)B_ * L_ * D_;
    uint8_t* attn_b = (uint8_t*)attn;

    uint8_t *qpk, *kpk, *vpk, *wqpk, *wkpk, *wvpk, *wopk, *qhpk, *khpk, *vTpk, *oapk;
    float *vh, *op, *rs;
    cudaGetSymbolAddress((void**)&qpk,  g_qpk);
    cudaGetSymbolAddress((void**)&kpk,  g_kpk);
    cudaGetSymbolAddress((void**)&vpk,  g_vpk);
    cudaGetSymbolAddress((void**)&wqpk, g_wqpk);
    cudaGetSymbolAddress((void**)&wkpk, g_wkpk);
    cudaGetSymbolAddress((void**)&wvpk, g_wvpk);
    cudaGetSymbolAddress((void**)&wopk, g_wopk);
    cudaGetSymbolAddress((void**)&qhpk, g_qhpk);
    cudaGetSymbolAddress((void**)&khpk, g_khpk);
    cudaGetSymbolAddress((void**)&vTpk, g_vTpk);
    cudaGetSymbolAddress((void**)&oapk, g_oapk);
    cudaGetSymbolAddress((void**)&vh,   g_vh);
    cudaGetSymbolAddress((void**)&op,   g_op);
    cudaGetSymbolAddress((void**)&rs,   g_rs);

    const int SMEM128 = 2 * (16384 + 128 * 128) + 1024;   // 66560
    const int SMEM64  = 2 * (16384 + 64 * 128) + 1024;    // 50176
    cudaFuncSetAttribute((const void*)pk_gemm<128, 0>, cudaFuncAttributeMaxDynamicSharedMemorySize, SMEM128);
    cudaFuncSetAttribute((const void*)pk_gemm<128, 1>, cudaFuncAttributeMaxDynamicSharedMemorySize, SMEM128);
    cudaFuncSetAttribute((const void*)pk_gemm<128, 2>, cudaFuncAttributeMaxDynamicSharedMemorySize, SMEM128);
    cudaFuncSetAttribute((const void*)pk_gemm<64, 3>,  cudaFuncAttributeMaxDynamicSharedMemorySize, SMEM64);

    dim3 blk(256);

    zero_rs<<<NROWS_ATTN / 256, blk>>>(rs);

    // pack inputs + weights (batched)
    pack_split3<<<dim3(MROWS_ * D_ / 4 / 256, 1, 3), blk>>>(q, k, v, qpk, kpk, vpk, D_);
    pack_split3<<<dim3(HD_ * D_ / 4 / 256, 1, 3), blk>>>(wq, wk, wv, wqpk, wkpk, wvpk, D_);
    pack_split1<<<D_ * HD_ / 4 / 256, blk>>>(wo, wopk, HD_);

    const long long ld32 = 32 * 128;   // 4096B row (K=1024)
    const long long ld64 = 64 * 128;   // 8192B row (K=2048)

    // QKV projections (K=1024 -> 32 chunks), 128x128 tiles, 2-pass
    dim3 gproj(HD_ / 128, MROWS_ / 128, 1);
    pk_gemm<128, 1><<<gproj, blk, SMEM128>>>(qpk, wqpk, bq, nullptr, qhpk, nullptr,
        32, ld32, ld32, 0, ld32, 1,
        0, 0, 0, 0, 0, 0, 0, 0, 0, 0, 1.0f);
    pk_gemm<128, 1><<<gproj, blk, SMEM128>>>(kpk, wkpk, bk, nullptr, khpk, nullptr,
        32, ld32, ld32, 0, ld32, 1,
        0, 0, 0, 0, 0, 0, 0, 0, 0, 0, 1.0f);
    pk_gemm<128, 0><<<gproj, blk, SMEM128>>>(vpk, wvpk, bv, vh, nullptr, nullptr,
        32, ld32, ld32, HD_, 0, 1,
        0, 0, 0, 0, 0, 0, 0, 0, 0, 0, 1.0f);

    transpose_v_pk<<<dim3(L_ / 32, DK_ / 32, B_ * H_), blk>>>(vh, vTpk);

    // Scores (K=64 -> 2 chunks), 128x128 tiles, 2-pass
    dim3 gsc(L_ / 128, L_ / 128, B_ * H_);
    pk_gemm<128, 2><<<gsc, blk, SMEM128>>>(qhpk, khpk, nullptr, nullptr, attn_b, rs,
        2, ld32, ld32, 0, ld64, H_,
        (long long)L_ * ld32, 256,
        (long long)L_ * ld32, 256,
        0, 0,
        (long long)L_ * L_ * 4, (long long)B_ * L_ * L_ * 4,
        (long long)L_, (long long)B_ * L_,
        0.125f);

    // PV (K=2048 -> 64 chunks), 128x64 tiles, 2-pass: in-place normalized P + oa packed
    dim3 gpv(1, L_ / 128, B_ * H_);
    pk_gemm<64, 3><<<gpv, blk, SMEM64>>>(attn_b, vTpk, nullptr, attn, oapk, rs,
        64, ld64, ld64, L_, ld32, H_,
        (long long)L_ * L_ * 4, (long long)B_ * L_ * L_ * 4,
        (long long)DK_ * ld64 * H_, (long long)DK_ * ld64,
        (long long)L_ * L_, (long long)B_ * L_ * L_,
        (long long)L_ * ld32, 256,
        (long long)L_, (long long)B_ * L_,
        1.0f);

    // Output projection (K=1024 -> 32 chunks), 128x128 tiles, 2-pass
    dim3 gop(D_ / 128, MROWS_ / 128, 1);
    pk_gemm<128, 0><<<gop, blk, SMEM128>>>(oapk, wopk, bo, op, nullptr, nullptr,
        32, ld32, ld32, D_, 0, 1,
        0, 0, 0, 0, 0, 0, 0, 0, 0, 0, 1.0f);

    // LayerNorm + residual
    ln_residual<<<MROWS_, blk>>>(op, q, lg, lb, out);
}

// round 13
// speedup vs baseline: 1.3612x; 1.1170x over previous
#include <cuda_runtime.h>
#include <cuda_fp16.h>
#include <stdint.h>

#define B_   4
#define L_   2048
#define D_   1024
#define H_   16
#define DK_  64
#define HD_  1024
#define MROWS_ 8192
#define LN_EPS_ 1e-5f
#define NROWS_ATTN (B_ * H_ * L_)

// ---------------------------------------------------------------------------
// Scratch (device globals). Packed split-fp16: [M][K/32][32 hi | 32 lo] 128B.
// Plain fp16: [M][K/64][64 fp16] 128B chunks.
// ---------------------------------------------------------------------------
__device__ __align__(256) uint8_t g_qpk [(long long)MROWS_ * D_ * 4];
__device__ __align__(256) uint8_t g_kpk [(long long)MROWS_ * D_ * 4];
__device__ __align__(256) uint8_t g_vpk [(long long)MROWS_ * D_ * 4];
__device__ __align__(256) uint8_t g_wqpk[(long long)HD_ * D_ * 4];
__device__ __align__(256) uint8_t g_wkpk[(long long)HD_ * D_ * 4];
__device__ __align__(256) uint8_t g_wvpk[(long long)HD_ * D_ * 4];
__device__ __align__(256) uint8_t g_wopk[(long long)D_ * HD_ * 4];
__device__ __align__(256) uint8_t g_qhpk[(long long)MROWS_ * HD_ * 4];
__device__ __align__(256) uint8_t g_khpk[(long long)MROWS_ * HD_ * 4];
__device__ __align__(256) uint8_t g_vT  [(long long)B_ * H_ * DK_ * L_ * 2];   // plain fp16
__device__ __align__(256) uint8_t g_oapk[(long long)MROWS_ * HD_ * 4];
__device__ __align__(256) uint8_t g_expP[(long long)B_ * H_ * L_ * L_ * 2];    // plain fp16
__device__ float g_vh[MROWS_ * HD_];
__device__ float g_op[MROWS_ * HD_];
__device__ float g_rs[NROWS_ATTN];

// ---------------------------------------------------------------------------
// helpers
// ---------------------------------------------------------------------------
__device__ __forceinline__ uint32_t smem_u32(const void* p) {
    uint32_t a;
    asm("{ .reg .u64 t; cvta.to.shared.u64 t, %1; cvt.u32.u64 %0, t; }" : "=r"(a) : "l"(p));
    return a;
}
__device__ __forceinline__ uint32_t sw128(uint32_t off) {
    return off ^ ((off >> 3) & 0x70);
}
__device__ __forceinline__ void cpa16(uint32_t dst, const void* src) {
    asm volatile("cp.async.cg.shared.global [%0], [%1], 16;" :: "r"(dst), "l"(src));
}
#define CP_COMMIT() asm volatile("cp.async.commit_group;" ::: "memory")
#define CP_WAIT0()  asm volatile("cp.async.wait_group 0;" ::: "memory")
#define CP_WAIT1()  asm volatile("cp.async.wait_group 1;" ::: "memory")
#define LDSM_X4(r0, r1, r2, r3, addr)                                      \
    asm volatile("ldmatrix.sync.aligned.m8n8.x4.shared.b16 "               \
                 "{%0,%1,%2,%3}, [%4];"                                    \
                 : "=r"(r0), "=r"(r1), "=r"(r2), "=r"(r3) : "r"(addr))

__device__ __forceinline__ void mma16816(float* d, const uint32_t* a, const uint32_t* b) {
    asm volatile(
        "mma.sync.aligned.m16n8k16.row.col.f32.f16.f16.f32 "
        "{%0,%1,%2,%3}, {%4,%5,%6,%7}, {%8,%9}, {%0,%1,%2,%3};"
        : "+f"(d[0]), "+f"(d[1]), "+f"(d[2]), "+f"(d[3])
        : "r"(a[0]), "r"(a[1]), "r"(a[2]), "r"(a[3]), "r"(b[0]), "r"(b[1]));
}

__device__ __forceinline__ void pack_store2(uint8_t* p, float v0, float v1) {
    __half2 h = __float22half2_rn(make_float2(v0, v1));
    float2 f = __half22float2(h);
    __half2 l = __float22half2_rn(make_float2(v0 - f.x, v1 - f.y));
    *(uint32_t*)p = *(uint32_t*)&h;
    *(uint32_t*)(p + 64) = *(uint32_t*)&l;
}
__device__ __forceinline__ void pack_store4(uint8_t* p, float4 v) {
    __half2 h0 = __float22half2_rn(make_float2(v.x, v.y));
    __half2 h1 = __float22half2_rn(make_float2(v.z, v.w));
    float2 f0 = __half22float2(h0), f1 = __half22float2(h1);
    __half2 l0 = __float22half2_rn(make_float2(v.x - f0.x, v.y - f0.y));
    __half2 l1 = __float22half2_rn(make_float2(v.z - f1.x, v.w - f1.y));
    uint2 hu, lu;
    hu.x = *(uint32_t*)&h0; hu.y = *(uint32_t*)&h1;
    lu.x = *(uint32_t*)&l0; lu.y = *(uint32_t*)&l1;
    *(uint2*)p = hu;
    *(uint2*)(p + 64) = lu;
}

// ---------------------------------------------------------------------------
// pack fp32 [M,K] -> packed split fp16 ; batched over 3 tensors via blockIdx.z
// ---------------------------------------------------------------------------
__global__ void __launch_bounds__(256)
pack_split3(const float* __restrict__ s0, const float* __restrict__ s1,
            const float* __restrict__ s2,
            uint8_t* __restrict__ d0, uint8_t* __restrict__ d1,
            uint8_t* __restrict__ d2, int K)
{
    const float* src = (blockIdx.z == 0) ? s0 : (blockIdx.z == 1) ? s1 : s2;
    uint8_t* dst = (blockIdx.z == 0) ? d0 : (blockIdx.z == 1) ? d1 : d2;
    const long long idx = (long long)blockIdx.x * 256 + threadIdx.x;
    const int perRow = K >> 2;
    const long long m = idx / perRow;
    const int j = (int)(idx - m * perRow);
    float4 v = *(const float4*)(src + m * K + j * 4);
    const int e0 = j * 4;
    uint8_t* p = dst + (m * (K >> 5) + (e0 >> 5)) * 128 + (e0 & 31) * 2;
    pack_store4(p, v);
}
__global__ void __launch_bounds__(256)
pack_split1(const float* __restrict__ src, uint8_t* __restrict__ dst, int K)
{
    const long long idx = (long long)blockIdx.x * 256 + threadIdx.x;
    const int perRow = K >> 2;
    const long long m = idx / perRow;
    const int j = (int)(idx - m * perRow);
    float4 v = *(const float4*)(src + m * K + j * 4);
    const int e0 = j * 4;
    uint8_t* p = dst + (m * (K >> 5) + (e0 >> 5)) * 128 + (e0 & 31) * 2;
    pack_store4(p, v);
}

// ---------------------------------------------------------------------------
// Packed split-fp16 GEMM. CTA tile 128 x TN, 32-K chunks, 8 warps as 4x2,
// 2 CTAs/SM. 2-pass (hh + lh): B-lo neither loaded nor read.
// MODE 0: C fp32 + bias.  MODE 1: C packed-split + bias.
// MODE 2: exp(alpha*acc)*2^-4 -> PLAIN fp16 + rowsum atomics.
// ---------------------------------------------------------------------------
template<int TN, int MODE>
__global__ void __launch_bounds__(256, 2)
pk_gemm(const uint8_t* Apk, const uint8_t* __restrict__ Bpk,
        const float* __restrict__ bias,
        float* Cf, uint8_t* Cpk, float* rs,
        int nchunks, long long ldA, long long ldB, int ldc, long long ldCpk,
        int zdiv,
        long long sAo, long long sAi, long long sBo, long long sBi,
        long long sCfO, long long sCfI, long long sCpO, long long sCpI,
        long long rsO, long long rsI, float alpha)
{
    constexpr int NT = TN / 16;
    constexpr int NBL = TN / 64;
    constexpr int STAGE = 16384 + TN * 128;

    extern __shared__ uint8_t dyn_raw[];
    __shared__ float s_bias[TN];
    __shared__ float s_aux[128];

    const int tid = threadIdx.x, wid = tid >> 5, lane = tid & 31;
    const int z = blockIdx.z, zo = z / zdiv, zi = z - zo * zdiv;
    Apk += zo * sAo + zi * sAi;
    Bpk += zo * sBo + zi * sBi;
    if (MODE == 0) Cf += zo * sCfO + zi * sCfI;
    if (MODE != 0) Cpk += zo * sCpO + zi * sCpI;
    const long long rs_off = zo * rsO + zi * rsI;

    const long long m0 = (long long)blockIdx.y * 128;
    const long long n0 = (long long)blockIdx.x * TN;

    uint32_t raw = smem_u32(dyn_raw);
    uint32_t base = (raw + 1023u) & ~1023u;
    const uint32_t aSu[2] = { base, base + STAGE };
    const uint32_t bSu[2] = { base + 16384, base + STAGE + 16384 };

    if (MODE == 0 || MODE == 1) {
        for (int i = tid; i < TN; i += 256) s_bias[i] = bias ? bias[n0 + i] : 0.0f;
    }
    if (MODE == 2) { if (tid < 128) s_aux[tid] = 0.0f; }

    float acc[2][NT][4];
#pragma unroll
    for (int i = 0; i < 2; i++)
#pragma unroll
        for (int j = 0; j < NT; j++)
#pragma unroll
            for (int e = 0; e < 4; e++) acc[i][j][e] = 0.0f;

    const uint32_t a_row = (uint32_t)((lane & 7) + (lane & 8));
    const uint32_t a_kof = (uint32_t)(((lane >> 4) & 1) * 16);
    const uint32_t b_row = (uint32_t)((lane & 7) + ((lane >> 4) & 1) * 8);
    const uint32_t b_kof = (uint32_t)(((lane >> 3) & 1) * 16);
    const int wm = (wid & 3) * 32;
    const int wn = (wid >> 2) * (TN / 2);

    auto prefetch = [&](int s, int c) {
        const uint8_t* Ab = Apk + (long long)c * 128;
#pragma unroll
        for (int i = 0; i < 4; i++) {
            const int idx = i * 256 + tid, row = idx >> 3, g = idx & 7;
            cpa16(aSu[s] + sw128((uint32_t)(row * 128 + g * 16)),
                  Ab + (m0 + row) * ldA + g * 16);
        }
        const uint8_t* Bb = Bpk + (long long)c * 128;
#pragma unroll
        for (int i = 0; i < NBL; i++) {
            const int idx = i * 256 + tid, row = idx >> 2, g = idx & 3;
            cpa16(bSu[s] + sw128((uint32_t)(row * 128 + g * 16)),
                  Bb + (n0 + row) * ldB + g * 16);
        }
        CP_COMMIT();
    };

    prefetch(0, 0);
    int cur = 0;
    for (int c = 0; c < nchunks; c++) {
        if (c + 1 < nchunks) {
            prefetch(cur ^ 1, c + 1);
            CP_WAIT1();
        } else {
            CP_WAIT0();
        }
        __syncthreads();

        const uint32_t aS = aSu[cur], bS = bSu[cur];
#pragma unroll
        for (int ks = 0; ks < 2; ks++) {
            uint32_t ah[2][4], al[2][4], bf[NT][2];
#pragma unroll
            for (int mt = 0; mt < 2; mt++) {
                uint32_t off = (uint32_t)(wm + mt * 16 + a_row) * 128 + ks * 32 + a_kof;
                LDSM_X4(ah[mt][0], ah[mt][1], ah[mt][2], ah[mt][3], aS + sw128(off));
            }
#pragma unroll
            for (int p = 0; p < NT / 2; p++) {
                uint32_t r0, r1, r2, r3;
                uint32_t off = (uint32_t)(wn + p * 16 + b_row) * 128 + ks * 32 + b_kof;
                LDSM_X4(r0, r1, r2, r3, bS + sw128(off));
                bf[2 * p][0] = r0; bf[2 * p][1] = r1;
                bf[2 * p + 1][0] = r2; bf[2 * p + 1][1] = r3;
            }
#pragma unroll
            for (int mt = 0; mt < 2; mt++)
#pragma unroll
                for (int nt = 0; nt < NT; nt++)
                    mma16816(acc[mt][nt], ah[mt], bf[nt]);
#pragma unroll
            for (int mt = 0; mt < 2; mt++) {
                uint32_t off = (uint32_t)(wm + mt * 16 + a_row) * 128 + 64 + ks * 32 + a_kof;
                LDSM_X4(al[mt][0], al[mt][1], al[mt][2], al[mt][3], aS + sw128(off));
            }
#pragma unroll
            for (int mt = 0; mt < 2; mt++)
#pragma unroll
                for (int nt = 0; nt < NT; nt++)
                    mma16816(acc[mt][nt], al[mt], bf[nt]);
        }
        __syncthreads();
        cur ^= 1;
    }

    // ---- epilogue ----
    const int g = lane >> 2, t = lane & 3;
    if (MODE == 2) {
        const float esc = 0.0625f;   // 2^-4 range guard; cancels in normalization
#pragma unroll
        for (int mt = 0; mt < 2; mt++) {
            float sum0 = 0.0f, sum1 = 0.0f;
#pragma unroll
            for (int nt = 0; nt < NT; nt++) {
                const int colw = wn + nt * 8 + 2 * t;
                const long long row0 = m0 + wm + mt * 16 + g;
                float e0 = __expf(acc[mt][nt][0] * alpha) * esc;
                float e1 = __expf(acc[mt][nt][1] * alpha) * esc;
                float e2 = __expf(acc[mt][nt][2] * alpha) * esc;
                float e3 = __expf(acc[mt][nt][3] * alpha) * esc;
                const long long colg = n0 + colw;
                const long long ch = colg >> 6;
                const int wi = (int)(colg & 63);
                __half2 h01 = __float22half2_rn(make_float2(e0, e1));
                __half2 h23 = __float22half2_rn(make_float2(e2, e3));
                *(uint32_t*)(Cpk + row0 * ldCpk + ch * 128 + wi * 2) = *(uint32_t*)&h01;
                *(uint32_t*)(Cpk + (row0 + 8) * ldCpk + ch * 128 + wi * 2) = *(uint32_t*)&h23;
                sum0 += e0 + e1; sum1 += e2 + e3;
            }
            sum0 += __shfl_xor_sync(0xffffffffu, sum0, 1);
            sum0 += __shfl_xor_sync(0xffffffffu, sum0, 2);
            sum1 += __shfl_xor_sync(0xffffffffu, sum1, 1);
            sum1 += __shfl_xor_sync(0xffffffffu, sum1, 2);
            if (t == 0) {
                atomicAdd(&s_aux[wm + mt * 16 + g], sum0);
                atomicAdd(&s_aux[wm + mt * 16 + g + 8], sum1);
            }
        }
        __syncthreads();
        if (tid < 128)
            atomicAdd(&rs[rs_off + m0 + tid], s_aux[tid]);
    } else if (MODE == 1) {
#pragma unroll
        for (int mt = 0; mt < 2; mt++) {
#pragma unroll
            for (int nt = 0; nt < NT; nt++) {
                const int colw = wn + nt * 8 + 2 * t;
                const long long row0 = m0 + wm + mt * 16 + g;
                const float b0 = s_bias[colw], b1 = s_bias[colw + 1];
                const long long colg = n0 + colw;
                const long long ch = colg >> 5;
                const int wi = (int)(colg & 31);
                pack_store2(Cpk + row0 * ldCpk + ch * 128 + wi * 2,
                            acc[mt][nt][0] + b0, acc[mt][nt][1] + b1);
                pack_store2(Cpk + (row0 + 8) * ldCpk + ch * 128 + wi * 2,
                            acc[mt][nt][2] + b0, acc[mt][nt][3] + b1);
            }
        }
    } else {
#pragma unroll
        for (int mt = 0; mt < 2; mt++) {
#pragma unroll
            for (int nt = 0; nt < NT; nt++) {
                const int colw = wn + nt * 8 + 2 * t;
                const float b0 = s_bias[colw], b1 = s_bias[colw + 1];
                const long long row0 = m0 + wm + mt * 16 + g;
                *(float2*)(Cf + row0 * (long long)ldc + n0 + colw) =
                    make_float2(acc[mt][nt][0] + b0, acc[mt][nt][1] + b1);
                *(float2*)(Cf + (row0 + 8) * (long long)ldc + n0 + colw) =
                    make_float2(acc[mt][nt][2] + b0, acc[mt][nt][3] + b1);
            }
        }
    }
}

// ---------------------------------------------------------------------------
// PV plain-fp16 GEMM: O[128 x 64] += P(fp16) @ V(fp16), K-chunks of 64.
// Also writes normalized fp32 P (the required attn output) and packed-split O.
// Grid: (L/128 qb, B*H z). 8 warps 4x2 (warp tile 32x32), 2 CTAs/SM.
// ---------------------------------------------------------------------------
__global__ void __launch_bounds__(256, 2)
pv_plain(const uint8_t* __restrict__ expP, const uint8_t* __restrict__ vT,
         float* __restrict__ attn, uint8_t* __restrict__ oapk,
         const float* __restrict__ rs)
{
    extern __shared__ uint8_t dyn_raw[];
    __shared__ float s_aux[128];

    const int tid = threadIdx.x, wid = tid >> 5, lane = tid & 31;
    const int qb = blockIdx.x;
    const int z = blockIdx.y;
    const int b = z >> 4, h = z & 15;
    const long long m0 = (long long)qb * 128;

    const uint8_t* P = expP + ((long long)(h * B_ + b) * L_ + m0) * 4096;  // 4096B/row
    const uint8_t* Vt = vT + (long long)z * 64 * 4096;                      // 64 d-rows
    float* Pf = attn + ((long long)(h * B_ + b) * L_ + m0) * L_;
    uint8_t* Oa = oapk + ((long long)b * L_ + m0) * 4096 + h * 256;
    const float* rsb = rs + (long long)(h * B_ + b) * L_ + m0;

    uint32_t raw = smem_u32(dyn_raw);
    uint32_t base = (raw + 1023u) & ~1023u;
    uint8_t* dsm = dyn_raw + (base - raw);
    const int STAGE = 16384 + 8192;
    uint8_t* smA[2] = { dsm, dsm + STAGE };
    const uint32_t aSu[2] = { base, base + STAGE };
    const uint32_t bSu[2] = { base + 16384, base + STAGE + 16384 };

    if (tid < 128) s_aux[tid] = 1.0f / rsb[tid];
    __syncthreads();

    float acc[2][4][4];
#pragma unroll
    for (int i = 0; i < 2; i++)
#pragma unroll
        for (int j = 0; j < 4; j++)
#pragma unroll
            for (int e = 0; e < 4; e++) acc[i][j][e] = 0.0f;

    const uint32_t a_row = (uint32_t)((lane & 7) + (lane & 8));
    const uint32_t a_kof = (uint32_t)(((lane >> 4) & 1) * 16);
    const uint32_t b_row = (uint32_t)((lane & 7) + ((lane >> 4) & 1) * 8);
    const uint32_t b_kof = (uint32_t)(((lane >> 3) & 1) * 16);
    const int wm = (wid & 3) * 32;
    const int wn = (wid >> 2) * 32;

    auto prefetch = [&](int s, int c) {
#pragma unroll
        for (int i = 0; i < 4; i++) {   // P: 128 rows x 128B chunk
            const int idx = i * 256 + tid, row = idx >> 3, g = idx & 7;
            cpa16(aSu[s] + sw128((uint32_t)(row * 128 + g * 16)),
                  P + (long long)row * 4096 + c * 128 + g * 16);
        }
#pragma unroll
        for (int i = 0; i < 2; i++) {   // V^T: 64 d-rows x 128B chunk
            const int idx = i * 256 + tid, row = idx >> 3, g = idx & 7;
            cpa16(bSu[s] + sw128((uint32_t)(row * 128 + g * 16)),
                  Vt + (long long)row * 4096 + c * 128 + g * 16);
        }
        CP_COMMIT();
    };

    prefetch(0, 0);
    int cur = 0;
    for (int c = 0; c < 32; c++) {      // 32 chunks x K=64
        if (c + 1 < 32) { prefetch(cur ^ 1, c + 1); CP_WAIT1(); }
        else            { CP_WAIT0(); }
        __syncthreads();

        // normalized fp32 P write (required output), from staged fp16
        {
            const int r = tid >> 1, hh = tid & 1;
            const uint8_t* sa = smA[cur];
            const float inv = s_aux[r];
            float* dst = Pf + (long long)r * L_ + c * 64 + hh * 32;
#pragma unroll
            for (int j = 0; j < 4; j++) {
                uint4 u = *(const uint4*)(sa + sw128((uint32_t)(r * 128 + hh * 64 + j * 16)));
                const uint32_t w[4] = { u.x, u.y, u.z, u.w };
                float o[8];
#pragma unroll
                for (int jj = 0; jj < 4; jj++) {
                    __half2 hb = *(const __half2*)&w[jj];
                    float2 f = __half22float2(hb);
                    o[2 * jj] = f.x * inv;
                    o[2 * jj + 1] = f.y * inv;
                }
                *(float4*)(dst + j * 8)     = make_float4(o[0], o[1], o[2], o[3]);
                *(float4*)(dst + j * 8 + 4) = make_float4(o[4], o[5], o[6], o[7]);
            }
        }

        const uint32_t aS = aSu[cur], bS = bSu[cur];
#pragma unroll
        for (int ks = 0; ks < 4; ks++) {
            uint32_t ah[2][4], bf[4][2];
#pragma unroll
            for (int mt = 0; mt < 2; mt++) {
                uint32_t off = (uint32_t)(wm + mt * 16 + a_row) * 128 + ks * 32 + a_kof;
                LDSM_X4(ah[mt][0], ah[mt][1], ah[mt][2], ah[mt][3], aS + sw128(off));
            }
#pragma unroll
            for (int p = 0; p < 2; p++) {
                uint32_t r0, r1, r2, r3;
                uint32_t off = (uint32_t)(wn + p * 16 + b_row) * 128 + ks * 32 + b_kof;
                LDSM_X4(r0, r1, r2, r3, bS + sw128(off));
                bf[2 * p][0] = r0; bf[2 * p][1] = r1;
                bf[2 * p + 1][0] = r2; bf[2 * p + 1][1] = r3;
            }
#pragma unroll
            for (int mt = 0; mt < 2; mt++)
#pragma unroll
                for (int nt = 0; nt < 4; nt++)
                    mma16816(acc[mt][nt], ah[mt], bf[nt]);
        }
        __syncthreads();
        cur ^= 1;
    }

    // epilogue: O * 1/rowsum -> packed split fp16
    const int g = lane >> 2, t = lane & 3;
#pragma unroll
    for (int mt = 0; mt < 2; mt++) {
        const float i0 = s_aux[wm + mt * 16 + g];
        const float i1 = s_aux[wm + mt * 16 + g + 8];
#pragma unroll
        for (int nt = 0; nt < 4; nt++) {
            const int colw = wn + nt * 8 + 2 * t;
            const int row0 = wm + mt * 16 + g;
            const int ch = colw >> 5, wi = colw & 31;
            pack_store2(Oa + (long long)row0 * 4096 + ch * 128 + wi * 2,
                        acc[mt][nt][0] * i0, acc[mt][nt][1] * i0);
            pack_store2(Oa + (long long)(row0 + 8) * 4096 + ch * 128 + wi * 2,
                        acc[mt][nt][2] * i1, acc[mt][nt][3] * i1);
        }
    }
}

// ---------------------------------------------------------------------------
// V transpose: vh fp32 [B,L,H,DK] -> vT plain fp16 [(b*H+h)][dk][L/64][128B]
// ---------------------------------------------------------------------------
__global__ void __launch_bounds__(256)
transpose_v_pk(const float* __restrict__ vh, uint8_t* __restrict__ vT)
{
    __shared__ float tsm[32][33];
    const int bh = blockIdx.z;
    const int b = bh >> 4, h = bh & 15;
    const int l0 = blockIdx.x * 32;
    const int d0 = blockIdx.y * 32;
    const int tid = threadIdx.x;
    const int tx = tid & 31;
    const int ty = tid >> 5;

    const float* src = vh + ((long long)b * L_ + l0) * HD_ + h * DK_ + d0;
#pragma unroll
    for (int i = 0; i < 32; i += 8)
        tsm[ty + i][tx] = src[(long long)(ty + i) * HD_ + tx];
    __syncthreads();

    const int lp = tid & 15;
#pragma unroll
    for (int it = 0; it < 2; it++) {
        const int d = (tid >> 4) + 16 * it;
        const int lg = l0 + 2 * lp;
        uint8_t* p = vT + ((long long)bh * 64 + d0 + d) * 4096
                        + (lg >> 6) * 128 + (lg & 63) * 2;
        __half2 hv = __float22half2_rn(make_float2(tsm[2 * lp][d], tsm[2 * lp + 1][d]));
        *(uint32_t*)p = *(uint32_t*)&hv;
    }
}

__global__ void zero_rs(float* __restrict__ rs)
{
    rs[blockIdx.x * 256 + threadIdx.x] = 0.0f;
}

// ---------------------------------------------------------------------------
// LayerNorm + residual
// ---------------------------------------------------------------------------
__global__ void __launch_bounds__(256)
ln_residual(const float* __restrict__ x, const float* __restrict__ res,
            const float* __restrict__ gam, const float* __restrict__ bet,
            float* __restrict__ out)
{
    const long long row = blockIdx.x;
    const float4* x4 = (const float4*)(x   + row * D_);
    const float4* r4 = (const float4*)(res + row * D_);
    const int tid = threadIdx.x;

    float4 v = x4[tid];
    float s  = (v.x + v.y) + (v.z + v.w);
    float sq = (v.x * v.x + v.y * v.y) + (v.z * v.z + v.w * v.w);
#pragma unroll
    for (int o = 16; o > 0; o >>= 1) {
        s  += __shfl_xor_sync(0xffffffffu, s,  o);
        sq += __shfl_xor_sync(0xffffffffu, sq, o);
    }
    __shared__ float ss[8], sqs[8];
    if ((tid & 31) == 0) { ss[tid >> 5] = s; sqs[tid >> 5] = sq; }
    __syncthreads();
    s  = (ss[0]  + ss[1])  + (ss[2]  + ss[3])  + (ss[4]  + ss[5])  + (ss[6]  + ss[7]);
    sq = (sqs[0] + sqs[1]) + (sqs[2] + sqs[3]) + (sqs[4] + sqs[5]) + (sqs[6] + sqs[7]);

    const float mean = s * (1.0f / D_);
    float var = sq * (1.0f / D_) - mean * mean;
    var = fmaxf(var, 0.0f);
    const float rstd = rsqrtf(var + LN_EPS_);

    float4 g  = ((const float4*)gam)[tid];
    float4 bt = ((const float4*)bet)[tid];
    float4 r  = r4[tid];
    float4 o;
    o.x = (v.x - mean) * rstd * g.x + bt.x + r.x;
    o.y = (v.y - mean) * rstd * g.y + bt.y + r.y;
    o.z = (v.z - mean) * rstd * g.z + bt.z + r.z;
    o.w = (v.w - mean) * rstd * g.w + bt.w + r.w;
    ((float4*)(out + row * D_))[tid] = o;
}

// ---------------------------------------------------------------------------
// Launch
// ---------------------------------------------------------------------------
extern "C" void kernel_launch(void* const* d_in, const int* in_sizes, int n_in,
                              void* d_out, int out_size)
{
    (void)in_sizes; (void)n_in; (void)out_size;
    const float* q  = (const float*)d_in[0];
    const float* k  = (const float*)d_in[1];
    const float* v  = (const float*)d_in[2];
    const float* wq = (const float*)d_in[3];
    const float* bq = (const float*)d_in[4];
    const float* wk = (const float*)d_in[5];
    const float* bk = (const float*)d_in[6];
    const float* wv = (const float*)d_in[7];
    const float* bv = (const float*)d_in[8];
    const float* wo = (const float*)d_in[9];
    const float* bo = (const float*)d_in[10];
    const float* lg = (const float*)d_in[11];
    const float* lb = (const float*)d_in[12];

    float* out  = (float*)d_out;
    float* attn = out + (long long)B_ * L_ * D_;

    uint8_t *qpk, *kpk, *vpk, *wqpk, *wkpk, *wvpk, *wopk, *qhpk, *khpk, *vT, *oapk, *expP;
    float *vh, *op, *rs;
    cudaGetSymbolAddress((void**)&qpk,  g_qpk);
    cudaGetSymbolAddress((void**)&kpk,  g_kpk);
    cudaGetSymbolAddress((void**)&vpk,  g_vpk);
    cudaGetSymbolAddress((void**)&wqpk, g_wqpk);
    cudaGetSymbolAddress((void**)&wkpk, g_wkpk);
    cudaGetSymbolAddress((void**)&wvpk, g_wvpk);
    cudaGetSymbolAddress((void**)&wopk, g_wopk);
    cudaGetSymbolAddress((void**)&qhpk, g_qhpk);
    cudaGetSymbolAddress((void**)&khpk, g_khpk);
    cudaGetSymbolAddress((void**)&vT,   g_vT);
    cudaGetSymbolAddress((void**)&oapk, g_oapk);
    cudaGetSymbolAddress((void**)&expP, g_expP);
    cudaGetSymbolAddress((void**)&vh,   g_vh);
    cudaGetSymbolAddress((void**)&op,   g_op);
    cudaGetSymbolAddress((void**)&rs,   g_rs);

    const int SMEM128 = 2 * (16384 + 128 * 128) + 1024;   // 66560
    const int SMEMPV  = 2 * (16384 + 8192) + 1024;        // 50176
    cudaFuncSetAttribute((const void*)pk_gemm<128, 0>, cudaFuncAttributeMaxDynamicSharedMemorySize, SMEM128);
    cudaFuncSetAttribute((const void*)pk_gemm<128, 1>, cudaFuncAttributeMaxDynamicSharedMemorySize, SMEM128);
    cudaFuncSetAttribute((const void*)pk_gemm<128, 2>, cudaFuncAttributeMaxDynamicSharedMemorySize, SMEM128);
    cudaFuncSetAttribute((const void*)pv_plain,        cudaFuncAttributeMaxDynamicSharedMemorySize, SMEMPV);

    dim3 blk(256);

    zero_rs<<<NROWS_ATTN / 256, blk>>>(rs);

    // pack inputs + weights (batched)
    pack_split3<<<dim3(MROWS_ * D_ / 4 / 256, 1, 3), blk>>>(q, k, v, qpk, kpk, vpk, D_);
    pack_split3<<<dim3(HD_ * D_ / 4 / 256, 1, 3), blk>>>(wq, wk, wv, wqpk, wkpk, wvpk, D_);
    pack_split1<<<D_ * HD_ / 4 / 256, blk>>>(wo, wopk, HD_);

    const long long ld32 = 32 * 128;   // 4096B row (K=1024 packed split)

    // QKV projections (K=1024 -> 32 chunks), 128x128 tiles, 2-pass
    dim3 gproj(HD_ / 128, MROWS_ / 128, 1);
    pk_gemm<128, 1><<<gproj, blk, SMEM128>>>(qpk, wqpk, bq, nullptr, qhpk, nullptr,
        32, ld32, ld32, 0, ld32, 1,
        0, 0, 0, 0, 0, 0, 0, 0, 0, 0, 1.0f);
    pk_gemm<128, 1><<<gproj, blk, SMEM128>>>(kpk, wkpk, bk, nullptr, khpk, nullptr,
        32, ld32, ld32, 0, ld32, 1,
        0, 0, 0, 0, 0, 0, 0, 0, 0, 0, 1.0f);
    pk_gemm<128, 0><<<gproj, blk, SMEM128>>>(vpk, wvpk, bv, vh, nullptr, nullptr,
        32, ld32, ld32, HD_, 0, 1,
        0, 0, 0, 0, 0, 0, 0, 0, 0, 0, 1.0f);

    transpose_v_pk<<<dim3(L_ / 32, DK_ / 32, B_ * H_), blk>>>(vh, vT);

    // Scores (K=64 -> 2 chunks), 2-pass, plain fp16 expP out + rowsums
    dim3 gsc(L_ / 128, L_ / 128, B_ * H_);
    pk_gemm<128, 2><<<gsc, blk, SMEM128>>>(qhpk, khpk, nullptr, nullptr, expP, rs,
        2, ld32, ld32, 0, (long long)L_ * 2, H_,
        (long long)L_ * ld32, 256,
        (long long)L_ * ld32, 256,
        0, 0,
        (long long)L_ * L_ * 2, (long long)B_ * L_ * L_ * 2,
        (long long)L_, (long long)B_ * L_,
        0.125f);

    // PV single-pass plain fp16; writes fp32 attn + packed oa
    pv_plain<<<dim3(L_ / 128, B_ * H_, 1), blk, SMEMPV>>>(expP, vT, attn, oapk, rs);

    // Output projection (K=1024 -> 32 chunks), 2-pass
    dim3 gop(D_ / 128, MROWS_ / 128, 1);
    pk_gemm<128, 0><<<gop, blk, SMEM128>>>(oapk, wopk, bo, op, nullptr, nullptr,
        32, ld32, ld32, D_, 0, 1,
        0, 0, 0, 0, 0, 0, 0, 0, 0, 0, 1.0f);

    // LayerNorm + residual
    ln_residual<<<MROWS_, blk>>>(op, q, lg, lb, out);
}

// round 14
// speedup vs baseline: 1.4497x; 1.0650x over previous
#include <cuda_runtime.h>
#include <cuda_fp16.h>
#include <stdint.h>

#define B_   4
#define L_   2048
#define D_   1024
#define H_   16
#define DK_  64
#define HD_  1024
#define MROWS_ 8192
#define LN_EPS_ 1e-5f
#define NROWS_ATTN (B_ * H_ * L_)

// ---------------------------------------------------------------------------
// Scratch. Packed split-fp16: [M][K/32][32 hi | 32 lo] 128B chunks.
// Plain fp16: [M][K/64][64 fp16] 128B chunks.
// ---------------------------------------------------------------------------
__device__ __align__(256) uint8_t g_qpk [(long long)MROWS_ * D_ * 4];
__device__ __align__(256) uint8_t g_kpk [(long long)MROWS_ * D_ * 4];
__device__ __align__(256) uint8_t g_vpk [(long long)MROWS_ * D_ * 4];
__device__ __align__(256) uint8_t g_wqpk[(long long)HD_ * D_ * 4];
__device__ __align__(256) uint8_t g_wkpk[(long long)HD_ * D_ * 4];
__device__ __align__(256) uint8_t g_wvpk[(long long)HD_ * D_ * 4];
__device__ __align__(256) uint8_t g_wopl[(long long)D_ * HD_ * 2];          // plain fp16
__device__ __align__(256) uint8_t g_qhpk[(long long)MROWS_ * HD_ * 4];
__device__ __align__(256) uint8_t g_khpk[(long long)MROWS_ * HD_ * 4];
__device__ __align__(256) uint8_t g_vT  [(long long)B_ * H_ * DK_ * L_ * 2]; // plain fp16
__device__ __align__(256) uint8_t g_oapl[(long long)MROWS_ * HD_ * 2];       // plain fp16
__device__ __align__(256) uint8_t g_expP[(long long)B_ * H_ * L_ * L_ * 2];  // plain fp16
__device__ float g_vh[MROWS_ * HD_];
__device__ float g_op[MROWS_ * HD_];
__device__ float g_rs[NROWS_ATTN];

// ---------------------------------------------------------------------------
// helpers
// ---------------------------------------------------------------------------
__device__ __forceinline__ uint32_t smem_u32(const void* p) {
    uint32_t a;
    asm("{ .reg .u64 t; cvta.to.shared.u64 t, %1; cvt.u32.u64 %0, t; }" : "=r"(a) : "l"(p));
    return a;
}
__device__ __forceinline__ uint32_t sw128(uint32_t off) {
    return off ^ ((off >> 3) & 0x70);
}
__device__ __forceinline__ void cpa16(uint32_t dst, const void* src) {
    asm volatile("cp.async.cg.shared.global [%0], [%1], 16;" :: "r"(dst), "l"(src));
}
#define CP_COMMIT() asm volatile("cp.async.commit_group;" ::: "memory")
#define CP_WAIT0()  asm volatile("cp.async.wait_group 0;" ::: "memory")
#define CP_WAIT1()  asm volatile("cp.async.wait_group 1;" ::: "memory")
#define LDSM_X4(r0, r1, r2, r3, addr)                                      \
    asm volatile("ldmatrix.sync.aligned.m8n8.x4.shared.b16 "               \
                 "{%0,%1,%2,%3}, [%4];"                                    \
                 : "=r"(r0), "=r"(r1), "=r"(r2), "=r"(r3) : "r"(addr))

__device__ __forceinline__ void mma16816(float* d, const uint32_t* a, const uint32_t* b) {
    asm volatile(
        "mma.sync.aligned.m16n8k16.row.col.f32.f16.f16.f32 "
        "{%0,%1,%2,%3}, {%4,%5,%6,%7}, {%8,%9}, {%0,%1,%2,%3};"
        : "+f"(d[0]), "+f"(d[1]), "+f"(d[2]), "+f"(d[3])
        : "r"(a[0]), "r"(a[1]), "r"(a[2]), "r"(a[3]), "r"(b[0]), "r"(b[1]));
}

__device__ __forceinline__ void pack_store2(uint8_t* p, float v0, float v1) {
    __half2 h = __float22half2_rn(make_float2(v0, v1));
    float2 f = __half22float2(h);
    __half2 l = __float22half2_rn(make_float2(v0 - f.x, v1 - f.y));
    *(uint32_t*)p = *(uint32_t*)&h;
    *(uint32_t*)(p + 64) = *(uint32_t*)&l;
}
__device__ __forceinline__ void pack_store4(uint8_t* p, float4 v) {
    __half2 h0 = __float22half2_rn(make_float2(v.x, v.y));
    __half2 h1 = __float22half2_rn(make_float2(v.z, v.w));
    float2 f0 = __half22float2(h0), f1 = __half22float2(h1);
    __half2 l0 = __float22half2_rn(make_float2(v.x - f0.x, v.y - f0.y));
    __half2 l1 = __float22half2_rn(make_float2(v.z - f1.x, v.w - f1.y));
    uint2 hu, lu;
    hu.x = *(uint32_t*)&h0; hu.y = *(uint32_t*)&h1;
    lu.x = *(uint32_t*)&l0; lu.y = *(uint32_t*)&l1;
    *(uint2*)p = hu;
    *(uint2*)(p + 64) = lu;
}

// ---------------------------------------------------------------------------
// pack fp32 [M,K] -> packed split fp16 ; batched over 3 tensors via blockIdx.z
// ---------------------------------------------------------------------------
__global__ void __launch_bounds__(256)
pack_split3(const float* __restrict__ s0, const float* __restrict__ s1,
            const float* __restrict__ s2,
            uint8_t* __restrict__ d0, uint8_t* __restrict__ d1,
            uint8_t* __restrict__ d2, int K)
{
    const float* src = (blockIdx.z == 0) ? s0 : (blockIdx.z == 1) ? s1 : s2;
    uint8_t* dst = (blockIdx.z == 0) ? d0 : (blockIdx.z == 1) ? d1 : d2;
    const long long idx = (long long)blockIdx.x * 256 + threadIdx.x;
    const int perRow = K >> 2;
    const long long m = idx / perRow;
    const int j = (int)(idx - m * perRow);
    float4 v = *(const float4*)(src + m * K + j * 4);
    const int e0 = j * 4;
    uint8_t* p = dst + (m * (K >> 5) + (e0 >> 5)) * 128 + (e0 & 31) * 2;
    pack_store4(p, v);
}
// fp32 -> plain fp16 (layout is just contiguous fp16)
__global__ void __launch_bounds__(256)
pack_plain(const float* __restrict__ src, uint8_t* __restrict__ dst)
{
    const long long idx = (long long)blockIdx.x * 256 + threadIdx.x;
    float4 v = *(const float4*)(src + idx * 4);
    __half2 h0 = __float22half2_rn(make_float2(v.x, v.y));
    __half2 h1 = __float22half2_rn(make_float2(v.z, v.w));
    uint2 u; u.x = *(uint32_t*)&h0; u.y = *(uint32_t*)&h1;
    *(uint2*)(dst + idx * 8) = u;
}

// ---------------------------------------------------------------------------
// Packed split-fp16 GEMM. CTA tile 128 x TN, 32-K chunks, 8 warps 4x2,
// 2 CTAs/SM. AP=2: hh + lh (B-lo dropped). AP=1: hh only.
// MODE 0: C fp32 + bias.  MODE 1: C packed-split + bias.
// MODE 2: exp(alpha*acc)*2^-4 -> PLAIN fp16 + rowsum atomics.
// ---------------------------------------------------------------------------
template<int TN, int MODE, int AP>
__global__ void __launch_bounds__(256, 2)
pk_gemm(const uint8_t* Apk, const uint8_t* __restrict__ Bpk,
        const float* __restrict__ bias,
        float* Cf, uint8_t* Cpk, float* rs,
        int nchunks, long long ldA, long long ldB, int ldc, long long ldCpk,
        int zdiv,
        long long sAo, long long sAi, long long sBo, long long sBi,
        long long sCfO, long long sCfI, long long sCpO, long long sCpI,
        long long rsO, long long rsI, float alpha)
{
    constexpr int NT = TN / 16;
    constexpr int NBL = TN / 64;
    constexpr int STAGE = 16384 + TN * 128;

    extern __shared__ uint8_t dyn_raw[];
    __shared__ float s_bias[TN];
    __shared__ float s_aux[128];

    const int tid = threadIdx.x, wid = tid >> 5, lane = tid & 31;
    const int z = blockIdx.z, zo = z / zdiv, zi = z - zo * zdiv;
    Apk += zo * sAo + zi * sAi;
    Bpk += zo * sBo + zi * sBi;
    if (MODE == 0) Cf += zo * sCfO + zi * sCfI;
    if (MODE != 0) Cpk += zo * sCpO + zi * sCpI;
    const long long rs_off = zo * rsO + zi * rsI;

    const long long m0 = (long long)blockIdx.y * 128;
    const long long n0 = (long long)blockIdx.x * TN;

    uint32_t raw = smem_u32(dyn_raw);
    uint32_t base = (raw + 1023u) & ~1023u;
    const uint32_t aSu[2] = { base, base + STAGE };
    const uint32_t bSu[2] = { base + 16384, base + STAGE + 16384 };

    if (MODE == 0 || MODE == 1) {
        for (int i = tid; i < TN; i += 256) s_bias[i] = bias ? bias[n0 + i] : 0.0f;
    }
    if (MODE == 2) { if (tid < 128) s_aux[tid] = 0.0f; }

    float acc[2][NT][4];
#pragma unroll
    for (int i = 0; i < 2; i++)
#pragma unroll
        for (int j = 0; j < NT; j++)
#pragma unroll
            for (int e = 0; e < 4; e++) acc[i][j][e] = 0.0f;

    const uint32_t a_row = (uint32_t)((lane & 7) + (lane & 8));
    const uint32_t a_kof = (uint32_t)(((lane >> 4) & 1) * 16);
    const uint32_t b_row = (uint32_t)((lane & 7) + ((lane >> 4) & 1) * 8);
    const uint32_t b_kof = (uint32_t)(((lane >> 3) & 1) * 16);
    const int wm = (wid & 3) * 32;
    const int wn = (wid >> 2) * (TN / 2);

    auto prefetch = [&](int s, int c) {
        const uint8_t* Ab = Apk + (long long)c * 128;
        if (AP == 2) {
#pragma unroll
            for (int i = 0; i < 4; i++) {       // A: hi + lo
                const int idx = i * 256 + tid, row = idx >> 3, g = idx & 7;
                cpa16(aSu[s] + sw128((uint32_t)(row * 128 + g * 16)),
                      Ab + (m0 + row) * ldA + g * 16);
            }
        } else {
#pragma unroll
            for (int i = 0; i < 2; i++) {       // A: hi only
                const int idx = i * 256 + tid, row = idx >> 2, g = idx & 3;
                cpa16(aSu[s] + sw128((uint32_t)(row * 128 + g * 16)),
                      Ab + (m0 + row) * ldA + g * 16);
            }
        }
        const uint8_t* Bb = Bpk + (long long)c * 128;
#pragma unroll
        for (int i = 0; i < NBL; i++) {         // B: hi only
            const int idx = i * 256 + tid, row = idx >> 2, g = idx & 3;
            cpa16(bSu[s] + sw128((uint32_t)(row * 128 + g * 16)),
                  Bb + (n0 + row) * ldB + g * 16);
        }
        CP_COMMIT();
    };

    prefetch(0, 0);
    int cur = 0;
    for (int c = 0; c < nchunks; c++) {
        if (c + 1 < nchunks) {
            prefetch(cur ^ 1, c + 1);
            CP_WAIT1();
        } else {
            CP_WAIT0();
        }
        __syncthreads();

        const uint32_t aS = aSu[cur], bS = bSu[cur];
#pragma unroll
        for (int ks = 0; ks < 2; ks++) {
            uint32_t ah[2][4], al[2][4], bf[NT][2];
#pragma unroll
            for (int mt = 0; mt < 2; mt++) {
                uint32_t off = (uint32_t)(wm + mt * 16 + a_row) * 128 + ks * 32 + a_kof;
                LDSM_X4(ah[mt][0], ah[mt][1], ah[mt][2], ah[mt][3], aS + sw128(off));
            }
#pragma unroll
            for (int p = 0; p < NT / 2; p++) {
                uint32_t r0, r1, r2, r3;
                uint32_t off = (uint32_t)(wn + p * 16 + b_row) * 128 + ks * 32 + b_kof;
                LDSM_X4(r0, r1, r2, r3, bS + sw128(off));
                bf[2 * p][0] = r0; bf[2 * p][1] = r1;
                bf[2 * p + 1][0] = r2; bf[2 * p + 1][1] = r3;
            }
#pragma unroll
            for (int mt = 0; mt < 2; mt++)
#pragma unroll
                for (int nt = 0; nt < NT; nt++)
                    mma16816(acc[mt][nt], ah[mt], bf[nt]);
            if (AP == 2) {
#pragma unroll
                for (int mt = 0; mt < 2; mt++) {
                    uint32_t off = (uint32_t)(wm + mt * 16 + a_row) * 128 + 64 + ks * 32 + a_kof;
                    LDSM_X4(al[mt][0], al[mt][1], al[mt][2], al[mt][3], aS + sw128(off));
                }
#pragma unroll
                for (int mt = 0; mt < 2; mt++)
#pragma unroll
                    for (int nt = 0; nt < NT; nt++)
                        mma16816(acc[mt][nt], al[mt], bf[nt]);
            }
        }
        __syncthreads();
        cur ^= 1;
    }

    // ---- epilogue ----
    const int g = lane >> 2, t = lane & 3;
    if (MODE == 2) {
        const float esc = 0.0625f;
#pragma unroll
        for (int mt = 0; mt < 2; mt++) {
            float sum0 = 0.0f, sum1 = 0.0f;
#pragma unroll
            for (int nt = 0; nt < NT; nt++) {
                const int colw = wn + nt * 8 + 2 * t;
                const long long row0 = m0 + wm + mt * 16 + g;
                float e0 = __expf(acc[mt][nt][0] * alpha) * esc;
                float e1 = __expf(acc[mt][nt][1] * alpha) * esc;
                float e2 = __expf(acc[mt][nt][2] * alpha) * esc;
                float e3 = __expf(acc[mt][nt][3] * alpha) * esc;
                const long long colg = n0 + colw;
                const long long ch = colg >> 6;
                const int wi = (int)(colg & 63);
                __half2 h01 = __float22half2_rn(make_float2(e0, e1));
                __half2 h23 = __float22half2_rn(make_float2(e2, e3));
                *(uint32_t*)(Cpk + row0 * ldCpk + ch * 128 + wi * 2) = *(uint32_t*)&h01;
                *(uint32_t*)(Cpk + (row0 + 8) * ldCpk + ch * 128 + wi * 2) = *(uint32_t*)&h23;
                sum0 += e0 + e1; sum1 += e2 + e3;
            }
            sum0 += __shfl_xor_sync(0xffffffffu, sum0, 1);
            sum0 += __shfl_xor_sync(0xffffffffu, sum0, 2);
            sum1 += __shfl_xor_sync(0xffffffffu, sum1, 1);
            sum1 += __shfl_xor_sync(0xffffffffu, sum1, 2);
            if (t == 0) {
                atomicAdd(&s_aux[wm + mt * 16 + g], sum0);
                atomicAdd(&s_aux[wm + mt * 16 + g + 8], sum1);
            }
        }
        __syncthreads();
        if (tid < 128)
            atomicAdd(&rs[rs_off + m0 + tid], s_aux[tid]);
    } else if (MODE == 1) {
#pragma unroll
        for (int mt = 0; mt < 2; mt++) {
#pragma unroll
            for (int nt = 0; nt < NT; nt++) {
                const int colw = wn + nt * 8 + 2 * t;
                const long long row0 = m0 + wm + mt * 16 + g;
                const float b0 = s_bias[colw], b1 = s_bias[colw + 1];
                const long long colg = n0 + colw;
                const long long ch = colg >> 5;
                const int wi = (int)(colg & 31);
                pack_store2(Cpk + row0 * ldCpk + ch * 128 + wi * 2,
                            acc[mt][nt][0] + b0, acc[mt][nt][1] + b1);
                pack_store2(Cpk + (row0 + 8) * ldCpk + ch * 128 + wi * 2,
                            acc[mt][nt][2] + b0, acc[mt][nt][3] + b1);
            }
        }
    } else {
#pragma unroll
        for (int mt = 0; mt < 2; mt++) {
#pragma unroll
            for (int nt = 0; nt < NT; nt++) {
                const int colw = wn + nt * 8 + 2 * t;
                const float b0 = s_bias[colw], b1 = s_bias[colw + 1];
                const long long row0 = m0 + wm + mt * 16 + g;
                *(float2*)(Cf + row0 * (long long)ldc + n0 + colw) =
                    make_float2(acc[mt][nt][0] + b0, acc[mt][nt][1] + b1);
                *(float2*)(Cf + (row0 + 8) * (long long)ldc + n0 + colw) =
                    make_float2(acc[mt][nt][2] + b0, acc[mt][nt][3] + b1);
            }
        }
    }
}

// ---------------------------------------------------------------------------
// Plain fp16 GEMM (single pass): C[128 x TN] = A_plain @ B_plain^T + bias.
// K-chunks of 64 (128B rows). 8 warps 4x2, 2 CTAs/SM. Used for o-proj.
// ---------------------------------------------------------------------------
template<int TN>
__global__ void __launch_bounds__(256, 2)
plain_gemm(const uint8_t* __restrict__ Apl, const uint8_t* __restrict__ Bpl,
           const float* __restrict__ bias, float* __restrict__ Cf,
           int nchunks, long long ldA, long long ldB, int ldc)
{
    constexpr int NT = TN / 16;
    constexpr int NB = TN / 32;
    constexpr int STAGE = 16384 + TN * 128;

    extern __shared__ uint8_t dyn_raw[];
    __shared__ float s_bias[TN];

    const int tid = threadIdx.x, wid = tid >> 5, lane = tid & 31;
    const long long m0 = (long long)blockIdx.y * 128;
    const long long n0 = (long long)blockIdx.x * TN;

    uint32_t raw = smem_u32(dyn_raw);
    uint32_t base = (raw + 1023u) & ~1023u;
    const uint32_t aSu[2] = { base, base + STAGE };
    const uint32_t bSu[2] = { base + 16384, base + STAGE + 16384 };

    for (int i = tid; i < TN; i += 256) s_bias[i] = bias ? bias[n0 + i] : 0.0f;

    float acc[2][NT][4];
#pragma unroll
    for (int i = 0; i < 2; i++)
#pragma unroll
        for (int j = 0; j < NT; j++)
#pragma unroll
            for (int e = 0; e < 4; e++) acc[i][j][e] = 0.0f;

    const uint32_t a_row = (uint32_t)((lane & 7) + (lane & 8));
    const uint32_t a_kof = (uint32_t)(((lane >> 4) & 1) * 16);
    const uint32_t b_row = (uint32_t)((lane & 7) + ((lane >> 4) & 1) * 8);
    const uint32_t b_kof = (uint32_t)(((lane >> 3) & 1) * 16);
    const int wm = (wid & 3) * 32;
    const int wn = (wid >> 2) * (TN / 2);

    auto prefetch = [&](int s, int c) {
#pragma unroll
        for (int i = 0; i < 4; i++) {
            const int idx = i * 256 + tid, row = idx >> 3, g = idx & 7;
            cpa16(aSu[s] + sw128((uint32_t)(row * 128 + g * 16)),
                  Apl + (m0 + row) * ldA + c * 128 + g * 16);
        }
#pragma unroll
        for (int i = 0; i < NB; i++) {
            const int idx = i * 256 + tid, row = idx >> 3, g = idx & 7;
            cpa16(bSu[s] + sw128((uint32_t)(row * 128 + g * 16)),
                  Bpl + (n0 + row) * ldB + c * 128 + g * 16);
        }
        CP_COMMIT();
    };

    prefetch(0, 0);
    int cur = 0;
    for (int c = 0; c < nchunks; c++) {
        if (c + 1 < nchunks) { prefetch(cur ^ 1, c + 1); CP_WAIT1(); }
        else                 { CP_WAIT0(); }
        __syncthreads();

        const uint32_t aS = aSu[cur], bS = bSu[cur];
#pragma unroll
        for (int ks = 0; ks < 4; ks++) {
            uint32_t ah[2][4], bf[NT][2];
#pragma unroll
            for (int mt = 0; mt < 2; mt++) {
                uint32_t off = (uint32_t)(wm + mt * 16 + a_row) * 128 + ks * 32 + a_kof;
                LDSM_X4(ah[mt][0], ah[mt][1], ah[mt][2], ah[mt][3], aS + sw128(off));
            }
#pragma unroll
            for (int p = 0; p < NT / 2; p++) {
                uint32_t r0, r1, r2, r3;
                uint32_t off = (uint32_t)(wn + p * 16 + b_row) * 128 + ks * 32 + b_kof;
                LDSM_X4(r0, r1, r2, r3, bS + sw128(off));
                bf[2 * p][0] = r0; bf[2 * p][1] = r1;
                bf[2 * p + 1][0] = r2; bf[2 * p + 1][1] = r3;
            }
#pragma unroll
            for (int mt = 0; mt < 2; mt++)
#pragma unroll
                for (int nt = 0; nt < NT; nt++)
                    mma16816(acc[mt][nt], ah[mt], bf[nt]);
        }
        __syncthreads();
        cur ^= 1;
    }

    const int g = lane >> 2, t = lane & 3;
#pragma unroll
    for (int mt = 0; mt < 2; mt++) {
#pragma unroll
        for (int nt = 0; nt < NT; nt++) {
            const int colw = wn + nt * 8 + 2 * t;
            const float b0 = s_bias[colw], b1 = s_bias[colw + 1];
            const long long row0 = m0 + wm + mt * 16 + g;
            *(float2*)(Cf + row0 * (long long)ldc + n0 + colw) =
                make_float2(acc[mt][nt][0] + b0, acc[mt][nt][1] + b1);
            *(float2*)(Cf + (row0 + 8) * (long long)ldc + n0 + colw) =
                make_float2(acc[mt][nt][2] + b0, acc[mt][nt][3] + b1);
        }
    }
}

// ---------------------------------------------------------------------------
// PV plain-fp16 GEMM: O[128 x 64] += P(fp16) @ V(fp16), K-chunks of 64.
// Writes normalized fp32 P (required output) and plain-fp16 O.
// ---------------------------------------------------------------------------
__global__ void __launch_bounds__(256, 2)
pv_plain(const uint8_t* __restrict__ expP, const uint8_t* __restrict__ vT,
         float* __restrict__ attn, uint8_t* __restrict__ oapl,
         const float* __restrict__ rs)
{
    extern __shared__ uint8_t dyn_raw[];
    __shared__ float s_aux[128];

    const int tid = threadIdx.x, wid = tid >> 5, lane = tid & 31;
    const int qb = blockIdx.x;
    const int z = blockIdx.y;
    const int b = z >> 4, h = z & 15;
    const long long m0 = (long long)qb * 128;

    const uint8_t* P = expP + ((long long)(h * B_ + b) * L_ + m0) * 4096;
    const uint8_t* Vt = vT + (long long)z * 64 * 4096;
    float* Pf = attn + ((long long)(h * B_ + b) * L_ + m0) * L_;
    uint8_t* Oa = oapl + ((long long)b * L_ + m0) * 2048 + h * 128;
    const float* rsb = rs + (long long)(h * B_ + b) * L_ + m0;

    uint32_t raw = smem_u32(dyn_raw);
    uint32_t base = (raw + 1023u) & ~1023u;
    uint8_t* dsm = dyn_raw + (base - raw);
    const int STAGE = 16384 + 8192;
    uint8_t* smA[2] = { dsm, dsm + STAGE };
    const uint32_t aSu[2] = { base, base + STAGE };
    const uint32_t bSu[2] = { base + 16384, base + STAGE + 16384 };

    if (tid < 128) s_aux[tid] = 1.0f / rsb[tid];
    __syncthreads();

    float acc[2][4][4];
#pragma unroll
    for (int i = 0; i < 2; i++)
#pragma unroll
        for (int j = 0; j < 4; j++)
#pragma unroll
            for (int e = 0; e < 4; e++) acc[i][j][e] = 0.0f;

    const uint32_t a_row = (uint32_t)((lane & 7) + (lane & 8));
    const uint32_t a_kof = (uint32_t)(((lane >> 4) & 1) * 16);
    const uint32_t b_row = (uint32_t)((lane & 7) + ((lane >> 4) & 1) * 8);
    const uint32_t b_kof = (uint32_t)(((lane >> 3) & 1) * 16);
    const int wm = (wid & 3) * 32;
    const int wn = (wid >> 2) * 32;

    auto prefetch = [&](int s, int c) {
#pragma unroll
        for (int i = 0; i < 4; i++) {
            const int idx = i * 256 + tid, row = idx >> 3, g = idx & 7;
            cpa16(aSu[s] + sw128((uint32_t)(row * 128 + g * 16)),
                  P + (long long)row * 4096 + c * 128 + g * 16);
        }
#pragma unroll
        for (int i = 0; i < 2; i++) {
            const int idx = i * 256 + tid, row = idx >> 3, g = idx & 7;
            cpa16(bSu[s] + sw128((uint32_t)(row * 128 + g * 16)),
                  Vt + (long long)row * 4096 + c * 128 + g * 16);
        }
        CP_COMMIT();
    };

    prefetch(0, 0);
    int cur = 0;
    for (int c = 0; c < 32; c++) {
        if (c + 1 < 32) { prefetch(cur ^ 1, c + 1); CP_WAIT1(); }
        else            { CP_WAIT0(); }
        __syncthreads();

        // normalized fp32 P write (required output)
        {
            const int r = tid >> 1, hh = tid & 1;
            const uint8_t* sa = smA[cur];
            const float inv = s_aux[r];
            float* dst = Pf + (long long)r * L_ + c * 64 + hh * 32;
#pragma unroll
            for (int j = 0; j < 4; j++) {
                uint4 u = *(const uint4*)(sa + sw128((uint32_t)(r * 128 + hh * 64 + j * 16)));
                const uint32_t w[4] = { u.x, u.y, u.z, u.w };
                float o[8];
#pragma unroll
                for (int jj = 0; jj < 4; jj++) {
                    __half2 hb = *(const __half2*)&w[jj];
                    float2 f = __half22float2(hb);
                    o[2 * jj] = f.x * inv;
                    o[2 * jj + 1] = f.y * inv;
                }
                *(float4*)(dst + j * 8)     = make_float4(o[0], o[1], o[2], o[3]);
                *(float4*)(dst + j * 8 + 4) = make_float4(o[4], o[5], o[6], o[7]);
            }
        }

        const uint32_t aS = aSu[cur], bS = bSu[cur];
#pragma unroll
        for (int ks = 0; ks < 4; ks++) {
            uint32_t ah[2][4], bf[4][2];
#pragma unroll
            for (int mt = 0; mt < 2; mt++) {
                uint32_t off = (uint32_t)(wm + mt * 16 + a_row) * 128 + ks * 32 + a_kof;
                LDSM_X4(ah[mt][0], ah[mt][1], ah[mt][2], ah[mt][3], aS + sw128(off));
            }
#pragma unroll
            for (int p = 0; p < 2; p++) {
                uint32_t r0, r1, r2, r3;
                uint32_t off = (uint32_t)(wn + p * 16 + b_row) * 128 + ks * 32 + b_kof;
                LDSM_X4(r0, r1, r2, r3, bS + sw128(off));
                bf[2 * p][0] = r0; bf[2 * p][1] = r1;
                bf[2 * p + 1][0] = r2; bf[2 * p + 1][1] = r3;
            }
#pragma unroll
            for (int mt = 0; mt < 2; mt++)
#pragma unroll
                for (int nt = 0; nt < 4; nt++)
                    mma16816(acc[mt][nt], ah[mt], bf[nt]);
        }
        __syncthreads();
        cur ^= 1;
    }

    // epilogue: O * 1/rowsum -> plain fp16
    const int g = lane >> 2, t = lane & 3;
#pragma unroll
    for (int mt = 0; mt < 2; mt++) {
        const float i0 = s_aux[wm + mt * 16 + g];
        const float i1 = s_aux[wm + mt * 16 + g + 8];
#pragma unroll
        for (int nt = 0; nt < 4; nt++) {
            const int colw = wn + nt * 8 + 2 * t;
            const int row0 = wm + mt * 16 + g;
            __half2 h0 = __float22half2_rn(make_float2(acc[mt][nt][0] * i0, acc[mt][nt][1] * i0));
            __half2 h1 = __float22half2_rn(make_float2(acc[mt][nt][2] * i1, acc[mt][nt][3] * i1));
            *(uint32_t*)(Oa + (long long)row0 * 2048 + colw * 2) = *(uint32_t*)&h0;
            *(uint32_t*)(Oa + (long long)(row0 + 8) * 2048 + colw * 2) = *(uint32_t*)&h1;
        }
    }
}

// ---------------------------------------------------------------------------
// V transpose: vh fp32 [B,L,H,DK] -> vT plain fp16 [(b*H+h)][dk][L/64][128B]
// ---------------------------------------------------------------------------
__global__ void __launch_bounds__(256)
transpose_v_pk(const float* __restrict__ vh, uint8_t* __restrict__ vT)
{
    __shared__ float tsm[32][33];
    const int bh = blockIdx.z;
    const int b = bh >> 4, h = bh & 15;
    const int l0 = blockIdx.x * 32;
    const int d0 = blockIdx.y * 32;
    const int tid = threadIdx.x;
    const int tx = tid & 31;
    const int ty = tid >> 5;

    const float* src = vh + ((long long)b * L_ + l0) * HD_ + h * DK_ + d0;
#pragma unroll
    for (int i = 0; i < 32; i += 8)
        tsm[ty + i][tx] = src[(long long)(ty + i) * HD_ + tx];
    __syncthreads();

    const int lp = tid & 15;
#pragma unroll
    for (int it = 0; it < 2; it++) {
        const int d = (tid >> 4) + 16 * it;
        const int lg = l0 + 2 * lp;
        uint8_t* p = vT + ((long long)bh * 64 + d0 + d) * 4096
                        + (lg >> 6) * 128 + (lg & 63) * 2;
        __half2 hv = __float22half2_rn(make_float2(tsm[2 * lp][d], tsm[2 * lp + 1][d]));
        *(uint32_t*)p = *(uint32_t*)&hv;
    }
}

__global__ void zero_rs(float* __restrict__ rs)
{
    rs[blockIdx.x * 256 + threadIdx.x] = 0.0f;
}

// ---------------------------------------------------------------------------
// LayerNorm + residual
// ---------------------------------------------------------------------------
__global__ void __launch_bounds__(256)
ln_residual(const float* __restrict__ x, const float* __restrict__ res,
            const float* __restrict__ gam, const float* __restrict__ bet,
            float* __restrict__ out)
{
    const long long row = blockIdx.x;
    const float4* x4 = (const float4*)(x   + row * D_);
    const float4* r4 = (const float4*)(res + row * D_);
    const int tid = threadIdx.x;

    float4 v = x4[tid];
    float s  = (v.x + v.y) + (v.z + v.w);
    float sq = (v.x * v.x + v.y * v.y) + (v.z * v.z + v.w * v.w);
#pragma unroll
    for (int o = 16; o > 0; o >>= 1) {
        s  += __shfl_xor_sync(0xffffffffu, s,  o);
        sq += __shfl_xor_sync(0xffffffffu, sq, o);
    }
    __shared__ float ss[8], sqs[8];
    if ((tid & 31) == 0) { ss[tid >> 5] = s; sqs[tid >> 5] = sq; }
    __syncthreads();
    s  = (ss[0]  + ss[1])  + (ss[2]  + ss[3])  + (ss[4]  + ss[5])  + (ss[6]  + ss[7]);
    sq = (sqs[0] + sqs[1]) + (sqs[2] + sqs[3]) + (sqs[4] + sqs[5]) + (sqs[6] + sqs[7]);

    const float mean = s * (1.0f / D_);
    float var = sq * (1.0f / D_) - mean * mean;
    var = fmaxf(var, 0.0f);
    const float rstd = rsqrtf(var + LN_EPS_);

    float4 g  = ((const float4*)gam)[tid];
    float4 bt = ((const float4*)bet)[tid];
    float4 r  = r4[tid];
    float4 o;
    o.x = (v.x - mean) * rstd * g.x + bt.x + r.x;
    o.y = (v.y - mean) * rstd * g.y + bt.y + r.y;
    o.z = (v.z - mean) * rstd * g.z + bt.z + r.z;
    o.w = (v.w - mean) * rstd * g.w + bt.w + r.w;
    ((float4*)(out + row * D_))[tid] = o;
}

// ---------------------------------------------------------------------------
// Launch
// ---------------------------------------------------------------------------
extern "C" void kernel_launch(void* const* d_in, const int* in_sizes, int n_in,
                              void* d_out, int out_size)
{
    (void)in_sizes; (void)n_in; (void)out_size;
    const float* q  = (const float*)d_in[0];
    const float* k  = (const float*)d_in[1];
    const float* v  = (const float*)d_in[2];
    const float* wq = (const float*)d_in[3];
    const float* bq = (const float*)d_in[4];
    const float* wk = (const float*)d_in[5];
    const float* bk = (const float*)d_in[6];
    const float* wv = (const float*)d_in[7];
    const float* bv = (const float*)d_in[8];
    const float* wo = (const float*)d_in[9];
    const float* bo = (const float*)d_in[10];
    const float* lg = (const float*)d_in[11];
    const float* lb = (const float*)d_in[12];

    float* out  = (float*)d_out;
    float* attn = out + (long long)B_ * L_ * D_;

    uint8_t *qpk, *kpk, *vpk, *wqpk, *wkpk, *wvpk, *wopl, *qhpk, *khpk, *vT, *oapl, *expP;
    float *vh, *op, *rs;
    cudaGetSymbolAddress((void**)&qpk,  g_qpk);
    cudaGetSymbolAddress((void**)&kpk,  g_kpk);
    cudaGetSymbolAddress((void**)&vpk,  g_vpk);
    cudaGetSymbolAddress((void**)&wqpk, g_wqpk);
    cudaGetSymbolAddress((void**)&wkpk, g_wkpk);
    cudaGetSymbolAddress((void**)&wvpk, g_wvpk);
    cudaGetSymbolAddress((void**)&wopl, g_wopl);
    cudaGetSymbolAddress((void**)&qhpk, g_qhpk);
    cudaGetSymbolAddress((void**)&khpk, g_khpk);
    cudaGetSymbolAddress((void**)&vT,   g_vT);
    cudaGetSymbolAddress((void**)&oapl, g_oapl);
    cudaGetSymbolAddress((void**)&expP, g_expP);
    cudaGetSymbolAddress((void**)&vh,   g_vh);
    cudaGetSymbolAddress((void**)&op,   g_op);
    cudaGetSymbolAddress((void**)&rs,   g_rs);

    const int SMEM128 = 2 * (16384 + 128 * 128) + 1024;   // 66560
    const int SMEMPV  = 2 * (16384 + 8192) + 1024;        // 50176
    cudaFuncSetAttribute((const void*)pk_gemm<128, 0, 1>, cudaFuncAttributeMaxDynamicSharedMemorySize, SMEM128);
    cudaFuncSetAttribute((const void*)pk_gemm<128, 1, 2>, cudaFuncAttributeMaxDynamicSharedMemorySize, SMEM128);
    cudaFuncSetAttribute((const void*)pk_gemm<128, 2, 2>, cudaFuncAttributeMaxDynamicSharedMemorySize, SMEM128);
    cudaFuncSetAttribute((const void*)plain_gemm<128>,    cudaFuncAttributeMaxDynamicSharedMemorySize, SMEM128);
    cudaFuncSetAttribute((const void*)pv_plain,           cudaFuncAttributeMaxDynamicSharedMemorySize, SMEMPV);

    dim3 blk(256);

    zero_rs<<<NROWS_ATTN / 256, blk>>>(rs);

    // pack inputs + weights
    pack_split3<<<dim3(MROWS_ * D_ / 4 / 256, 1, 3), blk>>>(q, k, v, qpk, kpk, vpk, D_);
    pack_split3<<<dim3(HD_ * D_ / 4 / 256, 1, 3), blk>>>(wq, wk, wv, wqpk, wkpk, wvpk, D_);
    pack_plain<<<D_ * HD_ / 4 / 256, blk>>>(wo, wopl);

    const long long ld32 = 32 * 128;   // 4096B row (K=1024 packed split)

    // Q/K projections 2-pass; V projection 1-pass (out-path tolerance)
    dim3 gproj(HD_ / 128, MROWS_ / 128, 1);
    pk_gemm<128, 1, 2><<<gproj, blk, SMEM128>>>(qpk, wqpk, bq, nullptr, qhpk, nullptr,
        32, ld32, ld32, 0, ld32, 1,
        0, 0, 0, 0, 0, 0, 0, 0, 0, 0, 1.0f);
    pk_gemm<128, 1, 2><<<gproj, blk, SMEM128>>>(kpk, wkpk, bk, nullptr, khpk, nullptr,
        32, ld32, ld32, 0, ld32, 1,
        0, 0, 0, 0, 0, 0, 0, 0, 0, 0, 1.0f);
    pk_gemm<128, 0, 1><<<gproj, blk, SMEM128>>>(vpk, wvpk, bv, vh, nullptr, nullptr,
        32, ld32, ld32, HD_, 0, 1,
        0, 0, 0, 0, 0, 0, 0, 0, 0, 0, 1.0f);

    transpose_v_pk<<<dim3(L_ / 32, DK_ / 32, B_ * H_), blk>>>(vh, vT);

    // Scores (K=64 -> 2 chunks), 2-pass, plain fp16 expP + rowsums
    dim3 gsc(L_ / 128, L_ / 128, B_ * H_);
    pk_gemm<128, 2, 2><<<gsc, blk, SMEM128>>>(qhpk, khpk, nullptr, nullptr, expP, rs,
        2, ld32, ld32, 0, (long long)L_ * 2, H_,
        (long long)L_ * ld32, 256,
        (long long)L_ * ld32, 256,
        0, 0,
        (long long)L_ * L_ * 2, (long long)B_ * L_ * L_ * 2,
        (long long)L_, (long long)B_ * L_,
        0.125f);

    // PV single-pass plain fp16; writes fp32 attn + plain-fp16 oa
    pv_plain<<<dim3(L_ / 128, B_ * H_, 1), blk, SMEMPV>>>(expP, vT, attn, oapl, rs);

    // Output projection: plain fp16 single-pass (K=1024 -> 16 chunks of 64)
    dim3 gop(D_ / 128, MROWS_ / 128, 1);
    plain_gemm<128><<<gop, blk, SMEM128>>>(oapl, wopl, bo, op, 16, 2048, 2048, D_);

    // LayerNorm + residual
    ln_residual<<<MROWS_, blk>>>(op, q, lg, lb, out);
}

// round 15
// speedup vs baseline: 1.5726x; 1.0848x over previous
#include <cuda_runtime.h>
#include <cuda_fp16.h>
#include <stdint.h>

#define B_   4
#define L_   2048
#define D_   1024
#define H_   16
#define DK_  64
#define HD_  1024
#define MROWS_ 8192
#define LN_EPS_ 1e-5f
#define NROWS_ATTN (B_ * H_ * L_)

// ---------------------------------------------------------------------------
// Scratch. Packed split-fp16: [M][K/32][32 hi | 32 lo] 128B chunks.
// Plain fp16: [M][K/64][64 fp16] 128B chunks.
// q/k share combined buffers (contiguous halves) for merged launches.
// ---------------------------------------------------------------------------
__device__ __align__(256) uint8_t g_qkpk [2ll * MROWS_ * D_ * 4];
__device__ __align__(256) uint8_t g_vpk  [(long long)MROWS_ * D_ * 4];
__device__ __align__(256) uint8_t g_wqkpk[2ll * HD_ * D_ * 4];
__device__ __align__(256) uint8_t g_wvpk [(long long)HD_ * D_ * 4];
__device__ __align__(256) uint8_t g_wopl [(long long)D_ * HD_ * 2];
__device__ __align__(256) uint8_t g_qkhpk[2ll * MROWS_ * HD_ * 4];
__device__ __align__(256) uint8_t g_vT   [(long long)B_ * H_ * DK_ * L_ * 2];
__device__ __align__(256) uint8_t g_oapl [(long long)MROWS_ * HD_ * 2];
__device__ __align__(256) uint8_t g_expP [(long long)B_ * H_ * L_ * L_ * 2];
__device__ float g_vh[MROWS_ * HD_];
__device__ float g_op[MROWS_ * HD_];
__device__ float g_rs[NROWS_ATTN];

// ---------------------------------------------------------------------------
// helpers
// ---------------------------------------------------------------------------
__device__ __forceinline__ uint32_t smem_u32(const void* p) {
    uint32_t a;
    asm("{ .reg .u64 t; cvta.to.shared.u64 t, %1; cvt.u32.u64 %0, t; }" : "=r"(a) : "l"(p));
    return a;
}
__device__ __forceinline__ uint32_t sw128(uint32_t off) {
    return off ^ ((off >> 3) & 0x70);
}
__device__ __forceinline__ void cpa16(uint32_t dst, const void* src) {
    asm volatile("cp.async.cg.shared.global [%0], [%1], 16;" :: "r"(dst), "l"(src));
}
#define CP_COMMIT() asm volatile("cp.async.commit_group;" ::: "memory")
#define CP_WAIT0()  asm volatile("cp.async.wait_group 0;" ::: "memory")
#define CP_WAIT1()  asm volatile("cp.async.wait_group 1;" ::: "memory")
#define LDSM_X4(r0, r1, r2, r3, addr)                                      \
    asm volatile("ldmatrix.sync.aligned.m8n8.x4.shared.b16 "               \
                 "{%0,%1,%2,%3}, [%4];"                                    \
                 : "=r"(r0), "=r"(r1), "=r"(r2), "=r"(r3) : "r"(addr))
#define STG_CS_F4(addr, v)                                                 \
    asm volatile("st.global.cs.v4.f32 [%0], {%1,%2,%3,%4};"                \
                 :: "l"(addr), "f"((v).x), "f"((v).y), "f"((v).z), "f"((v).w) : "memory")
#define STG_CS_U32(addr, v)                                                \
    asm volatile("st.global.cs.b32 [%0], %1;" :: "l"(addr), "r"(v) : "memory")

__device__ __forceinline__ void mma16816(float* d, const uint32_t* a, const uint32_t* b) {
    asm volatile(
        "mma.sync.aligned.m16n8k16.row.col.f32.f16.f16.f32 "
        "{%0,%1,%2,%3}, {%4,%5,%6,%7}, {%8,%9}, {%0,%1,%2,%3};"
        : "+f"(d[0]), "+f"(d[1]), "+f"(d[2]), "+f"(d[3])
        : "r"(a[0]), "r"(a[1]), "r"(a[2]), "r"(a[3]), "r"(b[0]), "r"(b[1]));
}

__device__ __forceinline__ void pack_store2(uint8_t* p, float v0, float v1) {
    __half2 h = __float22half2_rn(make_float2(v0, v1));
    float2 f = __half22float2(h);
    __half2 l = __float22half2_rn(make_float2(v0 - f.x, v1 - f.y));
    *(uint32_t*)p = *(uint32_t*)&h;
    *(uint32_t*)(p + 64) = *(uint32_t*)&l;
}
__device__ __forceinline__ void pack_store4(uint8_t* p, float4 v) {
    __half2 h0 = __float22half2_rn(make_float2(v.x, v.y));
    __half2 h1 = __float22half2_rn(make_float2(v.z, v.w));
    float2 f0 = __half22float2(h0), f1 = __half22float2(h1);
    __half2 l0 = __float22half2_rn(make_float2(v.x - f0.x, v.y - f0.y));
    __half2 l1 = __float22half2_rn(make_float2(v.z - f1.x, v.w - f1.y));
    uint2 hu, lu;
    hu.x = *(uint32_t*)&h0; hu.y = *(uint32_t*)&h1;
    lu.x = *(uint32_t*)&l0; lu.y = *(uint32_t*)&l1;
    *(uint2*)p = hu;
    *(uint2*)(p + 64) = lu;
}

// ---------------------------------------------------------------------------
// pack fp32 [M,K] -> packed split fp16 ; batched over 3 tensors via blockIdx.z
// ---------------------------------------------------------------------------
__global__ void __launch_bounds__(256)
pack_split3(const float* __restrict__ s0, const float* __restrict__ s1,
            const float* __restrict__ s2,
            uint8_t* __restrict__ d0, uint8_t* __restrict__ d1,
            uint8_t* __restrict__ d2, int K)
{
    const float* src = (blockIdx.z == 0) ? s0 : (blockIdx.z == 1) ? s1 : s2;
    uint8_t* dst = (blockIdx.z == 0) ? d0 : (blockIdx.z == 1) ? d1 : d2;
    const long long idx = (long long)blockIdx.x * 256 + threadIdx.x;
    const int perRow = K >> 2;
    const long long m = idx / perRow;
    const int j = (int)(idx - m * perRow);
    float4 v = *(const float4*)(src + m * K + j * 4);
    const int e0 = j * 4;
    uint8_t* p = dst + (m * (K >> 5) + (e0 >> 5)) * 128 + (e0 & 31) * 2;
    pack_store4(p, v);
}
__global__ void __launch_bounds__(256)
pack_plain(const float* __restrict__ src, uint8_t* __restrict__ dst)
{
    const long long idx = (long long)blockIdx.x * 256 + threadIdx.x;
    float4 v = *(const float4*)(src + idx * 4);
    __half2 h0 = __float22half2_rn(make_float2(v.x, v.y));
    __half2 h1 = __float22half2_rn(make_float2(v.z, v.w));
    uint2 u; u.x = *(uint32_t*)&h0; u.y = *(uint32_t*)&h1;
    *(uint2*)(dst + idx * 8) = u;
}

// ---------------------------------------------------------------------------
// Packed split-fp16 GEMM. CTA tile 128 x TN, 32-K chunks, 8 warps 4x2,
// 2 CTAs/SM. AP=2: hh + lh (B-lo dropped). AP=1: hh only.
// MODE 0: C fp32 + bias.  MODE 1: C packed-split + bias (bias2 for zo==1).
// MODE 2: exp(alpha*acc)*2^-4 -> PLAIN fp16 (streaming) + rowsum atomics.
// ---------------------------------------------------------------------------
template<int TN, int MODE, int AP>
__global__ void __launch_bounds__(256, 2)
pk_gemm(const uint8_t* Apk, const uint8_t* Bpk,
        const float* __restrict__ bias, const float* __restrict__ bias2,
        float* Cf, uint8_t* Cpk, float* rs,
        int nchunks, long long ldA, long long ldB, int ldc, long long ldCpk,
        int zdiv,
        long long sAo, long long sAi, long long sBo, long long sBi,
        long long sCfO, long long sCfI, long long sCpO, long long sCpI,
        long long rsO, long long rsI, float alpha)
{
    constexpr int NT = TN / 16;
    constexpr int NBL = TN / 64;
    constexpr int STAGE = 16384 + TN * 128;

    extern __shared__ uint8_t dyn_raw[];
    __shared__ float s_bias[TN];
    __shared__ float s_aux[128];

    const int tid = threadIdx.x, wid = tid >> 5, lane = tid & 31;
    const int z = blockIdx.z, zo = z / zdiv, zi = z - zo * zdiv;
    Apk += zo * sAo + zi * sAi;
    Bpk += zo * sBo + zi * sBi;
    if (MODE == 0) Cf += zo * sCfO + zi * sCfI;
    if (MODE != 0) Cpk += zo * sCpO + zi * sCpI;
    const long long rs_off = zo * rsO + zi * rsI;

    const long long m0 = (long long)blockIdx.y * 128;
    const long long n0 = (long long)blockIdx.x * TN;

    uint32_t raw = smem_u32(dyn_raw);
    uint32_t base = (raw + 1023u) & ~1023u;
    const uint32_t aSu[2] = { base, base + STAGE };
    const uint32_t bSu[2] = { base + 16384, base + STAGE + 16384 };

    if (MODE == 0 || MODE == 1) {
        const float* bp = (zo == 1 && bias2) ? bias2 : bias;
        for (int i = tid; i < TN; i += 256) s_bias[i] = bp ? bp[n0 + i] : 0.0f;
    }
    if (MODE == 2) { if (tid < 128) s_aux[tid] = 0.0f; }

    float acc[2][NT][4];
#pragma unroll
    for (int i = 0; i < 2; i++)
#pragma unroll
        for (int j = 0; j < NT; j++)
#pragma unroll
            for (int e = 0; e < 4; e++) acc[i][j][e] = 0.0f;

    const uint32_t a_row = (uint32_t)((lane & 7) + (lane & 8));
    const uint32_t a_kof = (uint32_t)(((lane >> 4) & 1) * 16);
    const uint32_t b_row = (uint32_t)((lane & 7) + ((lane >> 4) & 1) * 8);
    const uint32_t b_kof = (uint32_t)(((lane >> 3) & 1) * 16);
    const int wm = (wid & 3) * 32;
    const int wn = (wid >> 2) * (TN / 2);

    auto prefetch = [&](int s, int c) {
        const uint8_t* Ab = Apk + (long long)c * 128;
        if (AP == 2) {
#pragma unroll
            for (int i = 0; i < 4; i++) {
                const int idx = i * 256 + tid, row = idx >> 3, g = idx & 7;
                cpa16(aSu[s] + sw128((uint32_t)(row * 128 + g * 16)),
                      Ab + (m0 + row) * ldA + g * 16);
            }
        } else {
#pragma unroll
            for (int i = 0; i < 2; i++) {
                const int idx = i * 256 + tid, row = idx >> 2, g = idx & 3;
                cpa16(aSu[s] + sw128((uint32_t)(row * 128 + g * 16)),
                      Ab + (m0 + row) * ldA + g * 16);
            }
        }
        const uint8_t* Bb = Bpk + (long long)c * 128;
#pragma unroll
        for (int i = 0; i < NBL; i++) {
            const int idx = i * 256 + tid, row = idx >> 2, g = idx & 3;
            cpa16(bSu[s] + sw128((uint32_t)(row * 128 + g * 16)),
                  Bb + (n0 + row) * ldB + g * 16);
        }
        CP_COMMIT();
    };

    prefetch(0, 0);
    int cur = 0;
    for (int c = 0; c < nchunks; c++) {
        if (c + 1 < nchunks) {
            prefetch(cur ^ 1, c + 1);
            CP_WAIT1();
        } else {
            CP_WAIT0();
        }
        __syncthreads();

        const uint32_t aS = aSu[cur], bS = bSu[cur];
#pragma unroll
        for (int ks = 0; ks < 2; ks++) {
            uint32_t ah[2][4], al[2][4], bf[NT][2];
#pragma unroll
            for (int mt = 0; mt < 2; mt++) {
                uint32_t off = (uint32_t)(wm + mt * 16 + a_row) * 128 + ks * 32 + a_kof;
                LDSM_X4(ah[mt][0], ah[mt][1], ah[mt][2], ah[mt][3], aS + sw128(off));
            }
#pragma unroll
            for (int p = 0; p < NT / 2; p++) {
                uint32_t r0, r1, r2, r3;
                uint32_t off = (uint32_t)(wn + p * 16 + b_row) * 128 + ks * 32 + b_kof;
                LDSM_X4(r0, r1, r2, r3, bS + sw128(off));
                bf[2 * p][0] = r0; bf[2 * p][1] = r1;
                bf[2 * p + 1][0] = r2; bf[2 * p + 1][1] = r3;
            }
#pragma unroll
            for (int mt = 0; mt < 2; mt++)
#pragma unroll
                for (int nt = 0; nt < NT; nt++)
                    mma16816(acc[mt][nt], ah[mt], bf[nt]);
            if (AP == 2) {
#pragma unroll
                for (int mt = 0; mt < 2; mt++) {
                    uint32_t off = (uint32_t)(wm + mt * 16 + a_row) * 128 + 64 + ks * 32 + a_kof;
                    LDSM_X4(al[mt][0], al[mt][1], al[mt][2], al[mt][3], aS + sw128(off));
                }
#pragma unroll
                for (int mt = 0; mt < 2; mt++)
#pragma unroll
                    for (int nt = 0; nt < NT; nt++)
                        mma16816(acc[mt][nt], al[mt], bf[nt]);
            }
        }
        __syncthreads();
        cur ^= 1;
    }

    // ---- epilogue ----
    const int g = lane >> 2, t = lane & 3;
    if (MODE == 2) {
        const float esc = 0.0625f;
#pragma unroll
        for (int mt = 0; mt < 2; mt++) {
            float sum0 = 0.0f, sum1 = 0.0f;
#pragma unroll
            for (int nt = 0; nt < NT; nt++) {
                const int colw = wn + nt * 8 + 2 * t;
                const long long row0 = m0 + wm + mt * 16 + g;
                float e0 = __expf(acc[mt][nt][0] * alpha) * esc;
                float e1 = __expf(acc[mt][nt][1] * alpha) * esc;
                float e2 = __expf(acc[mt][nt][2] * alpha) * esc;
                float e3 = __expf(acc[mt][nt][3] * alpha) * esc;
                const long long colg = n0 + colw;
                const long long ch = colg >> 6;
                const int wi = (int)(colg & 63);
                __half2 h01 = __float22half2_rn(make_float2(e0, e1));
                __half2 h23 = __float22half2_rn(make_float2(e2, e3));
                STG_CS_U32(Cpk + row0 * ldCpk + ch * 128 + wi * 2, *(uint32_t*)&h01);
                STG_CS_U32(Cpk + (row0 + 8) * ldCpk + ch * 128 + wi * 2, *(uint32_t*)&h23);
                sum0 += e0 + e1; sum1 += e2 + e3;
            }
            sum0 += __shfl_xor_sync(0xffffffffu, sum0, 1);
            sum0 += __shfl_xor_sync(0xffffffffu, sum0, 2);
            sum1 += __shfl_xor_sync(0xffffffffu, sum1, 1);
            sum1 += __shfl_xor_sync(0xffffffffu, sum1, 2);
            if (t == 0) {
                atomicAdd(&s_aux[wm + mt * 16 + g], sum0);
                atomicAdd(&s_aux[wm + mt * 16 + g + 8], sum1);
            }
        }
        __syncthreads();
        if (tid < 128)
            atomicAdd(&rs[rs_off + m0 + tid], s_aux[tid]);
    } else if (MODE == 1) {
#pragma unroll
        for (int mt = 0; mt < 2; mt++) {
#pragma unroll
            for (int nt = 0; nt < NT; nt++) {
                const int colw = wn + nt * 8 + 2 * t;
                const long long row0 = m0 + wm + mt * 16 + g;
                const float b0 = s_bias[colw], b1 = s_bias[colw + 1];
                const long long colg = n0 + colw;
                const long long ch = colg >> 5;
                const int wi = (int)(colg & 31);
                pack_store2(Cpk + row0 * ldCpk + ch * 128 + wi * 2,
                            acc[mt][nt][0] + b0, acc[mt][nt][1] + b1);
                pack_store2(Cpk + (row0 + 8) * ldCpk + ch * 128 + wi * 2,
                            acc[mt][nt][2] + b0, acc[mt][nt][3] + b1);
            }
        }
    } else {
#pragma unroll
        for (int mt = 0; mt < 2; mt++) {
#pragma unroll
            for (int nt = 0; nt < NT; nt++) {
                const int colw = wn + nt * 8 + 2 * t;
                const float b0 = s_bias[colw], b1 = s_bias[colw + 1];
                const long long row0 = m0 + wm + mt * 16 + g;
                *(float2*)(Cf + row0 * (long long)ldc + n0 + colw) =
                    make_float2(acc[mt][nt][0] + b0, acc[mt][nt][1] + b1);
                *(float2*)(Cf + (row0 + 8) * (long long)ldc + n0 + colw) =
                    make_float2(acc[mt][nt][2] + b0, acc[mt][nt][3] + b1);
            }
        }
    }
}

// ---------------------------------------------------------------------------
// Plain fp16 GEMM (single pass): C[128 x TN] = A_plain @ B_plain^T + bias.
// ---------------------------------------------------------------------------
template<int TN>
__global__ void __launch_bounds__(256, 2)
plain_gemm(const uint8_t* __restrict__ Apl, const uint8_t* __restrict__ Bpl,
           const float* __restrict__ bias, float* __restrict__ Cf,
           int nchunks, long long ldA, long long ldB, int ldc)
{
    constexpr int NT = TN / 16;
    constexpr int NB = TN / 32;
    constexpr int STAGE = 16384 + TN * 128;

    extern __shared__ uint8_t dyn_raw[];
    __shared__ float s_bias[TN];

    const int tid = threadIdx.x, wid = tid >> 5, lane = tid & 31;
    const long long m0 = (long long)blockIdx.y * 128;
    const long long n0 = (long long)blockIdx.x * TN;

    uint32_t raw = smem_u32(dyn_raw);
    uint32_t base = (raw + 1023u) & ~1023u;
    const uint32_t aSu[2] = { base, base + STAGE };
    const uint32_t bSu[2] = { base + 16384, base + STAGE + 16384 };

    for (int i = tid; i < TN; i += 256) s_bias[i] = bias ? bias[n0 + i] : 0.0f;

    float acc[2][NT][4];
#pragma unroll
    for (int i = 0; i < 2; i++)
#pragma unroll
        for (int j = 0; j < NT; j++)
#pragma unroll
            for (int e = 0; e < 4; e++) acc[i][j][e] = 0.0f;

    const uint32_t a_row = (uint32_t)((lane & 7) + (lane & 8));
    const uint32_t a_kof = (uint32_t)(((lane >> 4) & 1) * 16);
    const uint32_t b_row = (uint32_t)((lane & 7) + ((lane >> 4) & 1) * 8);
    const uint32_t b_kof = (uint32_t)(((lane >> 3) & 1) * 16);
    const int wm = (wid & 3) * 32;
    const int wn = (wid >> 2) * (TN / 2);

    auto prefetch = [&](int s, int c) {
#pragma unroll
        for (int i = 0; i < 4; i++) {
            const int idx = i * 256 + tid, row = idx >> 3, g = idx & 7;
            cpa16(aSu[s] + sw128((uint32_t)(row * 128 + g * 16)),
                  Apl + (m0 + row) * ldA + c * 128 + g * 16);
        }
#pragma unroll
        for (int i = 0; i < NB; i++) {
            const int idx = i * 256 + tid, row = idx >> 3, g = idx & 7;
            cpa16(bSu[s] + sw128((uint32_t)(row * 128 + g * 16)),
                  Bpl + (n0 + row) * ldB + c * 128 + g * 16);
        }
        CP_COMMIT();
    };

    prefetch(0, 0);
    int cur = 0;
    for (int c = 0; c < nchunks; c++) {
        if (c + 1 < nchunks) { prefetch(cur ^ 1, c + 1); CP_WAIT1(); }
        else                 { CP_WAIT0(); }
        __syncthreads();

        const uint32_t aS = aSu[cur], bS = bSu[cur];
#pragma unroll
        for (int ks = 0; ks < 4; ks++) {
            uint32_t ah[2][4], bf[NT][2];
#pragma unroll
            for (int mt = 0; mt < 2; mt++) {
                uint32_t off = (uint32_t)(wm + mt * 16 + a_row) * 128 + ks * 32 + a_kof;
                LDSM_X4(ah[mt][0], ah[mt][1], ah[mt][2], ah[mt][3], aS + sw128(off));
            }
#pragma unroll
            for (int p = 0; p < NT / 2; p++) {
                uint32_t r0, r1, r2, r3;
                uint32_t off = (uint32_t)(wn + p * 16 + b_row) * 128 + ks * 32 + b_kof;
                LDSM_X4(r0, r1, r2, r3, bS + sw128(off));
                bf[2 * p][0] = r0; bf[2 * p][1] = r1;
                bf[2 * p + 1][0] = r2; bf[2 * p + 1][1] = r3;
            }
#pragma unroll
            for (int mt = 0; mt < 2; mt++)
#pragma unroll
                for (int nt = 0; nt < NT; nt++)
                    mma16816(acc[mt][nt], ah[mt], bf[nt]);
        }
        __syncthreads();
        cur ^= 1;
    }

    const int g = lane >> 2, t = lane & 3;
#pragma unroll
    for (int mt = 0; mt < 2; mt++) {
#pragma unroll
        for (int nt = 0; nt < NT; nt++) {
            const int colw = wn + nt * 8 + 2 * t;
            const float b0 = s_bias[colw], b1 = s_bias[colw + 1];
            const long long row0 = m0 + wm + mt * 16 + g;
            *(float2*)(Cf + row0 * (long long)ldc + n0 + colw) =
                make_float2(acc[mt][nt][0] + b0, acc[mt][nt][1] + b1);
            *(float2*)(Cf + (row0 + 8) * (long long)ldc + n0 + colw) =
                make_float2(acc[mt][nt][2] + b0, acc[mt][nt][3] + b1);
        }
    }
}

// ---------------------------------------------------------------------------
// PV plain-fp16 GEMM + normalized fp32 attn write (streaming) + plain-fp16 O.
// ---------------------------------------------------------------------------
__global__ void __launch_bounds__(256, 2)
pv_plain(const uint8_t* __restrict__ expP, const uint8_t* __restrict__ vT,
         float* __restrict__ attn, uint8_t* __restrict__ oapl,
         const float* __restrict__ rs)
{
    extern __shared__ uint8_t dyn_raw[];
    __shared__ float s_aux[128];

    const int tid = threadIdx.x, wid = tid >> 5, lane = tid & 31;
    const int qb = blockIdx.x;
    const int z = blockIdx.y;
    const int b = z >> 4, h = z & 15;
    const long long m0 = (long long)qb * 128;

    const uint8_t* P = expP + ((long long)(h * B_ + b) * L_ + m0) * 4096;
    const uint8_t* Vt = vT + (long long)z * 64 * 4096;
    float* Pf = attn + ((long long)(h * B_ + b) * L_ + m0) * L_;
    uint8_t* Oa = oapl + ((long long)b * L_ + m0) * 2048 + h * 128;
    const float* rsb = rs + (long long)(h * B_ + b) * L_ + m0;

    uint32_t raw = smem_u32(dyn_raw);
    uint32_t base = (raw + 1023u) & ~1023u;
    uint8_t* dsm = dyn_raw + (base - raw);
    const int STAGE = 16384 + 8192;
    uint8_t* smA[2] = { dsm, dsm + STAGE };
    const uint32_t aSu[2] = { base, base + STAGE };
    const uint32_t bSu[2] = { base + 16384, base + STAGE + 16384 };

    if (tid < 128) s_aux[tid] = 1.0f / rsb[tid];
    __syncthreads();

    float acc[2][4][4];
#pragma unroll
    for (int i = 0; i < 2; i++)
#pragma unroll
        for (int j = 0; j < 4; j++)
#pragma unroll
            for (int e = 0; e < 4; e++) acc[i][j][e] = 0.0f;

    const uint32_t a_row = (uint32_t)((lane & 7) + (lane & 8));
    const uint32_t a_kof = (uint32_t)(((lane >> 4) & 1) * 16);
    const uint32_t b_row = (uint32_t)((lane & 7) + ((lane >> 4) & 1) * 8);
    const uint32_t b_kof = (uint32_t)(((lane >> 3) & 1) * 16);
    const int wm = (wid & 3) * 32;
    const int wn = (wid >> 2) * 32;

    auto prefetch = [&](int s, int c) {
#pragma unroll
        for (int i = 0; i < 4; i++) {
            const int idx = i * 256 + tid, row = idx >> 3, g = idx & 7;
            cpa16(aSu[s] + sw128((uint32_t)(row * 128 + g * 16)),
                  P + (long long)row * 4096 + c * 128 + g * 16);
        }
#pragma unroll
        for (int i = 0; i < 2; i++) {
            const int idx = i * 256 + tid, row = idx >> 3, g = idx & 7;
            cpa16(bSu[s] + sw128((uint32_t)(row * 128 + g * 16)),
                  Vt + (long long)row * 4096 + c * 128 + g * 16);
        }
        CP_COMMIT();
    };

    prefetch(0, 0);
    int cur = 0;
    for (int c = 0; c < 32; c++) {
        if (c + 1 < 32) { prefetch(cur ^ 1, c + 1); CP_WAIT1(); }
        else            { CP_WAIT0(); }
        __syncthreads();

        // normalized fp32 P write (required output), streaming stores
        {
            const int r = tid >> 1, hh = tid & 1;
            const uint8_t* sa = smA[cur];
            const float inv = s_aux[r];
            float* dst = Pf + (long long)r * L_ + c * 64 + hh * 32;
#pragma unroll
            for (int j = 0; j < 4; j++) {
                uint4 u = *(const uint4*)(sa + sw128((uint32_t)(r * 128 + hh * 64 + j * 16)));
                const uint32_t w[4] = { u.x, u.y, u.z, u.w };
                float o[8];
#pragma unroll
                for (int jj = 0; jj < 4; jj++) {
                    __half2 hb = *(const __half2*)&w[jj];
                    float2 f = __half22float2(hb);
                    o[2 * jj] = f.x * inv;
                    o[2 * jj + 1] = f.y * inv;
                }
                float4 v0 = make_float4(o[0], o[1], o[2], o[3]);
                float4 v1 = make_float4(o[4], o[5], o[6], o[7]);
                STG_CS_F4(dst + j * 8, v0);
                STG_CS_F4(dst + j * 8 + 4, v1);
            }
        }

        const uint32_t aS = aSu[cur], bS = bSu[cur];
#pragma unroll
        for (int ks = 0; ks < 4; ks++) {
            uint32_t ah[2][4], bf[4][2];
#pragma unroll
            for (int mt = 0; mt < 2; mt++) {
                uint32_t off = (uint32_t)(wm + mt * 16 + a_row) * 128 + ks * 32 + a_kof;
                LDSM_X4(ah[mt][0], ah[mt][1], ah[mt][2], ah[mt][3], aS + sw128(off));
            }
#pragma unroll
            for (int p = 0; p < 2; p++) {
                uint32_t r0, r1, r2, r3;
                uint32_t off = (uint32_t)(wn + p * 16 + b_row) * 128 + ks * 32 + b_kof;
                LDSM_X4(r0, r1, r2, r3, bS + sw128(off));
                bf[2 * p][0] = r0; bf[2 * p][1] = r1;
                bf[2 * p + 1][0] = r2; bf[2 * p + 1][1] = r3;
            }
#pragma unroll
            for (int mt = 0; mt < 2; mt++)
#pragma unroll
                for (int nt = 0; nt < 4; nt++)
                    mma16816(acc[mt][nt], ah[mt], bf[nt]);
        }
        __syncthreads();
        cur ^= 1;
    }

    const int g = lane >> 2, t = lane & 3;
#pragma unroll
    for (int mt = 0; mt < 2; mt++) {
        const float i0 = s_aux[wm + mt * 16 + g];
        const float i1 = s_aux[wm + mt * 16 + g + 8];
#pragma unroll
        for (int nt = 0; nt < 4; nt++) {
            const int colw = wn + nt * 8 + 2 * t;
            const int row0 = wm + mt * 16 + g;
            __half2 h0 = __float22half2_rn(make_float2(acc[mt][nt][0] * i0, acc[mt][nt][1] * i0));
            __half2 h1 = __float22half2_rn(make_float2(acc[mt][nt][2] * i1, acc[mt][nt][3] * i1));
            *(uint32_t*)(Oa + (long long)row0 * 2048 + colw * 2) = *(uint32_t*)&h0;
            *(uint32_t*)(Oa + (long long)(row0 + 8) * 2048 + colw * 2) = *(uint32_t*)&h1;
        }
    }
}

// ---------------------------------------------------------------------------
// V transpose: vh fp32 [B,L,H,DK] -> vT plain fp16 [(b*H+h)][dk][L/64][128B]
// ---------------------------------------------------------------------------
__global__ void __launch_bounds__(256)
transpose_v_pk(const float* __restrict__ vh, uint8_t* __restrict__ vT)
{
    __shared__ float tsm[32][33];
    const int bh = blockIdx.z;
    const int b = bh >> 4, h = bh & 15;
    const int l0 = blockIdx.x * 32;
    const int d0 = blockIdx.y * 32;
    const int tid = threadIdx.x;
    const int tx = tid & 31;
    const int ty = tid >> 5;

    const float* src = vh + ((long long)b * L_ + l0) * HD_ + h * DK_ + d0;
#pragma unroll
    for (int i = 0; i < 32; i += 8)
        tsm[ty + i][tx] = src[(long long)(ty + i) * HD_ + tx];
    __syncthreads();

    const int lp = tid & 15;
#pragma unroll
    for (int it = 0; it < 2; it++) {
        const int d = (tid >> 4) + 16 * it;
        const int lg = l0 + 2 * lp;
        uint8_t* p = vT + ((long long)bh * 64 + d0 + d) * 4096
                        + (lg >> 6) * 128 + (lg & 63) * 2;
        __half2 hv = __float22half2_rn(make_float2(tsm[2 * lp][d], tsm[2 * lp + 1][d]));
        *(uint32_t*)p = *(uint32_t*)&hv;
    }
}

__global__ void zero_rs(float* __restrict__ rs)
{
    rs[blockIdx.x * 256 + threadIdx.x] = 0.0f;
}

// ---------------------------------------------------------------------------
// LayerNorm + residual
// ---------------------------------------------------------------------------
__global__ void __launch_bounds__(256)
ln_residual(const float* __restrict__ x, const float* __restrict__ res,
            const float* __restrict__ gam, const float* __restrict__ bet,
            float* __restrict__ out)
{
    const long long row = blockIdx.x;
    const float4* x4 = (const float4*)(x   + row * D_);
    const float4* r4 = (const float4*)(res + row * D_);
    const int tid = threadIdx.x;

    float4 v = x4[tid];
    float s  = (v.x + v.y) + (v.z + v.w);
    float sq = (v.x * v.x + v.y * v.y) + (v.z * v.z + v.w * v.w);
#pragma unroll
    for (int o = 16; o > 0; o >>= 1) {
        s  += __shfl_xor_sync(0xffffffffu, s,  o);
        sq += __shfl_xor_sync(0xffffffffu, sq, o);
    }
    __shared__ float ss[8], sqs[8];
    if ((tid & 31) == 0) { ss[tid >> 5] = s; sqs[tid >> 5] = sq; }
    __syncthreads();
    s  = (ss[0]  + ss[1])  + (ss[2]  + ss[3])  + (ss[4]  + ss[5])  + (ss[6]  + ss[7]);
    sq = (sqs[0] + sqs[1]) + (sqs[2] + sqs[3]) + (sqs[4] + sqs[5]) + (sqs[6] + sqs[7]);

    const float mean = s * (1.0f / D_);
    float var = sq * (1.0f / D_) - mean * mean;
    var = fmaxf(var, 0.0f);
    const float rstd = rsqrtf(var + LN_EPS_);

    float4 g  = ((const float4*)gam)[tid];
    float4 bt = ((const float4*)bet)[tid];
    float4 r  = r4[tid];
    float4 o;
    o.x = (v.x - mean) * rstd * g.x + bt.x + r.x;
    o.y = (v.y - mean) * rstd * g.y + bt.y + r.y;
    o.z = (v.z - mean) * rstd * g.z + bt.z + r.z;
    o.w = (v.w - mean) * rstd * g.w + bt.w + r.w;
    ((float4*)(out + row * D_))[tid] = o;
}

// ---------------------------------------------------------------------------
// Launch
// ---------------------------------------------------------------------------
extern "C" void kernel_launch(void* const* d_in, const int* in_sizes, int n_in,
                              void* d_out, int out_size)
{
    (void)in_sizes; (void)n_in; (void)out_size;
    const float* q  = (const float*)d_in[0];
    const float* k  = (const float*)d_in[1];
    const float* v  = (const float*)d_in[2];
    const float* wq = (const float*)d_in[3];
    const float* bq = (const float*)d_in[4];
    const float* wk = (const float*)d_in[5];
    const float* bk = (const float*)d_in[6];
    const float* wv = (const float*)d_in[7];
    const float* bv = (const float*)d_in[8];
    const float* wo = (const float*)d_in[9];
    const float* bo = (const float*)d_in[10];
    const float* lg = (const float*)d_in[11];
    const float* lb = (const float*)d_in[12];

    float* out  = (float*)d_out;
    float* attn = out + (long long)B_ * L_ * D_;

    uint8_t *qkpk, *vpk, *wqkpk, *wvpk, *wopl, *qkhpk, *vT, *oapl, *expP;
    float *vh, *op, *rs;
    cudaGetSymbolAddress((void**)&qkpk,  g_qkpk);
    cudaGetSymbolAddress((void**)&vpk,   g_vpk);
    cudaGetSymbolAddress((void**)&wqkpk, g_wqkpk);
    cudaGetSymbolAddress((void**)&wvpk,  g_wvpk);
    cudaGetSymbolAddress((void**)&wopl,  g_wopl);
    cudaGetSymbolAddress((void**)&qkhpk, g_qkhpk);
    cudaGetSymbolAddress((void**)&vT,    g_vT);
    cudaGetSymbolAddress((void**)&oapl,  g_oapl);
    cudaGetSymbolAddress((void**)&expP,  g_expP);
    cudaGetSymbolAddress((void**)&vh,    g_vh);
    cudaGetSymbolAddress((void**)&op,    g_op);
    cudaGetSymbolAddress((void**)&rs,    g_rs);

    const long long QKPK_HALF = (long long)MROWS_ * D_ * 4;
    const long long WQK_HALF  = (long long)HD_ * D_ * 4;
    const long long QKH_HALF  = (long long)MROWS_ * HD_ * 4;

    const int SMEM128 = 2 * (16384 + 128 * 128) + 1024;
    const int SMEMPV  = 2 * (16384 + 8192) + 1024;
    cudaFuncSetAttribute((const void*)pk_gemm<128, 0, 1>, cudaFuncAttributeMaxDynamicSharedMemorySize, SMEM128);
    cudaFuncSetAttribute((const void*)pk_gemm<128, 1, 2>, cudaFuncAttributeMaxDynamicSharedMemorySize, SMEM128);
    cudaFuncSetAttribute((const void*)pk_gemm<128, 2, 2>, cudaFuncAttributeMaxDynamicSharedMemorySize, SMEM128);
    cudaFuncSetAttribute((const void*)plain_gemm<128>,    cudaFuncAttributeMaxDynamicSharedMemorySize, SMEM128);
    cudaFuncSetAttribute((const void*)pv_plain,           cudaFuncAttributeMaxDynamicSharedMemorySize, SMEMPV);

    dim3 blk(256);

    zero_rs<<<NROWS_ATTN / 256, blk>>>(rs);

    // pack inputs + weights (q/k into combined buffers)
    pack_split3<<<dim3(MROWS_ * D_ / 4 / 256, 1, 3), blk>>>(
        q, k, v, qkpk, qkpk + QKPK_HALF, vpk, D_);
    pack_split3<<<dim3(HD_ * D_ / 4 / 256, 1, 3), blk>>>(
        wq, wk, wv, wqkpk, wqkpk + WQK_HALF, wvpk, D_);
    pack_plain<<<D_ * HD_ / 4 / 256, blk>>>(wo, wopl);

    const long long ld32 = 32 * 128;

    // Merged Q+K projections (z=0 -> q, z=1 -> k), 2-pass
    dim3 gqk(HD_ / 128, MROWS_ / 128, 2);
    pk_gemm<128, 1, 2><<<gqk, blk, SMEM128>>>(qkpk, wqkpk, bq, bk, nullptr, qkhpk, nullptr,
        32, ld32, ld32, 0, ld32, 1,
        QKPK_HALF, 0, WQK_HALF, 0, 0, 0, QKH_HALF, 0, 0, 0, 1.0f);

    // V projection, 1-pass, fp32 out
    dim3 gproj(HD_ / 128, MROWS_ / 128, 1);
    pk_gemm<128, 0, 1><<<gproj, blk, SMEM128>>>(vpk, wvpk, bv, nullptr, vh, nullptr, nullptr,
        32, ld32, ld32, HD_, 0, 1,
        0, 0, 0, 0, 0, 0, 0, 0, 0, 0, 1.0f);

    transpose_v_pk<<<dim3(L_ / 32, DK_ / 32, B_ * H_), blk>>>(vh, vT);

    // Scores (K=64 -> 2 chunks), 2-pass, plain fp16 expP (streaming) + rowsums
    dim3 gsc(L_ / 128, L_ / 128, B_ * H_);
    pk_gemm<128, 2, 2><<<gsc, blk, SMEM128>>>(qkhpk, qkhpk + QKH_HALF, nullptr, nullptr,
        nullptr, expP, rs,
        2, ld32, ld32, 0, (long long)L_ * 2, H_,
        (long long)L_ * ld32, 256,
        (long long)L_ * ld32, 256,
        0, 0,
        (long long)L_ * L_ * 2, (long long)B_ * L_ * L_ * 2,
        (long long)L_, (long long)B_ * L_,
        0.125f);

    // PV single-pass plain fp16; writes fp32 attn (streaming) + plain-fp16 oa
    pv_plain<<<dim3(L_ / 128, B_ * H_, 1), blk, SMEMPV>>>(expP, vT, attn, oapl, rs);

    // Output projection: plain fp16 single-pass
    dim3 gop(D_ / 128, MROWS_ / 128, 1);
    plain_gemm<128><<<gop, blk, SMEM128>>>(oapl, wopl, bo, op, 16, 2048, 2048, D_);

    // LayerNorm + residual
    ln_residual<<<MROWS_, blk>>>(op, q, lg, lb, out);
}

// round 16
// speedup vs baseline: 1.5811x; 1.0054x over previous
#include <cuda_runtime.h>
#include <cuda_fp16.h>
#include <stdint.h>

#define B_   4
#define L_   2048
#define D_   1024
#define H_   16
#define DK_  64
#define HD_  1024
#define MROWS_ 8192
#define LN_EPS_ 1e-5f
#define NROWS_ATTN (B_ * H_ * L_)

// ---------------------------------------------------------------------------
// Scratch. Packed split-fp16: [M][K/32][32 hi | 32 lo] 128B chunks.
// Plain fp16: [M][K/64][64 fp16] 128B chunks.
// ---------------------------------------------------------------------------
__device__ __align__(256) uint8_t g_qkpk [2ll * MROWS_ * D_ * 4];
__device__ __align__(256) uint8_t g_vpk  [(long long)MROWS_ * D_ * 4];
__device__ __align__(256) uint8_t g_wqkpk[2ll * HD_ * D_ * 4];
__device__ __align__(256) uint8_t g_wvpk [(long long)HD_ * D_ * 4];
__device__ __align__(256) uint8_t g_wopl [(long long)D_ * HD_ * 2];
__device__ __align__(256) uint8_t g_qkhpk[2ll * MROWS_ * HD_ * 4];
__device__ __align__(256) uint8_t g_vT   [(long long)B_ * H_ * DK_ * L_ * 2];
__device__ __align__(256) uint8_t g_oapl [(long long)MROWS_ * HD_ * 2];
__device__ __align__(256) uint8_t g_expP [(long long)B_ * H_ * L_ * L_ * 2];
__device__ float g_op[MROWS_ * HD_];
__device__ float g_rs[NROWS_ATTN];

// ---------------------------------------------------------------------------
// helpers
// ---------------------------------------------------------------------------
__device__ __forceinline__ uint32_t smem_u32(const void* p) {
    uint32_t a;
    asm("{ .reg .u64 t; cvta.to.shared.u64 t, %1; cvt.u32.u64 %0, t; }" : "=r"(a) : "l"(p));
    return a;
}
__device__ __forceinline__ uint32_t sw128(uint32_t off) {
    return off ^ ((off >> 3) & 0x70);
}
__device__ __forceinline__ void cpa16(uint32_t dst, const void* src) {
    asm volatile("cp.async.cg.shared.global [%0], [%1], 16;" :: "r"(dst), "l"(src));
}
#define CP_COMMIT() asm volatile("cp.async.commit_group;" ::: "memory")
#define CP_WAIT0()  asm volatile("cp.async.wait_group 0;" ::: "memory")
#define CP_WAIT1()  asm volatile("cp.async.wait_group 1;" ::: "memory")
#define LDSM_X4(r0, r1, r2, r3, addr)                                      \
    asm volatile("ldmatrix.sync.aligned.m8n8.x4.shared.b16 "               \
                 "{%0,%1,%2,%3}, [%4];"                                    \
                 : "=r"(r0), "=r"(r1), "=r"(r2), "=r"(r3) : "r"(addr))
#define STG_CS_F4(addr, v)                                                 \
    asm volatile("st.global.cs.v4.f32 [%0], {%1,%2,%3,%4};"                \
                 :: "l"(addr), "f"((v).x), "f"((v).y), "f"((v).z), "f"((v).w) : "memory")
#define STG_CS_U32(addr, v)                                                \
    asm volatile("st.global.cs.b32 [%0], %1;" :: "l"(addr), "r"(v) : "memory")

__device__ __forceinline__ void mma16816(float* d, const uint32_t* a, const uint32_t* b) {
    asm volatile(
        "mma.sync.aligned.m16n8k16.row.col.f32.f16.f16.f32 "
        "{%0,%1,%2,%3}, {%4,%5,%6,%7}, {%8,%9}, {%0,%1,%2,%3};"
        : "+f"(d[0]), "+f"(d[1]), "+f"(d[2]), "+f"(d[3])
        : "r"(a[0]), "r"(a[1]), "r"(a[2]), "r"(a[3]), "r"(b[0]), "r"(b[1]));
}

__device__ __forceinline__ void pack_store2(uint8_t* p, float v0, float v1) {
    __half2 h = __float22half2_rn(make_float2(v0, v1));
    float2 f = __half22float2(h);
    __half2 l = __float22half2_rn(make_float2(v0 - f.x, v1 - f.y));
    *(uint32_t*)p = *(uint32_t*)&h;
    *(uint32_t*)(p + 64) = *(uint32_t*)&l;
}
__device__ __forceinline__ void pack_store4(uint8_t* p, float4 v) {
    __half2 h0 = __float22half2_rn(make_float2(v.x, v.y));
    __half2 h1 = __float22half2_rn(make_float2(v.z, v.w));
    float2 f0 = __half22float2(h0), f1 = __half22float2(h1);
    __half2 l0 = __float22half2_rn(make_float2(v.x - f0.x, v.y - f0.y));
    __half2 l1 = __float22half2_rn(make_float2(v.z - f1.x, v.w - f1.y));
    uint2 hu, lu;
    hu.x = *(uint32_t*)&h0; hu.y = *(uint32_t*)&h1;
    lu.x = *(uint32_t*)&l0; lu.y = *(uint32_t*)&l1;
    *(uint2*)p = hu;
    *(uint2*)(p + 64) = lu;
}

// ---------------------------------------------------------------------------
// pack fp32 [M,K] -> packed split fp16 ; batched over 3 tensors via blockIdx.z
// ---------------------------------------------------------------------------
__global__ void __launch_bounds__(256)
pack_split3(const float* __restrict__ s0, const float* __restrict__ s1,
            const float* __restrict__ s2,
            uint8_t* __restrict__ d0, uint8_t* __restrict__ d1,
            uint8_t* __restrict__ d2, int K)
{
    const float* src = (blockIdx.z == 0) ? s0 : (blockIdx.z == 1) ? s1 : s2;
    uint8_t* dst = (blockIdx.z == 0) ? d0 : (blockIdx.z == 1) ? d1 : d2;
    const long long idx = (long long)blockIdx.x * 256 + threadIdx.x;
    const int perRow = K >> 2;
    const long long m = idx / perRow;
    const int j = (int)(idx - m * perRow);
    float4 v = *(const float4*)(src + m * K + j * 4);
    const int e0 = j * 4;
    uint8_t* p = dst + (m * (K >> 5) + (e0 >> 5)) * 128 + (e0 & 31) * 2;
    pack_store4(p, v);
}
__global__ void __launch_bounds__(256)
pack_plain(const float* __restrict__ src, uint8_t* __restrict__ dst)
{
    const long long idx = (long long)blockIdx.x * 256 + threadIdx.x;
    float4 v = *(const float4*)(src + idx * 4);
    __half2 h0 = __float22half2_rn(make_float2(v.x, v.y));
    __half2 h1 = __float22half2_rn(make_float2(v.z, v.w));
    uint2 u; u.x = *(uint32_t*)&h0; u.y = *(uint32_t*)&h1;
    *(uint2*)(dst + idx * 8) = u;
}

// ---------------------------------------------------------------------------
// Packed split-fp16 GEMM. CTA tile 128 x TN, 32-K chunks, 8 warps 4x2,
// 2 CTAs/SM. AP=2: hh + lh (B-lo dropped). AP=1: hh only.
// MODE 0: C fp32 + bias.  MODE 1: C packed-split + bias (bias2 for zo==1).
// MODE 2: exp(alpha*acc)*2^-4 -> PLAIN fp16 (streaming) + rowsum atomics.
// MODE 4: v-proj: epilogue smem-transposes tile -> vT plain fp16 (coalesced).
// ---------------------------------------------------------------------------
template<int TN, int MODE, int AP>
__global__ void __launch_bounds__(256, 2)
pk_gemm(const uint8_t* Apk, const uint8_t* Bpk,
        const float* __restrict__ bias, const float* __restrict__ bias2,
        float* Cf, uint8_t* Cpk, float* rs,
        int nchunks, long long ldA, long long ldB, int ldc, long long ldCpk,
        int zdiv,
        long long sAo, long long sAi, long long sBo, long long sBi,
        long long sCfO, long long sCfI, long long sCpO, long long sCpI,
        long long rsO, long long rsI, float alpha)
{
    constexpr int NT = TN / 16;
    constexpr int NBL = TN / 64;
    constexpr int STAGE = 16384 + TN * 128;

    extern __shared__ uint8_t dyn_raw[];
    __shared__ float s_bias[TN];
    __shared__ float s_aux[128];

    const int tid = threadIdx.x, wid = tid >> 5, lane = tid & 31;
    const int z = blockIdx.z, zo = z / zdiv, zi = z - zo * zdiv;
    Apk += zo * sAo + zi * sAi;
    Bpk += zo * sBo + zi * sBi;
    if (MODE == 0) Cf += zo * sCfO + zi * sCfI;
    if (MODE != 0) Cpk += zo * sCpO + zi * sCpI;
    const long long rs_off = zo * rsO + zi * rsI;

    const long long m0 = (long long)blockIdx.y * 128;
    const long long n0 = (long long)blockIdx.x * TN;

    uint32_t raw = smem_u32(dyn_raw);
    uint32_t base = (raw + 1023u) & ~1023u;
    uint8_t* dsm = dyn_raw + (base - raw);
    const uint32_t aSu[2] = { base, base + STAGE };
    const uint32_t bSu[2] = { base + 16384, base + STAGE + 16384 };

    if (MODE == 0 || MODE == 1 || MODE == 4) {
        const float* bp = (zo == 1 && bias2) ? bias2 : bias;
        for (int i = tid; i < TN; i += 256) s_bias[i] = bp ? bp[n0 + i] : 0.0f;
    }
    if (MODE == 2) { if (tid < 128) s_aux[tid] = 0.0f; }

    float acc[2][NT][4];
#pragma unroll
    for (int i = 0; i < 2; i++)
#pragma unroll
        for (int j = 0; j < NT; j++)
#pragma unroll
            for (int e = 0; e < 4; e++) acc[i][j][e] = 0.0f;

    const uint32_t a_row = (uint32_t)((lane & 7) + (lane & 8));
    const uint32_t a_kof = (uint32_t)(((lane >> 4) & 1) * 16);
    const uint32_t b_row = (uint32_t)((lane & 7) + ((lane >> 4) & 1) * 8);
    const uint32_t b_kof = (uint32_t)(((lane >> 3) & 1) * 16);
    const int wm = (wid & 3) * 32;
    const int wn = (wid >> 2) * (TN / 2);

    auto prefetch = [&](int s, int c) {
        const uint8_t* Ab = Apk + (long long)c * 128;
        if (AP == 2) {
#pragma unroll
            for (int i = 0; i < 4; i++) {
                const int idx = i * 256 + tid, row = idx >> 3, g = idx & 7;
                cpa16(aSu[s] + sw128((uint32_t)(row * 128 + g * 16)),
                      Ab + (m0 + row) * ldA + g * 16);
            }
        } else {
#pragma unroll
            for (int i = 0; i < 2; i++) {
                const int idx = i * 256 + tid, row = idx >> 2, g = idx & 3;
                cpa16(aSu[s] + sw128((uint32_t)(row * 128 + g * 16)),
                      Ab + (m0 + row) * ldA + g * 16);
            }
        }
        const uint8_t* Bb = Bpk + (long long)c * 128;
#pragma unroll
        for (int i = 0; i < NBL; i++) {
            const int idx = i * 256 + tid, row = idx >> 2, g = idx & 3;
            cpa16(bSu[s] + sw128((uint32_t)(row * 128 + g * 16)),
                  Bb + (n0 + row) * ldB + g * 16);
        }
        CP_COMMIT();
    };

    prefetch(0, 0);
    int cur = 0;
    for (int c = 0; c < nchunks; c++) {
        if (c + 1 < nchunks) {
            prefetch(cur ^ 1, c + 1);
            CP_WAIT1();
        } else {
            CP_WAIT0();
        }
        __syncthreads();

        const uint32_t aS = aSu[cur], bS = bSu[cur];
#pragma unroll
        for (int ks = 0; ks < 2; ks++) {
            uint32_t ah[2][4], al[2][4], bf[NT][2];
#pragma unroll
            for (int mt = 0; mt < 2; mt++) {
                uint32_t off = (uint32_t)(wm + mt * 16 + a_row) * 128 + ks * 32 + a_kof;
                LDSM_X4(ah[mt][0], ah[mt][1], ah[mt][2], ah[mt][3], aS + sw128(off));
            }
#pragma unroll
            for (int p = 0; p < NT / 2; p++) {
                uint32_t r0, r1, r2, r3;
                uint32_t off = (uint32_t)(wn + p * 16 + b_row) * 128 + ks * 32 + b_kof;
                LDSM_X4(r0, r1, r2, r3, bS + sw128(off));
                bf[2 * p][0] = r0; bf[2 * p][1] = r1;
                bf[2 * p + 1][0] = r2; bf[2 * p + 1][1] = r3;
            }
#pragma unroll
            for (int mt = 0; mt < 2; mt++)
#pragma unroll
                for (int nt = 0; nt < NT; nt++)
                    mma16816(acc[mt][nt], ah[mt], bf[nt]);
            if (AP == 2) {
#pragma unroll
                for (int mt = 0; mt < 2; mt++) {
                    uint32_t off = (uint32_t)(wm + mt * 16 + a_row) * 128 + 64 + ks * 32 + a_kof;
                    LDSM_X4(al[mt][0], al[mt][1], al[mt][2], al[mt][3], aS + sw128(off));
                }
#pragma unroll
                for (int mt = 0; mt < 2; mt++)
#pragma unroll
                    for (int nt = 0; nt < NT; nt++)
                        mma16816(acc[mt][nt], al[mt], bf[nt]);
            }
        }
        __syncthreads();
        cur ^= 1;
    }

    // ---- epilogue ----
    const int g = lane >> 2, t = lane & 3;
    if (MODE == 2) {
        const float esc = 0.0625f;
#pragma unroll
        for (int mt = 0; mt < 2; mt++) {
            float sum0 = 0.0f, sum1 = 0.0f;
#pragma unroll
            for (int nt = 0; nt < NT; nt++) {
                const int colw = wn + nt * 8 + 2 * t;
                const long long row0 = m0 + wm + mt * 16 + g;
                float e0 = __expf(acc[mt][nt][0] * alpha) * esc;
                float e1 = __expf(acc[mt][nt][1] * alpha) * esc;
                float e2 = __expf(acc[mt][nt][2] * alpha) * esc;
                float e3 = __expf(acc[mt][nt][3] * alpha) * esc;
                const long long colg = n0 + colw;
                const long long ch = colg >> 6;
                const int wi = (int)(colg & 63);
                __half2 h01 = __float22half2_rn(make_float2(e0, e1));
                __half2 h23 = __float22half2_rn(make_float2(e2, e3));
                STG_CS_U32(Cpk + row0 * ldCpk + ch * 128 + wi * 2, *(uint32_t*)&h01);
                STG_CS_U32(Cpk + (row0 + 8) * ldCpk + ch * 128 + wi * 2, *(uint32_t*)&h23);
                sum0 += e0 + e1; sum1 += e2 + e3;
            }
            sum0 += __shfl_xor_sync(0xffffffffu, sum0, 1);
            sum0 += __shfl_xor_sync(0xffffffffu, sum0, 2);
            sum1 += __shfl_xor_sync(0xffffffffu, sum1, 1);
            sum1 += __shfl_xor_sync(0xffffffffu, sum1, 2);
            if (t == 0) {
                atomicAdd(&s_aux[wm + mt * 16 + g], sum0);
                atomicAdd(&s_aux[wm + mt * 16 + g + 8], sum1);
            }
        }
        __syncthreads();
        if (tid < 128)
            atomicAdd(&rs[rs_off + m0 + tid], s_aux[tid]);
    } else if (MODE == 4) {
        // smem-transposed staging: tbuf[col][row] fp16, pitch 136 halfs (272B)
        __half* tb = (__half*)dsm;
        constexpr int PH = 136;
#pragma unroll
        for (int mt = 0; mt < 2; mt++) {
#pragma unroll
            for (int nt = 0; nt < NT; nt++) {
                const int colw = wn + nt * 8 + 2 * t;
                const int r0 = wm + mt * 16 + g;
                const float b0 = s_bias[colw], b1 = s_bias[colw + 1];
                tb[(colw)     * PH + r0]     = __float2half_rn(acc[mt][nt][0] + b0);
                tb[(colw + 1) * PH + r0]     = __float2half_rn(acc[mt][nt][1] + b1);
                tb[(colw)     * PH + r0 + 8] = __float2half_rn(acc[mt][nt][2] + b0);
                tb[(colw + 1) * PH + r0 + 8] = __float2half_rn(acc[mt][nt][3] + b1);
            }
        }
        __syncthreads();
        const int bidx = (int)(m0 / L_);
        const int m0g = (int)(m0 - (long long)bidx * L_);
#pragma unroll
        for (int it = 0; it < TN / 16; it++) {
            const int chunk = it * 256 + tid;      // TN*16 chunks of 16B
            const int cg = chunk >> 4, lc = chunk & 15;
            const int colg = (int)n0 + cg;
            const int hh = colg >> 6, dk = colg & 63;
            uint4 v = *(const uint4*)(tb + cg * PH + lc * 8);
            *(uint4*)(Cpk + ((long long)((bidx * H_ + hh) * DK_ + dk)) * 4096
                           + (m0g + lc * 8) * 2) = v;
        }
    } else if (MODE == 1) {
#pragma unroll
        for (int mt = 0; mt < 2; mt++) {
#pragma unroll
            for (int nt = 0; nt < NT; nt++) {
                const int colw = wn + nt * 8 + 2 * t;
                const long long row0 = m0 + wm + mt * 16 + g;
                const float b0 = s_bias[colw], b1 = s_bias[colw + 1];
                const long long colg = n0 + colw;
                const long long ch = colg >> 5;
                const int wi = (int)(colg & 31);
                pack_store2(Cpk + row0 * ldCpk + ch * 128 + wi * 2,
                            acc[mt][nt][0] + b0, acc[mt][nt][1] + b1);
                pack_store2(Cpk + (row0 + 8) * ldCpk + ch * 128 + wi * 2,
                            acc[mt][nt][2] + b0, acc[mt][nt][3] + b1);
            }
        }
    } else {
#pragma unroll
        for (int mt = 0; mt < 2; mt++) {
#pragma unroll
            for (int nt = 0; nt < NT; nt++) {
                const int colw = wn + nt * 8 + 2 * t;
                const float b0 = s_bias[colw], b1 = s_bias[colw + 1];
                const long long row0 = m0 + wm + mt * 16 + g;
                *(float2*)(Cf + row0 * (long long)ldc + n0 + colw) =
                    make_float2(acc[mt][nt][0] + b0, acc[mt][nt][1] + b1);
                *(float2*)(Cf + (row0 + 8) * (long long)ldc + n0 + colw) =
                    make_float2(acc[mt][nt][2] + b0, acc[mt][nt][3] + b1);
            }
        }
    }
}

// ---------------------------------------------------------------------------
// Plain fp16 GEMM (single pass): C[128 x TN] = A_plain @ B_plain^T + bias.
// ---------------------------------------------------------------------------
template<int TN>
__global__ void __launch_bounds__(256, 2)
plain_gemm(const uint8_t* __restrict__ Apl, const uint8_t* __restrict__ Bpl,
           const float* __restrict__ bias, float* __restrict__ Cf,
           int nchunks, long long ldA, long long ldB, int ldc)
{
    constexpr int NT = TN / 16;
    constexpr int NB = TN / 32;
    constexpr int STAGE = 16384 + TN * 128;

    extern __shared__ uint8_t dyn_raw[];
    __shared__ float s_bias[TN];

    const int tid = threadIdx.x, wid = tid >> 5, lane = tid & 31;
    const long long m0 = (long long)blockIdx.y * 128;
    const long long n0 = (long long)blockIdx.x * TN;

    uint32_t raw = smem_u32(dyn_raw);
    uint32_t base = (raw + 1023u) & ~1023u;
    const uint32_t aSu[2] = { base, base + STAGE };
    const uint32_t bSu[2] = { base + 16384, base + STAGE + 16384 };

    for (int i = tid; i < TN; i += 256) s_bias[i] = bias ? bias[n0 + i] : 0.0f;

    float acc[2][NT][4];
#pragma unroll
    for (int i = 0; i < 2; i++)
#pragma unroll
        for (int j = 0; j < NT; j++)
#pragma unroll
            for (int e = 0; e < 4; e++) acc[i][j][e] = 0.0f;

    const uint32_t a_row = (uint32_t)((lane & 7) + (lane & 8));
    const uint32_t a_kof = (uint32_t)(((lane >> 4) & 1) * 16);
    const uint32_t b_row = (uint32_t)((lane & 7) + ((lane >> 4) & 1) * 8);
    const uint32_t b_kof = (uint32_t)(((lane >> 3) & 1) * 16);
    const int wm = (wid & 3) * 32;
    const int wn = (wid >> 2) * (TN / 2);

    auto prefetch = [&](int s, int c) {
#pragma unroll
        for (int i = 0; i < 4; i++) {
            const int idx = i * 256 + tid, row = idx >> 3, g = idx & 7;
            cpa16(aSu[s] + sw128((uint32_t)(row * 128 + g * 16)),
                  Apl + (m0 + row) * ldA + c * 128 + g * 16);
        }
#pragma unroll
        for (int i = 0; i < NB; i++) {
            const int idx = i * 256 + tid, row = idx >> 3, g = idx & 7;
            cpa16(bSu[s] + sw128((uint32_t)(row * 128 + g * 16)),
                  Bpl + (n0 + row) * ldB + c * 128 + g * 16);
        }
        CP_COMMIT();
    };

    prefetch(0, 0);
    int cur = 0;
    for (int c = 0; c < nchunks; c++) {
        if (c + 1 < nchunks) { prefetch(cur ^ 1, c + 1); CP_WAIT1(); }
        else                 { CP_WAIT0(); }
        __syncthreads();

        const uint32_t aS = aSu[cur], bS = bSu[cur];
#pragma unroll
        for (int ks = 0; ks < 4; ks++) {
            uint32_t ah[2][4], bf[NT][2];
#pragma unroll
            for (int mt = 0; mt < 2; mt++) {
                uint32_t off = (uint32_t)(wm + mt * 16 + a_row) * 128 + ks * 32 + a_kof;
                LDSM_X4(ah[mt][0], ah[mt][1], ah[mt][2], ah[mt][3], aS + sw128(off));
            }
#pragma unroll
            for (int p = 0; p < NT / 2; p++) {
                uint32_t r0, r1, r2, r3;
                uint32_t off = (uint32_t)(wn + p * 16 + b_row) * 128 + ks * 32 + b_kof;
                LDSM_X4(r0, r1, r2, r3, bS + sw128(off));
                bf[2 * p][0] = r0; bf[2 * p][1] = r1;
                bf[2 * p + 1][0] = r2; bf[2 * p + 1][1] = r3;
            }
#pragma unroll
            for (int mt = 0; mt < 2; mt++)
#pragma unroll
                for (int nt = 0; nt < NT; nt++)
                    mma16816(acc[mt][nt], ah[mt], bf[nt]);
        }
        __syncthreads();
        cur ^= 1;
    }

    const int g = lane >> 2, t = lane & 3;
#pragma unroll
    for (int mt = 0; mt < 2; mt++) {
#pragma unroll
        for (int nt = 0; nt < NT; nt++) {
            const int colw = wn + nt * 8 + 2 * t;
            const float b0 = s_bias[colw], b1 = s_bias[colw + 1];
            const long long row0 = m0 + wm + mt * 16 + g;
            *(float2*)(Cf + row0 * (long long)ldc + n0 + colw) =
                make_float2(acc[mt][nt][0] + b0, acc[mt][nt][1] + b1);
            *(float2*)(Cf + (row0 + 8) * (long long)ldc + n0 + colw) =
                make_float2(acc[mt][nt][2] + b0, acc[mt][nt][3] + b1);
        }
    }
}

// ---------------------------------------------------------------------------
// PV plain-fp16 GEMM + normalized fp32 attn write (streaming) + plain-fp16 O.
// ---------------------------------------------------------------------------
__global__ void __launch_bounds__(256, 2)
pv_plain(const uint8_t* __restrict__ expP, const uint8_t* __restrict__ vT,
         float* __restrict__ attn, uint8_t* __restrict__ oapl,
         const float* __restrict__ rs)
{
    extern __shared__ uint8_t dyn_raw[];
    __shared__ float s_aux[128];

    const int tid = threadIdx.x, wid = tid >> 5, lane = tid & 31;
    const int qb = blockIdx.x;
    const int z = blockIdx.y;
    const int b = z >> 4, h = z & 15;
    const long long m0 = (long long)qb * 128;

    const uint8_t* P = expP + ((long long)(h * B_ + b) * L_ + m0) * 4096;
    const uint8_t* Vt = vT + (long long)z * 64 * 4096;
    float* Pf = attn + ((long long)(h * B_ + b) * L_ + m0) * L_;
    uint8_t* Oa = oapl + ((long long)b * L_ + m0) * 2048 + h * 128;
    const float* rsb = rs + (long long)(h * B_ + b) * L_ + m0;

    uint32_t raw = smem_u32(dyn_raw);
    uint32_t base = (raw + 1023u) & ~1023u;
    uint8_t* dsm = dyn_raw + (base - raw);
    const int STAGE = 16384 + 8192;
    uint8_t* smA[2] = { dsm, dsm + STAGE };
    const uint32_t aSu[2] = { base, base + STAGE };
    const uint32_t bSu[2] = { base + 16384, base + STAGE + 16384 };

    if (tid < 128) s_aux[tid] = 1.0f / rsb[tid];
    __syncthreads();

    float acc[2][4][4];
#pragma unroll
    for (int i = 0; i < 2; i++)
#pragma unroll
        for (int j = 0; j < 4; j++)
#pragma unroll
            for (int e = 0; e < 4; e++) acc[i][j][e] = 0.0f;

    const uint32_t a_row = (uint32_t)((lane & 7) + (lane & 8));
    const uint32_t a_kof = (uint32_t)(((lane >> 4) & 1) * 16);
    const uint32_t b_row = (uint32_t)((lane & 7) + ((lane >> 4) & 1) * 8);
    const uint32_t b_kof = (uint32_t)(((lane >> 3) & 1) * 16);
    const int wm = (wid & 3) * 32;
    const int wn = (wid >> 2) * 32;

    auto prefetch = [&](int s, int c) {
#pragma unroll
        for (int i = 0; i < 4; i++) {
            const int idx = i * 256 + tid, row = idx >> 3, g = idx & 7;
            cpa16(aSu[s] + sw128((uint32_t)(row * 128 + g * 16)),
                  P + (long long)row * 4096 + c * 128 + g * 16);
        }
#pragma unroll
        for (int i = 0; i < 2; i++) {
            const int idx = i * 256 + tid, row = idx >> 3, g = idx & 7;
            cpa16(bSu[s] + sw128((uint32_t)(row * 128 + g * 16)),
                  Vt + (long long)row * 4096 + c * 128 + g * 16);
        }
        CP_COMMIT();
    };

    prefetch(0, 0);
    int cur = 0;
    for (int c = 0; c < 32; c++) {
        if (c + 1 < 32) { prefetch(cur ^ 1, c + 1); CP_WAIT1(); }
        else            { CP_WAIT0(); }
        __syncthreads();

        // normalized fp32 P write (required output), streaming stores
        {
            const int r = tid >> 1, hh = tid & 1;
            const uint8_t* sa = smA[cur];
            const float inv = s_aux[r];
            float* dst = Pf + (long long)r * L_ + c * 64 + hh * 32;
#pragma unroll
            for (int j = 0; j < 4; j++) {
                uint4 u = *(const uint4*)(sa + sw128((uint32_t)(r * 128 + hh * 64 + j * 16)));
                const uint32_t w[4] = { u.x, u.y, u.z, u.w };
                float o[8];
#pragma unroll
                for (int jj = 0; jj < 4; jj++) {
                    __half2 hb = *(const __half2*)&w[jj];
                    float2 f = __half22float2(hb);
                    o[2 * jj] = f.x * inv;
                    o[2 * jj + 1] = f.y * inv;
                }
                float4 v0 = make_float4(o[0], o[1], o[2], o[3]);
                float4 v1 = make_float4(o[4], o[5], o[6], o[7]);
                STG_CS_F4(dst + j * 8, v0);
                STG_CS_F4(dst + j * 8 + 4, v1);
            }
        }

        const uint32_t aS = aSu[cur], bS = bSu[cur];
#pragma unroll
        for (int ks = 0; ks < 4; ks++) {
            uint32_t ah[2][4], bf[4][2];
#pragma unroll
            for (int mt = 0; mt < 2; mt++) {
                uint32_t off = (uint32_t)(wm + mt * 16 + a_row) * 128 + ks * 32 + a_kof;
                LDSM_X4(ah[mt][0], ah[mt][1], ah[mt][2], ah[mt][3], aS + sw128(off));
            }
#pragma unroll
            for (int p = 0; p < 2; p++) {
                uint32_t r0, r1, r2, r3;
                uint32_t off = (uint32_t)(wn + p * 16 + b_row) * 128 + ks * 32 + b_kof;
                LDSM_X4(r0, r1, r2, r3, bS + sw128(off));
                bf[2 * p][0] = r0; bf[2 * p][1] = r1;
                bf[2 * p + 1][0] = r2; bf[2 * p + 1][1] = r3;
            }
#pragma unroll
            for (int mt = 0; mt < 2; mt++)
#pragma unroll
                for (int nt = 0; nt < 4; nt++)
                    mma16816(acc[mt][nt], ah[mt], bf[nt]);
        }
        __syncthreads();
        cur ^= 1;
    }

    const int g = lane >> 2, t = lane & 3;
#pragma unroll
    for (int mt = 0; mt < 2; mt++) {
        const float i0 = s_aux[wm + mt * 16 + g];
        const float i1 = s_aux[wm + mt * 16 + g + 8];
#pragma unroll
        for (int nt = 0; nt < 4; nt++) {
            const int colw = wn + nt * 8 + 2 * t;
            const int row0 = wm + mt * 16 + g;
            __half2 h0 = __float22half2_rn(make_float2(acc[mt][nt][0] * i0, acc[mt][nt][1] * i0));
            __half2 h1 = __float22half2_rn(make_float2(acc[mt][nt][2] * i1, acc[mt][nt][3] * i1));
            *(uint32_t*)(Oa + (long long)row0 * 2048 + colw * 2) = *(uint32_t*)&h0;
            *(uint32_t*)(Oa + (long long)(row0 + 8) * 2048 + colw * 2) = *(uint32_t*)&h1;
        }
    }
}

__global__ void zero_rs(float* __restrict__ rs)
{
    rs[blockIdx.x * 256 + threadIdx.x] = 0.0f;
}

// ---------------------------------------------------------------------------
// LayerNorm + residual
// ---------------------------------------------------------------------------
__global__ void __launch_bounds__(256)
ln_residual(const float* __restrict__ x, const float* __restrict__ res,
            const float* __restrict__ gam, const float* __restrict__ bet,
            float* __restrict__ out)
{
    const long long row = blockIdx.x;
    const float4* x4 = (const float4*)(x   + row * D_);
    const float4* r4 = (const float4*)(res + row * D_);
    const int tid = threadIdx.x;

    float4 v = x4[tid];
    float s  = (v.x + v.y) + (v.z + v.w);
    float sq = (v.x * v.x + v.y * v.y) + (v.z * v.z + v.w * v.w);
#pragma unroll
    for (int o = 16; o > 0; o >>= 1) {
        s  += __shfl_xor_sync(0xffffffffu, s,  o);
        sq += __shfl_xor_sync(0xffffffffu, sq, o);
    }
    __shared__ float ss[8], sqs[8];
    if ((tid & 31) == 0) { ss[tid >> 5] = s; sqs[tid >> 5] = sq; }
    __syncthreads();
    s  = (ss[0]  + ss[1])  + (ss[2]  + ss[3])  + (ss[4]  + ss[5])  + (ss[6]  + ss[7]);
    sq = (sqs[0] + sqs[1]) + (sqs[2] + sqs[3]) + (sqs[4] + sqs[5]) + (sqs[6] + sqs[7]);

    const float mean = s * (1.0f / D_);
    float var = sq * (1.0f / D_) - mean * mean;
    var = fmaxf(var, 0.0f);
    const float rstd = rsqrtf(var + LN_EPS_);

    float4 g  = ((const float4*)gam)[tid];
    float4 bt = ((const float4*)bet)[tid];
    float4 r  = r4[tid];
    float4 o;
    o.x = (v.x - mean) * rstd * g.x + bt.x + r.x;
    o.y = (v.y - mean) * rstd * g.y + bt.y + r.y;
    o.z = (v.z - mean) * rstd * g.z + bt.z + r.z;
    o.w = (v.w - mean) * rstd * g.w + bt.w + r.w;
    ((float4*)(out + row * D_))[tid] = o;
}

// ---------------------------------------------------------------------------
// Launch
// ---------------------------------------------------------------------------
extern "C" void kernel_launch(void* const* d_in, const int* in_sizes, int n_in,
                              void* d_out, int out_size)
{
    (void)in_sizes; (void)n_in; (void)out_size;
    const float* q  = (const float*)d_in[0];
    const float* k  = (const float*)d_in[1];
    const float* v  = (const float*)d_in[2];
    const float* wq = (const float*)d_in[3];
    const float* bq = (const float*)d_in[4];
    const float* wk = (const float*)d_in[5];
    const float* bk = (const float*)d_in[6];
    const float* wv = (const float*)d_in[7];
    const float* bv = (const float*)d_in[8];
    const float* wo = (const float*)d_in[9];
    const float* bo = (const float*)d_in[10];
    const float* lg = (const float*)d_in[11];
    const float* lb = (const float*)d_in[12];

    float* out  = (float*)d_out;
    float* attn = out + (long long)B_ * L_ * D_;

    uint8_t *qkpk, *vpk, *wqkpk, *wvpk, *wopl, *qkhpk, *vT, *oapl, *expP;
    float *op, *rs;
    cudaGetSymbolAddress((void**)&qkpk,  g_qkpk);
    cudaGetSymbolAddress((void**)&vpk,   g_vpk);
    cudaGetSymbolAddress((void**)&wqkpk, g_wqkpk);
    cudaGetSymbolAddress((void**)&wvpk,  g_wvpk);
    cudaGetSymbolAddress((void**)&wopl,  g_wopl);
    cudaGetSymbolAddress((void**)&qkhpk, g_qkhpk);
    cudaGetSymbolAddress((void**)&vT,    g_vT);
    cudaGetSymbolAddress((void**)&oapl,  g_oapl);
    cudaGetSymbolAddress((void**)&expP,  g_expP);
    cudaGetSymbolAddress((void**)&op,    g_op);
    cudaGetSymbolAddress((void**)&rs,    g_rs);

    const long long QKPK_HALF = (long long)MROWS_ * D_ * 4;
    const long long WQK_HALF  = (long long)HD_ * D_ * 4;
    const long long QKH_HALF  = (long long)MROWS_ * HD_ * 4;

    const int SMEM128 = 2 * (16384 + 128 * 128) + 1024;
    const int SMEMPV  = 2 * (16384 + 8192) + 1024;
    cudaFuncSetAttribute((const void*)pk_gemm<128, 4, 1>, cudaFuncAttributeMaxDynamicSharedMemorySize, SMEM128);
    cudaFuncSetAttribute((const void*)pk_gemm<128, 1, 2>, cudaFuncAttributeMaxDynamicSharedMemorySize, SMEM128);
    cudaFuncSetAttribute((const void*)pk_gemm<128, 2, 2>, cudaFuncAttributeMaxDynamicSharedMemorySize, SMEM128);
    cudaFuncSetAttribute((const void*)plain_gemm<128>,    cudaFuncAttributeMaxDynamicSharedMemorySize, SMEM128);
    cudaFuncSetAttribute((const void*)pv_plain,           cudaFuncAttributeMaxDynamicSharedMemorySize, SMEMPV);

    dim3 blk(256);

    zero_rs<<<NROWS_ATTN / 256, blk>>>(rs);

    // pack inputs + weights (q/k into combined buffers)
    pack_split3<<<dim3(MROWS_ * D_ / 4 / 256, 1, 3), blk>>>(
        q, k, v, qkpk, qkpk + QKPK_HALF, vpk, D_);
    pack_split3<<<dim3(HD_ * D_ / 4 / 256, 1, 3), blk>>>(
        wq, wk, wv, wqkpk, wqkpk + WQK_HALF, wvpk, D_);
    pack_plain<<<D_ * HD_ / 4 / 256, blk>>>(wo, wopl);

    const long long ld32 = 32 * 128;

    // Merged Q+K projections (z=0 -> q, z=1 -> k), 2-pass
    dim3 gqk(HD_ / 128, MROWS_ / 128, 2);
    pk_gemm<128, 1, 2><<<gqk, blk, SMEM128>>>(qkpk, wqkpk, bq, bk, nullptr, qkhpk, nullptr,
        32, ld32, ld32, 0, ld32, 1,
        QKPK_HALF, 0, WQK_HALF, 0, 0, 0, QKH_HALF, 0, 0, 0, 1.0f);

    // V projection, 1-pass, fused transpose -> vT plain fp16
    dim3 gproj(HD_ / 128, MROWS_ / 128, 1);
    pk_gemm<128, 4, 1><<<gproj, blk, SMEM128>>>(vpk, wvpk, bv, nullptr, nullptr, vT, nullptr,
        32, ld32, ld32, 0, 0, 1,
        0, 0, 0, 0, 0, 0, 0, 0, 0, 0, 1.0f);

    // Scores (K=64 -> 2 chunks), 2-pass, plain fp16 expP (streaming) + rowsums
    dim3 gsc(L_ / 128, L_ / 128, B_ * H_);
    pk_gemm<128, 2, 2><<<gsc, blk, SMEM128>>>(qkhpk, qkhpk + QKH_HALF, nullptr, nullptr,
        nullptr, expP, rs,
        2, ld32, ld32, 0, (long long)L_ * 2, H_,
        (long long)L_ * ld32, 256,
        (long long)L_ * ld32, 256,
        0, 0,
        (long long)L_ * L_ * 2, (long long)B_ * L_ * L_ * 2,
        (long long)L_, (long long)B_ * L_,
        0.125f);

    // PV single-pass plain fp16; writes fp32 attn (streaming) + plain-fp16 oa
    pv_plain<<<dim3(L_ / 128, B_ * H_, 1), blk, SMEMPV>>>(expP, vT, attn, oapl, rs);

    // Output projection: plain fp16 single-pass
    dim3 gop(D_ / 128, MROWS_ / 128, 1);
    plain_gemm<128><<<gop, blk, SMEM128>>>(oapl, wopl, bo, op, 16, 2048, 2048, D_);

    // LayerNorm + residual
    ln_residual<<<MROWS_, blk>>>(op, q, lg, lb, out);
}

// round 17
// speedup vs baseline: 1.7329x; 1.0960x over previous
#include <cuda_runtime.h>
#include <cuda_fp16.h>
#include <stdint.h>

#define B_   4
#define L_   2048
#define D_   1024
#define H_   16
#define DK_  64
#define HD_  1024
#define MROWS_ 8192
#define LN_EPS_ 1e-5f
#define NROWS_ATTN (B_ * H_ * L_)

// ---------------------------------------------------------------------------
// Scratch. Packed split-fp16: [M][K/32][32 hi | 32 lo] 128B chunks.
// Plain fp16: [M][K/64][64 fp16] 128B chunks.
// ---------------------------------------------------------------------------
__device__ __align__(256) uint8_t g_qkpk [2ll * MROWS_ * D_ * 4];
__device__ __align__(256) uint8_t g_vpk  [(long long)MROWS_ * D_ * 4];
__device__ __align__(256) uint8_t g_wqkpk[2ll * HD_ * D_ * 4];
__device__ __align__(256) uint8_t g_wvpk [(long long)HD_ * D_ * 4];
__device__ __align__(256) uint8_t g_wopl [(long long)D_ * HD_ * 2];
__device__ __align__(256) uint8_t g_qkhpk[2ll * MROWS_ * HD_ * 4];
__device__ __align__(256) uint8_t g_vT   [(long long)B_ * H_ * DK_ * L_ * 2];
__device__ __align__(256) uint8_t g_oapl [(long long)MROWS_ * HD_ * 2];
__device__ __align__(256) uint8_t g_expP [(long long)B_ * H_ * L_ * L_ * 2];
__device__ float g_op[MROWS_ * HD_];
__device__ float g_rs[NROWS_ATTN];

#define QKPK_HALF ((long long)MROWS_ * D_ * 4)
#define WQK_HALF  ((long long)HD_ * D_ * 4)
#define QKH_HALF  ((long long)MROWS_ * HD_ * 4)

// ---------------------------------------------------------------------------
// helpers
// ---------------------------------------------------------------------------
__device__ __forceinline__ uint32_t smem_u32(const void* p) {
    uint32_t a;
    asm("{ .reg .u64 t; cvta.to.shared.u64 t, %1; cvt.u32.u64 %0, t; }" : "=r"(a) : "l"(p));
    return a;
}
__device__ __forceinline__ uint32_t sw128(uint32_t off) {
    return off ^ ((off >> 3) & 0x70);
}
__device__ __forceinline__ void cpa16(uint32_t dst, const void* src) {
    asm volatile("cp.async.cg.shared.global [%0], [%1], 16;" :: "r"(dst), "l"(src));
}
#define CP_COMMIT() asm volatile("cp.async.commit_group;" ::: "memory")
#define CP_WAIT0()  asm volatile("cp.async.wait_group 0;" ::: "memory")
#define CP_WAIT1()  asm volatile("cp.async.wait_group 1;" ::: "memory")
#define LDSM_X4(r0, r1, r2, r3, addr)                                      \
    asm volatile("ldmatrix.sync.aligned.m8n8.x4.shared.b16 "               \
                 "{%0,%1,%2,%3}, [%4];"                                    \
                 : "=r"(r0), "=r"(r1), "=r"(r2), "=r"(r3) : "r"(addr))
#define STG_CS_F4(addr, v)                                                 \
    asm volatile("st.global.cs.v4.f32 [%0], {%1,%2,%3,%4};"                \
                 :: "l"(addr), "f"((v).x), "f"((v).y), "f"((v).z), "f"((v).w) : "memory")
#define STG_CS_U4(addr, v)                                                 \
    asm volatile("st.global.cs.v4.b32 [%0], {%1,%2,%3,%4};"                \
                 :: "l"(addr), "r"((v).x), "r"((v).y), "r"((v).z), "r"((v).w) : "memory")

__device__ __forceinline__ void mma16816(float* d, const uint32_t* a, const uint32_t* b) {
    asm volatile(
        "mma.sync.aligned.m16n8k16.row.col.f32.f16.f16.f32 "
        "{%0,%1,%2,%3}, {%4,%5,%6,%7}, {%8,%9}, {%0,%1,%2,%3};"
        : "+f"(d[0]), "+f"(d[1]), "+f"(d[2]), "+f"(d[3])
        : "r"(a[0]), "r"(a[1]), "r"(a[2]), "r"(a[3]), "r"(b[0]), "r"(b[1]));
}

__device__ __forceinline__ void pack_store2(uint8_t* p, float v0, float v1) {
    __half2 h = __float22half2_rn(make_float2(v0, v1));
    float2 f = __half22float2(h);
    __half2 l = __float22half2_rn(make_float2(v0 - f.x, v1 - f.y));
    *(uint32_t*)p = *(uint32_t*)&h;
    *(uint32_t*)(p + 64) = *(uint32_t*)&l;
}
__device__ __forceinline__ void pack_store4(uint8_t* p, float4 v) {
    __half2 h0 = __float22half2_rn(make_float2(v.x, v.y));
    __half2 h1 = __float22half2_rn(make_float2(v.z, v.w));
    float2 f0 = __half22float2(h0), f1 = __half22float2(h1);
    __half2 l0 = __float22half2_rn(make_float2(v.x - f0.x, v.y - f0.y));
    __half2 l1 = __float22half2_rn(make_float2(v.z - f1.x, v.w - f1.y));
    uint2 hu, lu;
    hu.x = *(uint32_t*)&h0; hu.y = *(uint32_t*)&h1;
    lu.x = *(uint32_t*)&l0; lu.y = *(uint32_t*)&l1;
    *(uint2*)p = hu;
    *(uint2*)(p + 64) = lu;
}

// ---------------------------------------------------------------------------
// pack inputs: q,k,v fp32 [8192,1024] -> packed split fp16 (z = 0..2)
// ---------------------------------------------------------------------------
__global__ void __launch_bounds__(256)
pack_qkv(const float* __restrict__ s0, const float* __restrict__ s1,
         const float* __restrict__ s2,
         uint8_t* __restrict__ d0, uint8_t* __restrict__ d1,
         uint8_t* __restrict__ d2)
{
    const float* src = (blockIdx.z == 0) ? s0 : (blockIdx.z == 1) ? s1 : s2;
    uint8_t* dst = (blockIdx.z == 0) ? d0 : (blockIdx.z == 1) ? d1 : d2;
    const long long idx = (long long)blockIdx.x * 256 + threadIdx.x;
    const long long m = idx >> 8;          // D/4 = 256 float4 per row
    const int j = (int)(idx & 255);
    float4 v = *(const float4*)(src + m * D_ + j * 4);
    const int e0 = j * 4;
    uint8_t* p = dst + (m * 32 + (e0 >> 5)) * 128 + (e0 & 31) * 2;
    pack_store4(p, v);
}

// pack weights: z=0..2 -> wq/wk/wv packed-split; z=3 -> wo plain fp16
__global__ void __launch_bounds__(256)
pack_w(const float* __restrict__ wq, const float* __restrict__ wk,
       const float* __restrict__ wv, const float* __restrict__ wo,
       uint8_t* __restrict__ dq, uint8_t* __restrict__ dk,
       uint8_t* __restrict__ dv, uint8_t* __restrict__ dwo)
{
    const long long idx = (long long)blockIdx.x * 256 + threadIdx.x;
    if (blockIdx.z == 3) {
        float4 v = *(const float4*)(wo + idx * 4);
        __half2 h0 = __float22half2_rn(make_float2(v.x, v.y));
        __half2 h1 = __float22half2_rn(make_float2(v.z, v.w));
        uint2 u; u.x = *(uint32_t*)&h0; u.y = *(uint32_t*)&h1;
        *(uint2*)(dwo + idx * 8) = u;
        return;
    }
    const float* src = (blockIdx.z == 0) ? wq : (blockIdx.z == 1) ? wk : wv;
    uint8_t* dst = (blockIdx.z == 0) ? dq : (blockIdx.z == 1) ? dk : dv;
    const long long m = idx >> 8;
    const int j = (int)(idx & 255);
    float4 v = *(const float4*)(src + m * D_ + j * 4);
    const int e0 = j * 4;
    uint8_t* p = dst + (m * 32 + (e0 >> 5)) * 128 + (e0 & 31) * 2;
    pack_store4(p, v);
}

// ---------------------------------------------------------------------------
// Merged QKV projection GEMM. Grid (8, 64, 3). 128x128 tiles, 32-K chunks,
// 8 warps 4x2, 2 CTAs/SM.
//   z<2 : 2-pass (hh+lh), epilogue packed-split -> qkh halves (bq/bk bias)
//   z==2: 1-pass (hh),   epilogue smem-transpose -> vT plain fp16 (bv bias)
// ---------------------------------------------------------------------------
__global__ void __launch_bounds__(256, 2)
qkv_gemm(const uint8_t* __restrict__ qkpk, const uint8_t* __restrict__ vpk,
         const uint8_t* __restrict__ wqkpk, const uint8_t* __restrict__ wvpk,
         const float* __restrict__ bq, const float* __restrict__ bk,
         const float* __restrict__ bv,
         uint8_t* __restrict__ qkhpk, uint8_t* __restrict__ vT)
{
    extern __shared__ uint8_t dyn_raw[];
    __shared__ float s_bias[128];

    const int tid = threadIdx.x, wid = tid >> 5, lane = tid & 31;
    const int z = blockIdx.z;
    const bool ap2 = (z < 2);
    const long long m0 = (long long)blockIdx.y * 128;
    const long long n0 = (long long)blockIdx.x * 128;

    const uint8_t* Apk = ap2 ? (qkpk + z * QKPK_HALF) : vpk;
    const uint8_t* Bpk = ap2 ? (wqkpk + z * WQK_HALF) : wvpk;
    const float* bias = (z == 0) ? bq : (z == 1) ? bk : bv;
    uint8_t* Cpk = ap2 ? (qkhpk + z * QKH_HALF) : vT;

    uint32_t raw = smem_u32(dyn_raw);
    uint32_t base = (raw + 1023u) & ~1023u;
    uint8_t* dsm = dyn_raw + (base - raw);
    const int STAGE = 16384 + 16384;
    const uint32_t aSu[2] = { base, base + STAGE };
    const uint32_t bSu[2] = { base + 16384, base + STAGE + 16384 };

    if (tid < 128) s_bias[tid] = bias[n0 + tid];

    float acc[2][8][4];
#pragma unroll
    for (int i = 0; i < 2; i++)
#pragma unroll
        for (int j = 0; j < 8; j++)
#pragma unroll
            for (int e = 0; e < 4; e++) acc[i][j][e] = 0.0f;

    const uint32_t a_row = (uint32_t)((lane & 7) + (lane & 8));
    const uint32_t a_kof = (uint32_t)(((lane >> 4) & 1) * 16);
    const uint32_t b_row = (uint32_t)((lane & 7) + ((lane >> 4) & 1) * 8);
    const uint32_t b_kof = (uint32_t)(((lane >> 3) & 1) * 16);
    const int wm = (wid & 3) * 32;
    const int wn = (wid >> 2) * 64;

    auto prefetch = [&](int s, int c) {
        const uint8_t* Ab = Apk + (long long)c * 128;
        if (ap2) {
#pragma unroll
            for (int i = 0; i < 4; i++) {
                const int idx = i * 256 + tid, row = idx >> 3, g = idx & 7;
                cpa16(aSu[s] + sw128((uint32_t)(row * 128 + g * 16)),
                      Ab + (m0 + row) * 4096 + g * 16);
            }
        } else {
#pragma unroll
            for (int i = 0; i < 2; i++) {
                const int idx = i * 256 + tid, row = idx >> 2, g = idx & 3;
                cpa16(aSu[s] + sw128((uint32_t)(row * 128 + g * 16)),
                      Ab + (m0 + row) * 4096 + g * 16);
            }
        }
        const uint8_t* Bb = Bpk + (long long)c * 128;
#pragma unroll
        for (int i = 0; i < 2; i++) {
            const int idx = i * 256 + tid, row = idx >> 2, g = idx & 3;
            cpa16(bSu[s] + sw128((uint32_t)(row * 128 + g * 16)),
                  Bb + (n0 + row) * 4096 + g * 16);
        }
        CP_COMMIT();
    };

    prefetch(0, 0);
    int cur = 0;
    for (int c = 0; c < 32; c++) {
        if (c + 1 < 32) { prefetch(cur ^ 1, c + 1); CP_WAIT1(); }
        else            { CP_WAIT0(); }
        __syncthreads();

        const uint32_t aS = aSu[cur], bS = bSu[cur];
#pragma unroll
        for (int ks = 0; ks < 2; ks++) {
            uint32_t ah[2][4], al[2][4], bf[8][2];
#pragma unroll
            for (int mt = 0; mt < 2; mt++) {
                uint32_t off = (uint32_t)(wm + mt * 16 + a_row) * 128 + ks * 32 + a_kof;
                LDSM_X4(ah[mt][0], ah[mt][1], ah[mt][2], ah[mt][3], aS + sw128(off));
            }
#pragma unroll
            for (int p = 0; p < 4; p++) {
                uint32_t r0, r1, r2, r3;
                uint32_t off = (uint32_t)(wn + p * 16 + b_row) * 128 + ks * 32 + b_kof;
                LDSM_X4(r0, r1, r2, r3, bS + sw128(off));
                bf[2 * p][0] = r0; bf[2 * p][1] = r1;
                bf[2 * p + 1][0] = r2; bf[2 * p + 1][1] = r3;
            }
#pragma unroll
            for (int mt = 0; mt < 2; mt++)
#pragma unroll
                for (int nt = 0; nt < 8; nt++)
                    mma16816(acc[mt][nt], ah[mt], bf[nt]);
            if (ap2) {
#pragma unroll
                for (int mt = 0; mt < 2; mt++) {
                    uint32_t off = (uint32_t)(wm + mt * 16 + a_row) * 128 + 64 + ks * 32 + a_kof;
                    LDSM_X4(al[mt][0], al[mt][1], al[mt][2], al[mt][3], aS + sw128(off));
                }
#pragma unroll
                for (int mt = 0; mt < 2; mt++)
#pragma unroll
                    for (int nt = 0; nt < 8; nt++)
                        mma16816(acc[mt][nt], al[mt], bf[nt]);
            }
        }
        __syncthreads();
        cur ^= 1;
    }

    const int g = lane >> 2, t = lane & 3;
    if (ap2) {
        // packed-split epilogue into qkh half
#pragma unroll
        for (int mt = 0; mt < 2; mt++) {
#pragma unroll
            for (int nt = 0; nt < 8; nt++) {
                const int colw = wn + nt * 8 + 2 * t;
                const long long row0 = m0 + wm + mt * 16 + g;
                const float b0 = s_bias[colw], b1 = s_bias[colw + 1];
                const long long colg = n0 + colw;
                const long long ch = colg >> 5;
                const int wi = (int)(colg & 31);
                pack_store2(Cpk + row0 * 4096 + ch * 128 + wi * 2,
                            acc[mt][nt][0] + b0, acc[mt][nt][1] + b1);
                pack_store2(Cpk + (row0 + 8) * 4096 + ch * 128 + wi * 2,
                            acc[mt][nt][2] + b0, acc[mt][nt][3] + b1);
            }
        }
    } else {
        // smem-transposed epilogue -> vT plain fp16
        __half* tb = (__half*)dsm;
        constexpr int PH = 136;
#pragma unroll
        for (int mt = 0; mt < 2; mt++) {
#pragma unroll
            for (int nt = 0; nt < 8; nt++) {
                const int colw = wn + nt * 8 + 2 * t;
                const int r0 = wm + mt * 16 + g;
                const float b0 = s_bias[colw], b1 = s_bias[colw + 1];
                tb[(colw)     * PH + r0]     = __float2half_rn(acc[mt][nt][0] + b0);
                tb[(colw + 1) * PH + r0]     = __float2half_rn(acc[mt][nt][1] + b1);
                tb[(colw)     * PH + r0 + 8] = __float2half_rn(acc[mt][nt][2] + b0);
                tb[(colw + 1) * PH + r0 + 8] = __float2half_rn(acc[mt][nt][3] + b1);
            }
        }
        __syncthreads();
        const int bidx = (int)(m0 / L_);
        const int m0g = (int)(m0 - (long long)bidx * L_);
#pragma unroll
        for (int it = 0; it < 8; it++) {
            const int chunk = it * 256 + tid;
            const int cg = chunk >> 4, lc = chunk & 15;
            const int colg = (int)n0 + cg;
            const int hh = colg >> 6, dk = colg & 63;
            uint4 v = *(const uint4*)(tb + cg * PH + lc * 8);
            *(uint4*)(Cpk + ((long long)((bidx * H_ + hh) * DK_ + dk)) * 4096
                           + (m0g + lc * 8) * 2) = v;
        }
    }
}

// ---------------------------------------------------------------------------
// Scores GEMM: exp((qh@kh^T)/8)*2^-4 -> expP plain fp16 (smem-staged coalesced
// streaming writes) + rowsum atomics. Grid (16, 16, 64). 2-pass, K=64.
// ---------------------------------------------------------------------------
__global__ void __launch_bounds__(256, 2)
scores_gemm(const uint8_t* __restrict__ qkhpk, uint8_t* __restrict__ expP,
            float* __restrict__ rs)
{
    extern __shared__ uint8_t dyn_raw[];
    __shared__ float s_aux[128];

    const int tid = threadIdx.x, wid = tid >> 5, lane = tid & 31;
    const int z = blockIdx.z;
    const int b = z >> 4, h = z & 15;
    const long long m0 = (long long)blockIdx.y * 128;
    const long long n0 = (long long)blockIdx.x * 128;

    const uint8_t* Apk = qkhpk + (long long)b * L_ * 4096 + h * 256;
    const uint8_t* Bpk = qkhpk + QKH_HALF + (long long)b * L_ * 4096 + h * 256;
    uint8_t* Cpk = expP + ((long long)(h * B_ + b) * L_) * 4096;
    float* rsb = rs + (long long)(h * B_ + b) * L_;

    uint32_t raw = smem_u32(dyn_raw);
    uint32_t base = (raw + 1023u) & ~1023u;
    uint8_t* dsm = dyn_raw + (base - raw);
    const int STAGE = 16384 + 16384;
    const uint32_t aSu[2] = { base, base + STAGE };
    const uint32_t bSu[2] = { base + 16384, base + STAGE + 16384 };

    if (tid < 128) s_aux[tid] = 0.0f;

    float acc[2][8][4];
#pragma unroll
    for (int i = 0; i < 2; i++)
#pragma unroll
        for (int j = 0; j < 8; j++)
#pragma unroll
            for (int e = 0; e < 4; e++) acc[i][j][e] = 0.0f;

    const uint32_t a_row = (uint32_t)((lane & 7) + (lane & 8));
    const uint32_t a_kof = (uint32_t)(((lane >> 4) & 1) * 16);
    const uint32_t b_row = (uint32_t)((lane & 7) + ((lane >> 4) & 1) * 8);
    const uint32_t b_kof = (uint32_t)(((lane >> 3) & 1) * 16);
    const int wm = (wid & 3) * 32;
    const int wn = (wid >> 2) * 64;

    auto prefetch = [&](int s, int c) {
        const uint8_t* Ab = Apk + (long long)c * 128;
#pragma unroll
        for (int i = 0; i < 4; i++) {
            const int idx = i * 256 + tid, row = idx >> 3, g = idx & 7;
            cpa16(aSu[s] + sw128((uint32_t)(row * 128 + g * 16)),
                  Ab + (m0 + row) * 4096 + g * 16);
        }
        const uint8_t* Bb = Bpk + (long long)c * 128;
#pragma unroll
        for (int i = 0; i < 2; i++) {
            const int idx = i * 256 + tid, row = idx >> 2, g = idx & 3;
            cpa16(bSu[s] + sw128((uint32_t)(row * 128 + g * 16)),
                  Bb + (n0 + row) * 4096 + g * 16);
        }
        CP_COMMIT();
    };

    prefetch(0, 0);
    int cur = 0;
    for (int c = 0; c < 2; c++) {
        if (c + 1 < 2) { prefetch(cur ^ 1, c + 1); CP_WAIT1(); }
        else           { CP_WAIT0(); }
        __syncthreads();

        const uint32_t aS = aSu[cur], bS = bSu[cur];
#pragma unroll
        for (int ks = 0; ks < 2; ks++) {
            uint32_t ah[2][4], al[2][4], bf[8][2];
#pragma unroll
            for (int mt = 0; mt < 2; mt++) {
                uint32_t off = (uint32_t)(wm + mt * 16 + a_row) * 128 + ks * 32 + a_kof;
                LDSM_X4(ah[mt][0], ah[mt][1], ah[mt][2], ah[mt][3], aS + sw128(off));
            }
#pragma unroll
            for (int p = 0; p < 4; p++) {
                uint32_t r0, r1, r2, r3;
                uint32_t off = (uint32_t)(wn + p * 16 + b_row) * 128 + ks * 32 + b_kof;
                LDSM_X4(r0, r1, r2, r3, bS + sw128(off));
                bf[2 * p][0] = r0; bf[2 * p][1] = r1;
                bf[2 * p + 1][0] = r2; bf[2 * p + 1][1] = r3;
            }
#pragma unroll
            for (int mt = 0; mt < 2; mt++)
#pragma unroll
                for (int nt = 0; nt < 8; nt++)
                    mma16816(acc[mt][nt], ah[mt], bf[nt]);
#pragma unroll
            for (int mt = 0; mt < 2; mt++) {
                uint32_t off = (uint32_t)(wm + mt * 16 + a_row) * 128 + 64 + ks * 32 + a_kof;
                LDSM_X4(al[mt][0], al[mt][1], al[mt][2], al[mt][3], aS + sw128(off));
            }
#pragma unroll
            for (int mt = 0; mt < 2; mt++)
#pragma unroll
                for (int nt = 0; nt < 8; nt++)
                    mma16816(acc[mt][nt], al[mt], bf[nt]);
        }
        __syncthreads();
        cur ^= 1;
    }

    // ---- epilogue: exp + stage to smem + coalesced streaming writes ----
    const int g = lane >> 2, t = lane & 3;
    const float esc = 0.0625f;
    __half* tb = (__half*)dsm;          // tb[row][col], pitch 136 halfs
    constexpr int PH = 136;
#pragma unroll
    for (int mt = 0; mt < 2; mt++) {
        float sum0 = 0.0f, sum1 = 0.0f;
        const int r0 = wm + mt * 16 + g;
#pragma unroll
        for (int nt = 0; nt < 8; nt++) {
            const int colw = wn + nt * 8 + 2 * t;
            float e0 = __expf(acc[mt][nt][0] * 0.125f) * esc;
            float e1 = __expf(acc[mt][nt][1] * 0.125f) * esc;
            float e2 = __expf(acc[mt][nt][2] * 0.125f) * esc;
            float e3 = __expf(acc[mt][nt][3] * 0.125f) * esc;
            tb[r0 * PH + colw]           = __float2half_rn(e0);
            tb[r0 * PH + colw + 1]       = __float2half_rn(e1);
            tb[(r0 + 8) * PH + colw]     = __float2half_rn(e2);
            tb[(r0 + 8) * PH + colw + 1] = __float2half_rn(e3);
            sum0 += e0 + e1; sum1 += e2 + e3;
        }
        sum0 += __shfl_xor_sync(0xffffffffu, sum0, 1);
        sum0 += __shfl_xor_sync(0xffffffffu, sum0, 2);
        sum1 += __shfl_xor_sync(0xffffffffu, sum1, 1);
        sum1 += __shfl_xor_sync(0xffffffffu, sum1, 2);
        if (t == 0) {
            atomicAdd(&s_aux[r0], sum0);
            atomicAdd(&s_aux[r0 + 8], sum1);
        }
    }
    __syncthreads();
    if (tid < 128)
        atomicAdd(&rsb[m0 + tid], s_aux[tid]);
    // coalesced 16B streaming writes: 128 rows x 256B
#pragma unroll
    for (int it = 0; it < 8; it++) {
        const int chunk = it * 256 + tid;
        const int r = chunk >> 4, lc = chunk & 15;
        uint4 v = *(const uint4*)(tb + r * PH + lc * 8);
        STG_CS_U4(Cpk + (m0 + r) * 4096 + (n0 + lc * 8) * 2, v);
    }
}

// ---------------------------------------------------------------------------
// Plain fp16 GEMM (single pass): C[128 x 128] = A_plain @ B_plain^T + bias.
// Used for o-proj. K-chunks of 64.
// ---------------------------------------------------------------------------
__global__ void __launch_bounds__(256, 2)
plain_gemm(const uint8_t* __restrict__ Apl, const uint8_t* __restrict__ Bpl,
           const float* __restrict__ bias, float* __restrict__ Cf,
           int nchunks, long long ldA, long long ldB, int ldc)
{
    extern __shared__ uint8_t dyn_raw[];
    __shared__ float s_bias[128];

    const int tid = threadIdx.x, wid = tid >> 5, lane = tid & 31;
    const long long m0 = (long long)blockIdx.y * 128;
    const long long n0 = (long long)blockIdx.x * 128;

    uint32_t raw = smem_u32(dyn_raw);
    uint32_t base = (raw + 1023u) & ~1023u;
    const int STAGE = 16384 + 16384;
    const uint32_t aSu[2] = { base, base + STAGE };
    const uint32_t bSu[2] = { base + 16384, base + STAGE + 16384 };

    if (tid < 128) s_bias[tid] = bias ? bias[n0 + tid] : 0.0f;

    float acc[2][8][4];
#pragma unroll
    for (int i = 0; i < 2; i++)
#pragma unroll
        for (int j = 0; j < 8; j++)
#pragma unroll
            for (int e = 0; e < 4; e++) acc[i][j][e] = 0.0f;

    const uint32_t a_row = (uint32_t)((lane & 7) + (lane & 8));
    const uint32_t a_kof = (uint32_t)(((lane >> 4) & 1) * 16);
    const uint32_t b_row = (uint32_t)((lane & 7) + ((lane >> 4) & 1) * 8);
    const uint32_t b_kof = (uint32_t)(((lane >> 3) & 1) * 16);
    const int wm = (wid & 3) * 32;
    const int wn = (wid >> 2) * 64;

    auto prefetch = [&](int s, int c) {
#pragma unroll
        for (int i = 0; i < 4; i++) {
            const int idx = i * 256 + tid, row = idx >> 3, g = idx & 7;
            cpa16(aSu[s] + sw128((uint32_t)(row * 128 + g * 16)),
                  Apl + (m0 + row) * ldA + c * 128 + g * 16);
        }
#pragma unroll
        for (int i = 0; i < 4; i++) {
            const int idx = i * 256 + tid, row = idx >> 3, g = idx & 7;
            cpa16(bSu[s] + sw128((uint32_t)(row * 128 + g * 16)),
                  Bpl + (n0 + row) * ldB + c * 128 + g * 16);
        }
        CP_COMMIT();
    };

    prefetch(0, 0);
    int cur = 0;
    for (int c = 0; c < nchunks; c++) {
        if (c + 1 < nchunks) { prefetch(cur ^ 1, c + 1); CP_WAIT1(); }
        else                 { CP_WAIT0(); }
        __syncthreads();

        const uint32_t aS = aSu[cur], bS = bSu[cur];
#pragma unroll
        for (int ks = 0; ks < 4; ks++) {
            uint32_t ah[2][4], bf[8][2];
#pragma unroll
            for (int mt = 0; mt < 2; mt++) {
                uint32_t off = (uint32_t)(wm + mt * 16 + a_row) * 128 + ks * 32 + a_kof;
                LDSM_X4(ah[mt][0], ah[mt][1], ah[mt][2], ah[mt][3], aS + sw128(off));
            }
#pragma unroll
            for (int p = 0; p < 4; p++) {
                uint32_t r0, r1, r2, r3;
                uint32_t off = (uint32_t)(wn + p * 16 + b_row) * 128 + ks * 32 + b_kof;
                LDSM_X4(r0, r1, r2, r3, bS + sw128(off));
                bf[2 * p][0] = r0; bf[2 * p][1] = r1;
                bf[2 * p + 1][0] = r2; bf[2 * p + 1][1] = r3;
            }
#pragma unroll
            for (int mt = 0; mt < 2; mt++)
#pragma unroll
                for (int nt = 0; nt < 8; nt++)
                    mma16816(acc[mt][nt], ah[mt], bf[nt]);
        }
        __syncthreads();
        cur ^= 1;
    }

    const int g = lane >> 2, t = lane & 3;
#pragma unroll
    for (int mt = 0; mt < 2; mt++) {
#pragma unroll
        for (int nt = 0; nt < 8; nt++) {
            const int colw = wn + nt * 8 + 2 * t;
            const float b0 = s_bias[colw], b1 = s_bias[colw + 1];
            const long long row0 = m0 + wm + mt * 16 + g;
            *(float2*)(Cf + row0 * (long long)ldc + n0 + colw) =
                make_float2(acc[mt][nt][0] + b0, acc[mt][nt][1] + b1);
            *(float2*)(Cf + (row0 + 8) * (long long)ldc + n0 + colw) =
                make_float2(acc[mt][nt][2] + b0, acc[mt][nt][3] + b1);
        }
    }
}

// ---------------------------------------------------------------------------
// PV plain-fp16 GEMM + normalized fp32 attn write (streaming) + plain-fp16 O.
// ---------------------------------------------------------------------------
__global__ void __launch_bounds__(256, 2)
pv_plain(const uint8_t* __restrict__ expP, const uint8_t* __restrict__ vT,
         float* __restrict__ attn, uint8_t* __restrict__ oapl,
         const float* __restrict__ rs)
{
    extern __shared__ uint8_t dyn_raw[];
    __shared__ float s_aux[128];

    const int tid = threadIdx.x, wid = tid >> 5, lane = tid & 31;
    const int qb = blockIdx.x;
    const int z = blockIdx.y;
    const int b = z >> 4, h = z & 15;
    const long long m0 = (long long)qb * 128;

    const uint8_t* P = expP + ((long long)(h * B_ + b) * L_ + m0) * 4096;
    const uint8_t* Vt = vT + (long long)z * 64 * 4096;
    float* Pf = attn + ((long long)(h * B_ + b) * L_ + m0) * L_;
    uint8_t* Oa = oapl + ((long long)b * L_ + m0) * 2048 + h * 128;
    const float* rsb = rs + (long long)(h * B_ + b) * L_ + m0;

    uint32_t raw = smem_u32(dyn_raw);
    uint32_t base = (raw + 1023u) & ~1023u;
    uint8_t* dsm = dyn_raw + (base - raw);
    const int STAGE = 16384 + 8192;
    uint8_t* smA[2] = { dsm, dsm + STAGE };
    const uint32_t aSu[2] = { base, base + STAGE };
    const uint32_t bSu[2] = { base + 16384, base + STAGE + 16384 };

    if (tid < 128) s_aux[tid] = 1.0f / rsb[tid];
    __syncthreads();

    float acc[2][4][4];
#pragma unroll
    for (int i = 0; i < 2; i++)
#pragma unroll
        for (int j = 0; j < 4; j++)
#pragma unroll
            for (int e = 0; e < 4; e++) acc[i][j][e] = 0.0f;

    const uint32_t a_row = (uint32_t)((lane & 7) + (lane & 8));
    const uint32_t a_kof = (uint32_t)(((lane >> 4) & 1) * 16);
    const uint32_t b_row = (uint32_t)((lane & 7) + ((lane >> 4) & 1) * 8);
    const uint32_t b_kof = (uint32_t)(((lane >> 3) & 1) * 16);
    const int wm = (wid & 3) * 32;
    const int wn = (wid >> 2) * 32;

    auto prefetch = [&](int s, int c) {
#pragma unroll
        for (int i = 0; i < 4; i++) {
            const int idx = i * 256 + tid, row = idx >> 3, g = idx & 7;
            cpa16(aSu[s] + sw128((uint32_t)(row * 128 + g * 16)),
                  P + (long long)row * 4096 + c * 128 + g * 16);
        }
#pragma unroll
        for (int i = 0; i < 2; i++) {
            const int idx = i * 256 + tid, row = idx >> 3, g = idx & 7;
            cpa16(bSu[s] + sw128((uint32_t)(row * 128 + g * 16)),
                  Vt + (long long)row * 4096 + c * 128 + g * 16);
        }
        CP_COMMIT();
    };

    prefetch(0, 0);
    int cur = 0;
    for (int c = 0; c < 32; c++) {
        if (c + 1 < 32) { prefetch(cur ^ 1, c + 1); CP_WAIT1(); }
        else            { CP_WAIT0(); }
        __syncthreads();

        // normalized fp32 P write (required output), streaming stores
        {
            const int r = tid >> 1, hh = tid & 1;
            const uint8_t* sa = smA[cur];
            const float inv = s_aux[r];
            float* dst = Pf + (long long)r * L_ + c * 64 + hh * 32;
#pragma unroll
            for (int j = 0; j < 4; j++) {
                uint4 u = *(const uint4*)(sa + sw128((uint32_t)(r * 128 + hh * 64 + j * 16)));
                const uint32_t w[4] = { u.x, u.y, u.z, u.w };
                float o[8];
#pragma unroll
                for (int jj = 0; jj < 4; jj++) {
                    __half2 hb = *(const __half2*)&w[jj];
                    float2 f = __half22float2(hb);
                    o[2 * jj] = f.x * inv;
                    o[2 * jj + 1] = f.y * inv;
                }
                float4 v0 = make_float4(o[0], o[1], o[2], o[3]);
                float4 v1 = make_float4(o[4], o[5], o[6], o[7]);
                STG_CS_F4(dst + j * 8, v0);
                STG_CS_F4(dst + j * 8 + 4, v1);
            }
        }

        const uint32_t aS = aSu[cur], bS = bSu[cur];
#pragma unroll
        for (int ks = 0; ks < 4; ks++) {
            uint32_t ah[2][4], bf[4][2];
#pragma unroll
            for (int mt = 0; mt < 2; mt++) {
                uint32_t off = (uint32_t)(wm + mt * 16 + a_row) * 128 + ks * 32 + a_kof;
                LDSM_X4(ah[mt][0], ah[mt][1], ah[mt][2], ah[mt][3], aS + sw128(off));
            }
#pragma unroll
            for (int p = 0; p < 2; p++) {
                uint32_t r0, r1, r2, r3;
                uint32_t off = (uint32_t)(wn + p * 16 + b_row) * 128 + ks * 32 + b_kof;
                LDSM_X4(r0, r1, r2, r3, bS + sw128(off));
                bf[2 * p][0] = r0; bf[2 * p][1] = r1;
                bf[2 * p + 1][0] = r2; bf[2 * p + 1][1] = r3;
            }
#pragma unroll
            for (int mt = 0; mt < 2; mt++)
#pragma unroll
                for (int nt = 0; nt < 4; nt++)
                    mma16816(acc[mt][nt], ah[mt], bf[nt]);
        }
        __syncthreads();
        cur ^= 1;
    }

    const int g = lane >> 2, t = lane & 3;
#pragma unroll
    for (int mt = 0; mt < 2; mt++) {
        const float i0 = s_aux[wm + mt * 16 + g];
        const float i1 = s_aux[wm + mt * 16 + g + 8];
#pragma unroll
        for (int nt = 0; nt < 4; nt++) {
            const int colw = wn + nt * 8 + 2 * t;
            const int row0 = wm + mt * 16 + g;
            __half2 h0 = __float22half2_rn(make_float2(acc[mt][nt][0] * i0, acc[mt][nt][1] * i0));
            __half2 h1 = __float22half2_rn(make_float2(acc[mt][nt][2] * i1, acc[mt][nt][3] * i1));
            *(uint32_t*)(Oa + (long long)row0 * 2048 + colw * 2) = *(uint32_t*)&h0;
            *(uint32_t*)(Oa + (long long)(row0 + 8) * 2048 + colw * 2) = *(uint32_t*)&h1;
        }
    }
}

__global__ void zero_rs(float* __restrict__ rs)
{
    rs[blockIdx.x * 256 + threadIdx.x] = 0.0f;
}

// ---------------------------------------------------------------------------
// LayerNorm + residual
// ---------------------------------------------------------------------------
__global__ void __launch_bounds__(256)
ln_residual(const float* __restrict__ x, const float* __restrict__ res,
            const float* __restrict__ gam, const float* __restrict__ bet,
            float* __restrict__ out)
{
    const long long row = blockIdx.x;
    const float4* x4 = (const float4*)(x   + row * D_);
    const float4* r4 = (const float4*)(res + row * D_);
    const int tid = threadIdx.x;

    float4 v = x4[tid];
    float s  = (v.x + v.y) + (v.z + v.w);
    float sq = (v.x * v.x + v.y * v.y) + (v.z * v.z + v.w * v.w);
#pragma unroll
    for (int o = 16; o > 0; o >>= 1) {
        s  += __shfl_xor_sync(0xffffffffu, s,  o);
        sq += __shfl_xor_sync(0xffffffffu, sq, o);
    }
    __shared__ float ss[8], sqs[8];
    if ((tid & 31) == 0) { ss[tid >> 5] = s; sqs[tid >> 5] = sq; }
    __syncthreads();
    s  = (ss[0]  + ss[1])  + (ss[2]  + ss[3])  + (ss[4]  + ss[5])  + (ss[6]  + ss[7]);
    sq = (sqs[0] + sqs[1]) + (sqs[2] + sqs[3]) + (sqs[4] + sqs[5]) + (sqs[6] + sqs[7]);

    const float mean = s * (1.0f / D_);
    float var = sq * (1.0f / D_) - mean * mean;
    var = fmaxf(var, 0.0f);
    const float rstd = rsqrtf(var + LN_EPS_);

    float4 g  = ((const float4*)gam)[tid];
    float4 bt = ((const float4*)bet)[tid];
    float4 r  = r4[tid];
    float4 o;
    o.x = (v.x - mean) * rstd * g.x + bt.x + r.x;
    o.y = (v.y - mean) * rstd * g.y + bt.y + r.y;
    o.z = (v.z - mean) * rstd * g.z + bt.z + r.z;
    o.w = (v.w - mean) * rstd * g.w + bt.w + r.w;
    ((float4*)(out + row * D_))[tid] = o;
}

// ---------------------------------------------------------------------------
// Launch
// ---------------------------------------------------------------------------
extern "C" void kernel_launch(void* const* d_in, const int* in_sizes, int n_in,
                              void* d_out, int out_size)
{
    (void)in_sizes; (void)n_in; (void)out_size;
    const float* q  = (const float*)d_in[0];
    const float* k  = (const float*)d_in[1];
    const float* v  = (const float*)d_in[2];
    const float* wq = (const float*)d_in[3];
    const float* bq = (const float*)d_in[4];
    const float* wk = (const float*)d_in[5];
    const float* bk = (const float*)d_in[6];
    const float* wv = (const float*)d_in[7];
    const float* bv = (const float*)d_in[8];
    const float* wo = (const float*)d_in[9];
    const float* bo = (const float*)d_in[10];
    const float* lg = (const float*)d_in[11];
    const float* lb = (const float*)d_in[12];

    float* out  = (float*)d_out;
    float* attn = out + (long long)B_ * L_ * D_;

    uint8_t *qkpk, *vpk, *wqkpk, *wvpk, *wopl, *qkhpk, *vT, *oapl, *expP;
    float *op, *rs;
    cudaGetSymbolAddress((void**)&qkpk,  g_qkpk);
    cudaGetSymbolAddress((void**)&vpk,   g_vpk);
    cudaGetSymbolAddress((void**)&wqkpk, g_wqkpk);
    cudaGetSymbolAddress((void**)&wvpk,  g_wvpk);
    cudaGetSymbolAddress((void**)&wopl,  g_wopl);
    cudaGetSymbolAddress((void**)&qkhpk, g_qkhpk);
    cudaGetSymbolAddress((void**)&vT,    g_vT);
    cudaGetSymbolAddress((void**)&oapl,  g_oapl);
    cudaGetSymbolAddress((void**)&expP,  g_expP);
    cudaGetSymbolAddress((void**)&op,    g_op);
    cudaGetSymbolAddress((void**)&rs,    g_rs);

    const int SMEMG  = 2 * (16384 + 16384) + 1024;   // 66560
    const int SMEMPV = 2 * (16384 + 8192) + 1024;    // 50176
    cudaFuncSetAttribute((const void*)qkv_gemm,   cudaFuncAttributeMaxDynamicSharedMemorySize, SMEMG);
    cudaFuncSetAttribute((const void*)scores_gemm,cudaFuncAttributeMaxDynamicSharedMemorySize, SMEMG);
    cudaFuncSetAttribute((const void*)plain_gemm, cudaFuncAttributeMaxDynamicSharedMemorySize, SMEMG);
    cudaFuncSetAttribute((const void*)pv_plain,   cudaFuncAttributeMaxDynamicSharedMemorySize, SMEMPV);

    dim3 blk(256);

    zero_rs<<<NROWS_ATTN / 256, blk>>>(rs);

    // packs: inputs (z=0..2), weights (z=0..3)
    pack_qkv<<<dim3(MROWS_ * D_ / 4 / 256, 1, 3), blk>>>(
        q, k, v, qkpk, qkpk + QKPK_HALF, vpk);
    pack_w<<<dim3(HD_ * D_ / 4 / 256, 1, 4), blk>>>(
        wq, wk, wv, wo, wqkpk, wqkpk + WQK_HALF, wvpk, wopl);

    // merged Q/K/V projections (z=0 q, z=1 k, z=2 v->vT)
    qkv_gemm<<<dim3(HD_ / 128, MROWS_ / 128, 3), blk, SMEMG>>>(
        qkpk, vpk, wqkpk, wvpk, bq, bk, bv, qkhpk, vT);

    // scores: exp + rowsums + staged coalesced expP writes
    scores_gemm<<<dim3(L_ / 128, L_ / 128, B_ * H_), blk, SMEMG>>>(qkhpk, expP, rs);

    // PV: fp32 attn (streaming) + plain-fp16 oa
    pv_plain<<<dim3(L_ / 128, B_ * H_, 1), blk, SMEMPV>>>(expP, vT, attn, oapl, rs);

    // o-proj: plain fp16 single-pass
    plain_gemm<<<dim3(D_ / 128, MROWS_ / 128, 1), blk, SMEMG>>>(
        oapl, wopl, bo, op, 16, 2048, 2048, D_);

    // LayerNorm + residual
    ln_residual<<<MROWS_, blk>>>(op, q, lg, lb, out);
}